// round 1
// baseline (speedup 1.0000x reference)
#include <cuda_runtime.h>
#include <math.h>

#define D_MODEL 1024
#define S_LEN   2048
#define BATCH   2
#define NHEAD   16
#define DK      64
#define M_TOT   (BATCH * S_LEN)   // 4096
#define SCALE   0.125f            // 1/sqrt(64)

// ---------------- scratch (device globals; no allocations allowed) ----------
__device__ float g_Q[M_TOT * D_MODEL];
__device__ float g_K[M_TOT * D_MODEL];
__device__ float g_V[M_TOT * D_MODEL];
__device__ float g_attn[M_TOT * D_MODEL];

// ---------------- SGEMM: C[M,N] = A[M,K] @ W[N,K]^T + bias -------------------
// NT layout: both A and W are K-contiguous -> fully coalesced float4 loads.
#define BM 128
#define BN 128
#define BK 16
#define TM 8
#define TN 8

__device__ __forceinline__ void gemm_tile(const float* __restrict__ A,
                                          const float* __restrict__ W,
                                          const float* __restrict__ bias,
                                          float* __restrict__ C,
                                          int N, int K)
{
    __shared__ float As[BK][BM];
    __shared__ float Bs[BK][BN];

    const int tid = threadIdx.x;            // 256 threads
    const int bm  = blockIdx.y * BM;
    const int bn  = blockIdx.x * BN;
    const int tx  = tid & 15;               // 0..15
    const int ty  = tid >> 4;               // 0..15

    float acc[TM][TN];
#pragma unroll
    for (int i = 0; i < TM; i++)
#pragma unroll
        for (int j = 0; j < TN; j++) acc[i][j] = 0.f;

    for (int k0 = 0; k0 < K; k0 += BK) {
#pragma unroll
        for (int i = 0; i < 2; i++) {
            int flat = tid + i * 256;       // 0..511 float4 slots
            int row  = flat >> 2;           // 0..127
            int kc   = (flat & 3) * 4;      // 0,4,8,12
            float4 va = *(const float4*)&A[(size_t)(bm + row) * K + k0 + kc];
            As[kc + 0][row] = va.x; As[kc + 1][row] = va.y;
            As[kc + 2][row] = va.z; As[kc + 3][row] = va.w;
            float4 vb = *(const float4*)&W[(size_t)(bn + row) * K + k0 + kc];
            Bs[kc + 0][row] = vb.x; Bs[kc + 1][row] = vb.y;
            Bs[kc + 2][row] = vb.z; Bs[kc + 3][row] = vb.w;
        }
        __syncthreads();

#pragma unroll
        for (int kk = 0; kk < BK; kk++) {
            float a[TM], b[TN];
#pragma unroll
            for (int i = 0; i < TM; i++) a[i] = As[kk][ty * TM + i];
#pragma unroll
            for (int j = 0; j < TN; j++) b[j] = Bs[kk][tx * TN + j];
#pragma unroll
            for (int i = 0; i < TM; i++)
#pragma unroll
                for (int j = 0; j < TN; j++) acc[i][j] += a[i] * b[j];
        }
        __syncthreads();
    }

#pragma unroll
    for (int i = 0; i < TM; i++) {
        int m = bm + ty * TM + i;
#pragma unroll
        for (int j = 0; j < TN; j++) {
            int n = bn + tx * TN + j;
            C[(size_t)m * N + n] = acc[i][j] + bias[n];
        }
    }
}

// QKV fused over gridDim.z
__global__ __launch_bounds__(256, 2)
void sgemm_qkv(const float* __restrict__ X,
               const float* __restrict__ Wq, const float* __restrict__ bq,
               const float* __restrict__ Wk, const float* __restrict__ bk,
               const float* __restrict__ Wv, const float* __restrict__ bv)
{
    const float* W = (blockIdx.z == 0) ? Wq : (blockIdx.z == 1) ? Wk : Wv;
    const float* b = (blockIdx.z == 0) ? bq : (blockIdx.z == 1) ? bk : bv;
    float*       C = (blockIdx.z == 0) ? g_Q : (blockIdx.z == 1) ? g_K : g_V;
    gemm_tile(X, W, b, C, D_MODEL, D_MODEL);
}

__global__ __launch_bounds__(256, 2)
void sgemm_out(const float* __restrict__ Wo, const float* __restrict__ bo,
               float* __restrict__ out)
{
    gemm_tile(g_attn, Wo, bo, out, D_MODEL, D_MODEL);
}

// ---------------- RoPE on Q and K (interleaved pairs) ------------------------
// idx bits: i[0:5) pair, h[5:9) head, s[9:20) seq, b[20] batch  (total 2^21)
__global__ void rope_kernel()
{
    int idx = blockIdx.x * blockDim.x + threadIdx.x;
    if (idx >= BATCH * S_LEN * NHEAD * 32) return;
    int i = idx & 31;
    int h = (idx >> 5) & 15;
    int s = (idx >> 9) & 2047;
    int b = idx >> 20;

    // inv_freq = theta^{-2i/64}; expf is ~1ulp accurate -> angle err ~1e-4 rad max
    float inv_freq = __expf(-(float)(2 * i) * (9.210340371976184f / 64.0f));
    float ang = (float)s * inv_freq;
    float sn, cs;
    __sincosf(ang, &sn, &cs);
    // use accurate versions to be safe on the largest angles
    sn = sinf(ang); cs = cosf(ang);

    size_t base = ((size_t)(b * S_LEN + s)) * D_MODEL + h * DK + 2 * i;
    float qe = g_Q[base], qo = g_Q[base + 1];
    g_Q[base]     = qe * cs - qo * sn;
    g_Q[base + 1] = qe * sn + qo * cs;
    float ke = g_K[base], ko = g_K[base + 1];
    g_K[base]     = ke * cs - ko * sn;
    g_K[base + 1] = ke * sn + ko * cs;
}

// ---------------- causal flash attention (fp32, online softmax) --------------
// 4 warps/block, 4 query rows per warp (16 rows/block), 64-key tiles.
// Lane `l` owns key columns {l, l+32} and output dims {l, l+32}.
#define BN_ATT 64
#define RPW    4

__global__ __launch_bounds__(128)
void attn_kernel()
{
    __shared__ float Ks[BN_ATT][DK + 1];   // +1 pad: bank = (row+d)%32, conflict-free
    __shared__ float Vs[BN_ATT][DK + 1];
    __shared__ float qs[16][DK];
    __shared__ float ps[16][BN_ATT];

    const int bh   = blockIdx.y;
    const int b    = bh >> 4;
    const int h    = bh & 15;
    const int q0   = blockIdx.x * 16;            // first query row of block
    const int w    = threadIdx.x >> 5;
    const int lane = threadIdx.x & 31;

    const float* Qb = g_Q + (size_t)(b * S_LEN) * D_MODEL + h * DK;
    const float* Kb = g_K + (size_t)(b * S_LEN) * D_MODEL + h * DK;
    const float* Vb = g_V + (size_t)(b * S_LEN) * D_MODEL + h * DK;

    // load 16 q rows into shared (coalesced)
#pragma unroll
    for (int i = 0; i < 8; i++) {
        int flat = threadIdx.x + i * 128;        // 0..1023
        int row  = flat >> 6;
        int d    = flat & 63;
        qs[row][d] = Qb[(size_t)(q0 + row) * D_MODEL + d];
    }

    float m[RPW], l[RPW], o0[RPW], o1[RPW];
#pragma unroll
    for (int r = 0; r < RPW; r++) { m[r] = -1e30f; l[r] = 0.f; o0[r] = 0.f; o1[r] = 0.f; }

    const int myrow0 = q0 + w * RPW;
    const int ktiles = (q0 + 15) / BN_ATT + 1;

    for (int t = 0; t < ktiles; t++) {
        const int k0 = t * BN_ATT;
        __syncthreads();
#pragma unroll
        for (int i = 0; i < 8; i++) {
            int flat = threadIdx.x + i * 128;    // 0..1023 float4 slots
            int row  = flat >> 4;                // 0..63
            int c4   = (flat & 15) * 4;
            float4 vk = *(const float4*)&Kb[(size_t)(k0 + row) * D_MODEL + c4];
            Ks[row][c4 + 0] = vk.x; Ks[row][c4 + 1] = vk.y;
            Ks[row][c4 + 2] = vk.z; Ks[row][c4 + 3] = vk.w;
            float4 vv = *(const float4*)&Vb[(size_t)(k0 + row) * D_MODEL + c4];
            Vs[row][c4 + 0] = vv.x; Vs[row][c4 + 1] = vv.y;
            Vs[row][c4 + 2] = vv.z; Vs[row][c4 + 3] = vv.w;
        }
        __syncthreads();

        // scores for 4 rows x 2 keys per lane
        float s0[RPW], s1[RPW];
#pragma unroll
        for (int r = 0; r < RPW; r++) { s0[r] = 0.f; s1[r] = 0.f; }
#pragma unroll
        for (int d = 0; d < DK; d++) {
            float kv0 = Ks[lane][d];
            float kv1 = Ks[lane + 32][d];
#pragma unroll
            for (int r = 0; r < RPW; r++) {
                float qd = qs[w * RPW + r][d];   // broadcast
                s0[r] += qd * kv0;
                s1[r] += qd * kv1;
            }
        }

#pragma unroll
        for (int r = 0; r < RPW; r++) {
            int qrow = myrow0 + r;
            float a0 = s0[r] * SCALE;
            float a1 = s1[r] * SCALE;
            if (k0 + lane      > qrow) a0 = -1e30f;
            if (k0 + lane + 32 > qrow) a1 = -1e30f;

            float mt = fmaxf(a0, a1);
#pragma unroll
            for (int off = 16; off; off >>= 1)
                mt = fmaxf(mt, __shfl_xor_sync(0xffffffffu, mt, off));
            float mnew = fmaxf(m[r], mt);
            float corr = __expf(m[r] - mnew);
            float p0 = __expf(a0 - mnew);
            float p1 = __expf(a1 - mnew);
            float psum = p0 + p1;
#pragma unroll
            for (int off = 16; off; off >>= 1)
                psum += __shfl_xor_sync(0xffffffffu, psum, off);
            l[r]  = l[r] * corr + psum;
            o0[r] *= corr;
            o1[r] *= corr;
            m[r]  = mnew;
            ps[w * RPW + r][lane]      = p0;
            ps[w * RPW + r][lane + 32] = p1;
        }
        __syncwarp();

        // o += p @ V
#pragma unroll
        for (int j = 0; j < BN_ATT; j++) {
            float v0 = Vs[j][lane];
            float v1 = Vs[j][lane + 32];
#pragma unroll
            for (int r = 0; r < RPW; r++) {
                float pj = ps[w * RPW + r][j];   // broadcast
                o0[r] += pj * v0;
                o1[r] += pj * v1;
            }
        }
        __syncwarp();
    }

#pragma unroll
    for (int r = 0; r < RPW; r++) {
        int qrow = myrow0 + r;
        float inv = 1.0f / l[r];
        float* Ob = g_attn + (size_t)(b * S_LEN + qrow) * D_MODEL + h * DK;
        Ob[lane]      = o0[r] * inv;
        Ob[lane + 32] = o1[r] * inv;
    }
}

// ---------------- launch ------------------------------------------------------
extern "C" void kernel_launch(void* const* d_in, const int* in_sizes, int n_in,
                              void* d_out, int out_size)
{
    const float* x  = (const float*)d_in[0];
    const float* Wq = (const float*)d_in[1];
    const float* bq = (const float*)d_in[2];
    const float* Wk = (const float*)d_in[3];
    const float* bk = (const float*)d_in[4];
    const float* Wv = (const float*)d_in[5];
    const float* bv = (const float*)d_in[6];
    const float* Wo = (const float*)d_in[7];
    const float* bo = (const float*)d_in[8];
    // d_in[9] = token_positions (unused; reference uses arange(S))
    float* out = (float*)d_out;

    // 1) Q,K,V projections (fused over gridDim.z)
    dim3 g_qkv(D_MODEL / BN, M_TOT / BM, 3);
    sgemm_qkv<<<g_qkv, 256>>>(x, Wq, bq, Wk, bk, Wv, bv);

    // 2) RoPE on Q and K
    int n_pairs = BATCH * S_LEN * NHEAD * 32;
    rope_kernel<<<(n_pairs + 255) / 256, 256>>>();

    // 3) causal attention
    dim3 g_att(S_LEN / 16, BATCH * NHEAD);
    attn_kernel<<<g_att, 128>>>();

    // 4) output projection
    dim3 g_out(D_MODEL / BN, M_TOT / BM);
    sgemm_out<<<g_out, 256>>>(Wo, bo, out);
}

// round 3
// speedup vs baseline: 1.4708x; 1.4708x over previous
#include <cuda_runtime.h>
#include <cuda_bf16.h>
#include <math.h>
#include <stdint.h>

#define D_MODEL 1024
#define S_LEN   2048
#define BATCH   2
#define NHEAD   16
#define DK      64
#define M_TOT   (BATCH * S_LEN)   // 4096
#define SCALE   0.125f            // 1/sqrt(64)

// ---------------- scratch (device globals; no allocations allowed) ----------
__device__ float g_Q[M_TOT * D_MODEL];
__device__ float g_K[M_TOT * D_MODEL];
__device__ float g_V[M_TOT * D_MODEL];
__device__ float g_attn[M_TOT * D_MODEL];

// =================== bf16 mma.sync split GEMM (sm_80+ PTX) ===================
// C[M,N] = A[M,K] @ W[N,K]^T + bias, fp32 in/out.
// Markidis split: a = hi + lo (bf16); D += Ahi*Bhi + Ahi*Blo + Alo*Bhi (fp32 acc).
// CTA 128x128, 256 threads (8 warps as 2x4), warp tile 64x32, BK=32, dbl buffer.

#define GBM 128
#define GBN 128
#define GBK 32
#define GCHUNKS (D_MODEL / GBK)           // 32
#define ROWH   (GBK + 8)                  // 40 halves per row (80B stride: conflict-free)
#define ARR_B  (128 * ROWH * 2)           // 10240 bytes per bf16 array
#define STAGE_B (4 * ARR_B)               // Ahi,Alo,Bhi,Blo = 40960
#define GSMEM_TOTAL (2 * STAGE_B)         // 81920

__device__ __forceinline__ uint32_t smem_u32(const void* p) {
    uint32_t a;
    asm("{ .reg .u64 t; cvta.to.shared.u64 t, %1; cvt.u32.u64 %0, t; }" : "=r"(a) : "l"(p));
    return a;
}

__device__ __forceinline__ void ldsm_x4(uint32_t* r, uint32_t addr) {
    asm volatile("ldmatrix.sync.aligned.m8n8.x4.shared.b16 {%0,%1,%2,%3}, [%4];"
                 : "=r"(r[0]), "=r"(r[1]), "=r"(r[2]), "=r"(r[3]) : "r"(addr));
}

__device__ __forceinline__ void mma_bf16(float* c, const uint32_t* a,
                                         uint32_t b0, uint32_t b1) {
    asm volatile("mma.sync.aligned.m16n8k16.row.col.f32.bf16.bf16.f32 "
                 "{%0,%1,%2,%3}, {%4,%5,%6,%7}, {%8,%9}, {%0,%1,%2,%3};"
                 : "+f"(c[0]), "+f"(c[1]), "+f"(c[2]), "+f"(c[3])
                 : "r"(a[0]), "r"(a[1]), "r"(a[2]), "r"(a[3]), "r"(b0), "r"(b1));
}

__device__ __forceinline__ uint32_t pack2_hi(float a, float b, float& ra, float& rb) {
    __nv_bfloat16 ha = __float2bfloat16_rn(a);
    __nv_bfloat16 hb = __float2bfloat16_rn(b);
    ra = a - __bfloat162float(ha);
    rb = b - __bfloat162float(hb);
    union { __nv_bfloat162 h; uint32_t u; } c;
    c.h = __halves2bfloat162(ha, hb);
    return c.u;
}

__device__ __forceinline__ uint32_t pack2(float a, float b) {
    union { __nv_bfloat162 h; uint32_t u; } c;
    c.h = __halves2bfloat162(__float2bfloat16_rn(a), __float2bfloat16_rn(b));
    return c.u;
}

__device__ __forceinline__ void gemm_core(const float* __restrict__ A,
                                          const float* __restrict__ W,
                                          const float* __restrict__ bias,
                                          float* __restrict__ C)
{
    extern __shared__ char smem[];
    const uint32_t sb = smem_u32(smem);
    const int tid  = threadIdx.x;              // 256
    const int wid  = tid >> 5;
    const int lane = tid & 31;
    const int bm = blockIdx.y * GBM;
    const int bn = blockIdx.x * GBN;
    const int warp_m = (wid >> 2) * 64;
    const int warp_n = (wid & 3) * 32;

    const float* Abase = A + (size_t)bm * D_MODEL;
    const float* Wbase = W + (size_t)bn * D_MODEL;

    float acc[4][4][4];
#pragma unroll
    for (int i = 0; i < 4; i++)
#pragma unroll
        for (int j = 0; j < 4; j++)
#pragma unroll
            for (int k = 0; k < 4; k++) acc[i][j][k] = 0.f;

    // per-thread load slots: flat = tid + i*256 in [0,1024); row=flat/8, c4=(flat%8)*4
    const int lrow = (tid >> 3) + 0;           // base row for i=0 (rows advance by 32/i)
    const int lc4  = (tid & 7) * 4;

    float4 ra[4], rb[4];
#pragma unroll
    for (int i = 0; i < 4; i++) {
        int row = lrow + i * 32;
        ra[i] = *(const float4*)(Abase + (size_t)row * D_MODEL + lc4);
        rb[i] = *(const float4*)(Wbase + (size_t)row * D_MODEL + lc4);
    }

    // ldmatrix lane addressing
    const int qrow = lane & 15;
    const int qcol = (lane >> 4) << 3;

    for (int c = 0; c < GCHUNKS; c++) {
        const uint32_t st = sb + (c & 1) * STAGE_B;
        // ---- store prefetched regs as hi/lo bf16 ----
#pragma unroll
        for (int i = 0; i < 4; i++) {
            int row = lrow + i * 32;
            uint32_t off = (uint32_t)(row * ROWH + lc4) * 2;
            float r0, r1, r2, r3;
            uint2 hi, lo;
            hi.x = pack2_hi(ra[i].x, ra[i].y, r0, r1);
            hi.y = pack2_hi(ra[i].z, ra[i].w, r2, r3);
            lo.x = pack2(r0, r1); lo.y = pack2(r2, r3);
            *(uint2*)(smem + (st - sb) + off)          = hi;
            *(uint2*)(smem + (st - sb) + ARR_B + off)  = lo;
            hi.x = pack2_hi(rb[i].x, rb[i].y, r0, r1);
            hi.y = pack2_hi(rb[i].z, rb[i].w, r2, r3);
            lo.x = pack2(r0, r1); lo.y = pack2(r2, r3);
            *(uint2*)(smem + (st - sb) + 2 * ARR_B + off) = hi;
            *(uint2*)(smem + (st - sb) + 3 * ARR_B + off) = lo;
        }
        __syncthreads();
        // ---- prefetch next chunk ----
        if (c + 1 < GCHUNKS) {
#pragma unroll
            for (int i = 0; i < 4; i++) {
                int row = lrow + i * 32;
                ra[i] = *(const float4*)(Abase + (size_t)row * D_MODEL + (c + 1) * GBK + lc4);
                rb[i] = *(const float4*)(Wbase + (size_t)row * D_MODEL + (c + 1) * GBK + lc4);
            }
        }
        // ---- compute: 2 k16 steps ----
        const uint32_t aHi = st + (uint32_t)((warp_m + qrow) * ROWH + qcol) * 2;
        const uint32_t bHi = st + 2 * ARR_B + (uint32_t)((warp_n + qrow) * ROWH + qcol) * 2;
#pragma unroll
        for (int ks = 0; ks < 2; ks++) {
            const uint32_t ko = (uint32_t)(ks * 16) * 2;
            uint32_t ah[4][4], al[4][4], bh[2][4], bl[2][4];
#pragma unroll
            for (int mi = 0; mi < 4; mi++) {
                ldsm_x4(ah[mi], aHi + mi * (16 * ROWH * 2) + ko);
                ldsm_x4(al[mi], aHi + ARR_B + mi * (16 * ROWH * 2) + ko);
            }
#pragma unroll
            for (int nt = 0; nt < 2; nt++) {
                ldsm_x4(bh[nt], bHi + nt * (16 * ROWH * 2) + ko);
                ldsm_x4(bl[nt], bHi + ARR_B + nt * (16 * ROWH * 2) + ko);
            }
#pragma unroll
            for (int mi = 0; mi < 4; mi++)
#pragma unroll
                for (int nt = 0; nt < 2; nt++)
#pragma unroll
                    for (int nj = 0; nj < 2; nj++) {
                        float* cc = acc[mi][nt * 2 + nj];
                        mma_bf16(cc, ah[mi], bh[nt][nj], bh[nt][nj + 2]);
                        mma_bf16(cc, ah[mi], bl[nt][nj], bl[nt][nj + 2]);
                        mma_bf16(cc, al[mi], bh[nt][nj], bh[nt][nj + 2]);
                    }
        }
        __syncthreads();
    }

    // ---- epilogue ----
    const int erow = lane >> 2;
    const int ecol = (lane & 3) * 2;
#pragma unroll
    for (int mi = 0; mi < 4; mi++) {
#pragma unroll
        for (int nt = 0; nt < 2; nt++)
#pragma unroll
            for (int nj = 0; nj < 2; nj++) {
                float* cc = acc[mi][nt * 2 + nj];
                int m = bm + warp_m + mi * 16 + erow;
                int n = bn + warp_n + nt * 16 + nj * 8 + ecol;
                float2 v0 = make_float2(cc[0] + bias[n], cc[1] + bias[n + 1]);
                float2 v1 = make_float2(cc[2] + bias[n], cc[3] + bias[n + 1]);
                *(float2*)(C + (size_t)m * D_MODEL + n)       = v0;
                *(float2*)(C + (size_t)(m + 8) * D_MODEL + n) = v1;
            }
    }
}

__global__ __launch_bounds__(256, 1)
void tc_gemm_qkv(const float* __restrict__ X,
                 const float* __restrict__ Wq, const float* __restrict__ bq,
                 const float* __restrict__ Wk, const float* __restrict__ bk,
                 const float* __restrict__ Wv, const float* __restrict__ bv)
{
    const float* W = (blockIdx.z == 0) ? Wq : (blockIdx.z == 1) ? Wk : Wv;
    const float* b = (blockIdx.z == 0) ? bq : (blockIdx.z == 1) ? bk : bv;
    float*       C = (blockIdx.z == 0) ? g_Q : (blockIdx.z == 1) ? g_K : g_V;
    gemm_core(X, W, b, C);
}

__global__ __launch_bounds__(256, 1)
void tc_gemm_out(const float* __restrict__ Wo, const float* __restrict__ bo,
                 float* __restrict__ out)
{
    gemm_core(g_attn, Wo, bo, out);
}

// ---------------- RoPE on Q and K (interleaved pairs) ------------------------
__global__ void rope_kernel()
{
    int idx = blockIdx.x * blockDim.x + threadIdx.x;
    if (idx >= BATCH * S_LEN * NHEAD * 32) return;
    int i = idx & 31;
    int h = (idx >> 5) & 15;
    int s = (idx >> 9) & 2047;
    int b = idx >> 20;

    float inv_freq = __expf(-(float)(2 * i) * (9.210340371976184f / 64.0f));
    float ang = (float)s * inv_freq;
    float sn = sinf(ang), cs = cosf(ang);

    size_t base = ((size_t)(b * S_LEN + s)) * D_MODEL + h * DK + 2 * i;
    float qe = g_Q[base], qo = g_Q[base + 1];
    g_Q[base]     = qe * cs - qo * sn;
    g_Q[base + 1] = qe * sn + qo * cs;
    float ke = g_K[base], ko = g_K[base + 1];
    g_K[base]     = ke * cs - ko * sn;
    g_K[base + 1] = ke * sn + ko * cs;
}

// ---------------- causal flash attention (fp32, online softmax) --------------
#define BN_ATT 64
#define RPW    4

__global__ __launch_bounds__(128)
void attn_kernel()
{
    __shared__ float Ks[BN_ATT][DK + 1];
    __shared__ float Vs[BN_ATT][DK + 1];
    __shared__ float qs[16][DK];
    __shared__ float ps[16][BN_ATT];

    const int bh   = blockIdx.y;
    const int b    = bh >> 4;
    const int h    = bh & 15;
    const int q0   = blockIdx.x * 16;
    const int w    = threadIdx.x >> 5;
    const int lane = threadIdx.x & 31;

    const float* Qb = g_Q + (size_t)(b * S_LEN) * D_MODEL + h * DK;
    const float* Kb = g_K + (size_t)(b * S_LEN) * D_MODEL + h * DK;
    const float* Vb = g_V + (size_t)(b * S_LEN) * D_MODEL + h * DK;

#pragma unroll
    for (int i = 0; i < 8; i++) {
        int flat = threadIdx.x + i * 128;
        int row  = flat >> 6;
        int d    = flat & 63;
        qs[row][d] = Qb[(size_t)(q0 + row) * D_MODEL + d];
    }

    float m[RPW], l[RPW], o0[RPW], o1[RPW];
#pragma unroll
    for (int r = 0; r < RPW; r++) { m[r] = -1e30f; l[r] = 0.f; o0[r] = 0.f; o1[r] = 0.f; }

    const int myrow0 = q0 + w * RPW;
    const int ktiles = (q0 + 15) / BN_ATT + 1;

    for (int t = 0; t < ktiles; t++) {
        const int k0 = t * BN_ATT;
        __syncthreads();
#pragma unroll
        for (int i = 0; i < 8; i++) {
            int flat = threadIdx.x + i * 128;
            int row  = flat >> 4;
            int c4   = (flat & 15) * 4;
            float4 vk = *(const float4*)&Kb[(size_t)(k0 + row) * D_MODEL + c4];
            Ks[row][c4 + 0] = vk.x; Ks[row][c4 + 1] = vk.y;
            Ks[row][c4 + 2] = vk.z; Ks[row][c4 + 3] = vk.w;
            float4 vv = *(const float4*)&Vb[(size_t)(k0 + row) * D_MODEL + c4];
            Vs[row][c4 + 0] = vv.x; Vs[row][c4 + 1] = vv.y;
            Vs[row][c4 + 2] = vv.z; Vs[row][c4 + 3] = vv.w;
        }
        __syncthreads();

        float s0[RPW], s1[RPW];
#pragma unroll
        for (int r = 0; r < RPW; r++) { s0[r] = 0.f; s1[r] = 0.f; }
#pragma unroll
        for (int d = 0; d < DK; d++) {
            float kv0 = Ks[lane][d];
            float kv1 = Ks[lane + 32][d];
#pragma unroll
            for (int r = 0; r < RPW; r++) {
                float qd = qs[w * RPW + r][d];
                s0[r] += qd * kv0;
                s1[r] += qd * kv1;
            }
        }

#pragma unroll
        for (int r = 0; r < RPW; r++) {
            int qrow = myrow0 + r;
            float a0 = s0[r] * SCALE;
            float a1 = s1[r] * SCALE;
            if (k0 + lane      > qrow) a0 = -1e30f;
            if (k0 + lane + 32 > qrow) a1 = -1e30f;

            float mt = fmaxf(a0, a1);
#pragma unroll
            for (int off = 16; off; off >>= 1)
                mt = fmaxf(mt, __shfl_xor_sync(0xffffffffu, mt, off));
            float mnew = fmaxf(m[r], mt);
            float corr = __expf(m[r] - mnew);
            float p0 = __expf(a0 - mnew);
            float p1 = __expf(a1 - mnew);
            float psum = p0 + p1;
#pragma unroll
            for (int off = 16; off; off >>= 1)
                psum += __shfl_xor_sync(0xffffffffu, psum, off);
            l[r]  = l[r] * corr + psum;
            o0[r] *= corr;
            o1[r] *= corr;
            m[r]  = mnew;
            ps[w * RPW + r][lane]      = p0;
            ps[w * RPW + r][lane + 32] = p1;
        }
        __syncwarp();

#pragma unroll
        for (int j = 0; j < BN_ATT; j++) {
            float v0 = Vs[j][lane];
            float v1 = Vs[j][lane + 32];
#pragma unroll
            for (int r = 0; r < RPW; r++) {
                float pj = ps[w * RPW + r][j];
                o0[r] += pj * v0;
                o1[r] += pj * v1;
            }
        }
        __syncwarp();
    }

#pragma unroll
    for (int r = 0; r < RPW; r++) {
        int qrow = myrow0 + r;
        float inv = 1.0f / l[r];
        float* Ob = g_attn + (size_t)(b * S_LEN + qrow) * D_MODEL + h * DK;
        Ob[lane]      = o0[r] * inv;
        Ob[lane + 32] = o1[r] * inv;
    }
}

// ---------------- launch ------------------------------------------------------
extern "C" void kernel_launch(void* const* d_in, const int* in_sizes, int n_in,
                              void* d_out, int out_size)
{
    const float* x  = (const float*)d_in[0];
    const float* Wq = (const float*)d_in[1];
    const float* bq = (const float*)d_in[2];
    const float* Wk = (const float*)d_in[3];
    const float* bk = (const float*)d_in[4];
    const float* Wv = (const float*)d_in[5];
    const float* bv = (const float*)d_in[6];
    const float* Wo = (const float*)d_in[7];
    const float* bo = (const float*)d_in[8];
    float* out = (float*)d_out;

    static int configured = 0;
    if (!configured) {
        cudaFuncSetAttribute(tc_gemm_qkv, cudaFuncAttributeMaxDynamicSharedMemorySize, GSMEM_TOTAL);
        cudaFuncSetAttribute(tc_gemm_out, cudaFuncAttributeMaxDynamicSharedMemorySize, GSMEM_TOTAL);
        configured = 1;
    }

    // 1) Q,K,V projections (bf16 split mma.sync)
    dim3 g_qkv(D_MODEL / GBN, M_TOT / GBM, 3);
    tc_gemm_qkv<<<g_qkv, 256, GSMEM_TOTAL>>>(x, Wq, bq, Wk, bk, Wv, bv);

    // 2) RoPE on Q and K
    int n_pairs = BATCH * S_LEN * NHEAD * 32;
    rope_kernel<<<(n_pairs + 255) / 256, 256>>>();

    // 3) causal attention
    dim3 g_att(S_LEN / 16, BATCH * NHEAD);
    attn_kernel<<<g_att, 128>>>();

    // 4) output projection (bf16 split mma.sync)
    dim3 g_out(D_MODEL / GBN, M_TOT / GBM);
    tc_gemm_out<<<g_out, 256, GSMEM_TOTAL>>>(Wo, bo, out);
}

// round 4
// speedup vs baseline: 2.7017x; 1.8368x over previous
#include <cuda_runtime.h>
#include <cuda_bf16.h>
#include <math.h>
#include <stdint.h>

#define D_MODEL 1024
#define S_LEN   2048
#define BATCH   2
#define NHEAD   16
#define DK      64
#define M_TOT   (BATCH * S_LEN)   // 4096
#define SCALE   0.125f            // 1/sqrt(64)

// ---------------- scratch (device globals; no allocations allowed) ----------
__device__ float g_Q[M_TOT * D_MODEL];
__device__ float g_K[M_TOT * D_MODEL];
__device__ float g_V[M_TOT * D_MODEL];
__device__ float g_attn[M_TOT * D_MODEL];
__device__ __nv_bfloat16 g_Qhi[M_TOT * D_MODEL];
__device__ __nv_bfloat16 g_Qlo[M_TOT * D_MODEL];
__device__ __nv_bfloat16 g_Khi[M_TOT * D_MODEL];
__device__ __nv_bfloat16 g_Klo[M_TOT * D_MODEL];
__device__ __nv_bfloat16 g_Vhi[M_TOT * D_MODEL];
__device__ __nv_bfloat16 g_Vlo[M_TOT * D_MODEL];

// ---------------- common helpers --------------------------------------------
__device__ __forceinline__ uint32_t smem_u32(const void* p) {
    uint32_t a;
    asm("{ .reg .u64 t; cvta.to.shared.u64 t, %1; cvt.u32.u64 %0, t; }" : "=r"(a) : "l"(p));
    return a;
}

__device__ __forceinline__ void ldsm_x4(uint32_t* r, uint32_t addr) {
    asm volatile("ldmatrix.sync.aligned.m8n8.x4.shared.b16 {%0,%1,%2,%3}, [%4];"
                 : "=r"(r[0]), "=r"(r[1]), "=r"(r[2]), "=r"(r[3]) : "r"(addr));
}

__device__ __forceinline__ void ldsm_x4t(uint32_t* r, uint32_t addr) {
    asm volatile("ldmatrix.sync.aligned.m8n8.x4.trans.shared.b16 {%0,%1,%2,%3}, [%4];"
                 : "=r"(r[0]), "=r"(r[1]), "=r"(r[2]), "=r"(r[3]) : "r"(addr));
}

__device__ __forceinline__ void mma_bf16(float* c, const uint32_t* a,
                                         uint32_t b0, uint32_t b1) {
    asm volatile("mma.sync.aligned.m16n8k16.row.col.f32.bf16.bf16.f32 "
                 "{%0,%1,%2,%3}, {%4,%5,%6,%7}, {%8,%9}, {%0,%1,%2,%3};"
                 : "+f"(c[0]), "+f"(c[1]), "+f"(c[2]), "+f"(c[3])
                 : "r"(a[0]), "r"(a[1]), "r"(a[2]), "r"(a[3]), "r"(b0), "r"(b1));
}

__device__ __forceinline__ uint32_t pack2_hi(float a, float b, float& ra, float& rb) {
    __nv_bfloat16 ha = __float2bfloat16_rn(a);
    __nv_bfloat16 hb = __float2bfloat16_rn(b);
    ra = a - __bfloat162float(ha);
    rb = b - __bfloat162float(hb);
    union { __nv_bfloat162 h; uint32_t u; } c;
    c.h = __halves2bfloat162(ha, hb);
    return c.u;
}

__device__ __forceinline__ uint32_t pack2(float a, float b) {
    union { __nv_bfloat162 h; uint32_t u; } c;
    c.h = __halves2bfloat162(__float2bfloat16_rn(a), __float2bfloat16_rn(b));
    return c.u;
}

#define CP16(saddr, gptr) \
    asm volatile("cp.async.cg.shared.global [%0], [%1], 16;" :: "r"(saddr), "l"(gptr))
#define CP_COMMIT() asm volatile("cp.async.commit_group;" ::: "memory")
#define CP_WAIT0()  asm volatile("cp.async.wait_group 0;" ::: "memory")
#define CP_WAIT1()  asm volatile("cp.async.wait_group 1;" ::: "memory")

// =================== bf16 mma.sync split GEMM (unchanged from R3) ============
#define GBM 128
#define GBN 128
#define GBK 32
#define GCHUNKS (D_MODEL / GBK)
#define ROWH   (GBK + 8)
#define ARR_B  (128 * ROWH * 2)
#define STAGE_B (4 * ARR_B)
#define GSMEM_TOTAL (2 * STAGE_B)

__device__ __forceinline__ void gemm_core(const float* __restrict__ A,
                                          const float* __restrict__ W,
                                          const float* __restrict__ bias,
                                          float* __restrict__ C)
{
    extern __shared__ char smem[];
    const uint32_t sb = smem_u32(smem);
    const int tid  = threadIdx.x;
    const int wid  = tid >> 5;
    const int lane = tid & 31;
    const int bm = blockIdx.y * GBM;
    const int bn = blockIdx.x * GBN;
    const int warp_m = (wid >> 2) * 64;
    const int warp_n = (wid & 3) * 32;

    const float* Abase = A + (size_t)bm * D_MODEL;
    const float* Wbase = W + (size_t)bn * D_MODEL;

    float acc[4][4][4];
#pragma unroll
    for (int i = 0; i < 4; i++)
#pragma unroll
        for (int j = 0; j < 4; j++)
#pragma unroll
            for (int k = 0; k < 4; k++) acc[i][j][k] = 0.f;

    const int lrow = (tid >> 3);
    const int lc4  = (tid & 7) * 4;

    float4 ra[4], rb[4];
#pragma unroll
    for (int i = 0; i < 4; i++) {
        int row = lrow + i * 32;
        ra[i] = *(const float4*)(Abase + (size_t)row * D_MODEL + lc4);
        rb[i] = *(const float4*)(Wbase + (size_t)row * D_MODEL + lc4);
    }

    const int qrow = lane & 15;
    const int qcol = (lane >> 4) << 3;

    for (int c = 0; c < GCHUNKS; c++) {
        const uint32_t st = sb + (c & 1) * STAGE_B;
#pragma unroll
        for (int i = 0; i < 4; i++) {
            int row = lrow + i * 32;
            uint32_t off = (uint32_t)(row * ROWH + lc4) * 2;
            float r0, r1, r2, r3;
            uint2 hi, lo;
            hi.x = pack2_hi(ra[i].x, ra[i].y, r0, r1);
            hi.y = pack2_hi(ra[i].z, ra[i].w, r2, r3);
            lo.x = pack2(r0, r1); lo.y = pack2(r2, r3);
            *(uint2*)(smem + (st - sb) + off)          = hi;
            *(uint2*)(smem + (st - sb) + ARR_B + off)  = lo;
            hi.x = pack2_hi(rb[i].x, rb[i].y, r0, r1);
            hi.y = pack2_hi(rb[i].z, rb[i].w, r2, r3);
            lo.x = pack2(r0, r1); lo.y = pack2(r2, r3);
            *(uint2*)(smem + (st - sb) + 2 * ARR_B + off) = hi;
            *(uint2*)(smem + (st - sb) + 3 * ARR_B + off) = lo;
        }
        __syncthreads();
        if (c + 1 < GCHUNKS) {
#pragma unroll
            for (int i = 0; i < 4; i++) {
                int row = lrow + i * 32;
                ra[i] = *(const float4*)(Abase + (size_t)row * D_MODEL + (c + 1) * GBK + lc4);
                rb[i] = *(const float4*)(Wbase + (size_t)row * D_MODEL + (c + 1) * GBK + lc4);
            }
        }
        const uint32_t aHi = st + (uint32_t)((warp_m + qrow) * ROWH + qcol) * 2;
        const uint32_t bHi = st + 2 * ARR_B + (uint32_t)((warp_n + qrow) * ROWH + qcol) * 2;
#pragma unroll
        for (int ks = 0; ks < 2; ks++) {
            const uint32_t ko = (uint32_t)(ks * 16) * 2;
            uint32_t ah[4][4], al[4][4], bh[2][4], bl[2][4];
#pragma unroll
            for (int mi = 0; mi < 4; mi++) {
                ldsm_x4(ah[mi], aHi + mi * (16 * ROWH * 2) + ko);
                ldsm_x4(al[mi], aHi + ARR_B + mi * (16 * ROWH * 2) + ko);
            }
#pragma unroll
            for (int nt = 0; nt < 2; nt++) {
                ldsm_x4(bh[nt], bHi + nt * (16 * ROWH * 2) + ko);
                ldsm_x4(bl[nt], bHi + ARR_B + nt * (16 * ROWH * 2) + ko);
            }
#pragma unroll
            for (int mi = 0; mi < 4; mi++)
#pragma unroll
                for (int nt = 0; nt < 2; nt++)
#pragma unroll
                    for (int nj = 0; nj < 2; nj++) {
                        float* cc = acc[mi][nt * 2 + nj];
                        mma_bf16(cc, ah[mi], bh[nt][nj], bh[nt][nj + 2]);
                        mma_bf16(cc, ah[mi], bl[nt][nj], bl[nt][nj + 2]);
                        mma_bf16(cc, al[mi], bh[nt][nj], bh[nt][nj + 2]);
                    }
        }
        __syncthreads();
    }

    const int erow = lane >> 2;
    const int ecol = (lane & 3) * 2;
#pragma unroll
    for (int mi = 0; mi < 4; mi++) {
#pragma unroll
        for (int nt = 0; nt < 2; nt++)
#pragma unroll
            for (int nj = 0; nj < 2; nj++) {
                float* cc = acc[mi][nt * 2 + nj];
                int m = bm + warp_m + mi * 16 + erow;
                int n = bn + warp_n + nt * 16 + nj * 8 + ecol;
                float2 v0 = make_float2(cc[0] + bias[n], cc[1] + bias[n + 1]);
                float2 v1 = make_float2(cc[2] + bias[n], cc[3] + bias[n + 1]);
                *(float2*)(C + (size_t)m * D_MODEL + n)       = v0;
                *(float2*)(C + (size_t)(m + 8) * D_MODEL + n) = v1;
            }
    }
}

__global__ __launch_bounds__(256, 1)
void tc_gemm_qkv(const float* __restrict__ X,
                 const float* __restrict__ Wq, const float* __restrict__ bq,
                 const float* __restrict__ Wk, const float* __restrict__ bk,
                 const float* __restrict__ Wv, const float* __restrict__ bv)
{
    const float* W = (blockIdx.z == 0) ? Wq : (blockIdx.z == 1) ? Wk : Wv;
    const float* b = (blockIdx.z == 0) ? bq : (blockIdx.z == 1) ? bk : bv;
    float*       C = (blockIdx.z == 0) ? g_Q : (blockIdx.z == 1) ? g_K : g_V;
    gemm_core(X, W, b, C);
}

__global__ __launch_bounds__(256, 1)
void tc_gemm_out(const float* __restrict__ Wo, const float* __restrict__ bo,
                 float* __restrict__ out)
{
    gemm_core(g_attn, Wo, bo, out);
}

// ---------------- prep: RoPE(Q,K) + scale(Q) + hi/lo bf16 split of Q,K,V -----
__global__ void prep_kernel()
{
    int idx = blockIdx.x * blockDim.x + threadIdx.x;
    if (idx >= BATCH * S_LEN * NHEAD * 32) return;
    int i = idx & 31;
    int h = (idx >> 5) & 15;
    int s = (idx >> 9) & 2047;
    int b = idx >> 20;

    float inv_freq = __expf(-(float)(2 * i) * (9.210340371976184f / 64.0f));
    float ang = (float)s * inv_freq;
    float sn = sinf(ang), cs = cosf(ang);

    size_t base = ((size_t)(b * S_LEN + s)) * D_MODEL + h * DK + 2 * i;
    float r0, r1;

    float qe = g_Q[base], qo = g_Q[base + 1];
    float qre = (qe * cs - qo * sn) * SCALE;
    float qro = (qe * sn + qo * cs) * SCALE;
    *(uint32_t*)(g_Qhi + base) = pack2_hi(qre, qro, r0, r1);
    *(uint32_t*)(g_Qlo + base) = pack2(r0, r1);

    float ke = g_K[base], ko = g_K[base + 1];
    float kre = ke * cs - ko * sn;
    float kro = ke * sn + ko * cs;
    *(uint32_t*)(g_Khi + base) = pack2_hi(kre, kro, r0, r1);
    *(uint32_t*)(g_Klo + base) = pack2(r0, r1);

    float ve = g_V[base], vo = g_V[base + 1];
    *(uint32_t*)(g_Vhi + base) = pack2_hi(ve, vo, r0, r1);
    *(uint32_t*)(g_Vlo + base) = pack2(r0, r1);
}

// ---------------- tensor-core causal flash attention -------------------------
// Block: 64 q rows x 1 head, 4 warps (16 rows each), 64-key tiles.
#define AROW   72                       // halves per smem row (144B: conflict-free ldsm)
#define A_ARR  (64 * AROW * 2)          // 9216 bytes per array
#define SQ_HI  0
#define SQ_LO  A_ARR
#define STG0   (2 * A_ARR)              // 18432
#define STG_B  (4 * A_ARR)              // 36864 (Khi,Klo,Vhi,Vlo)
#define A_SMEM (2 * A_ARR + 2 * STG_B)  // 92160

__global__ __launch_bounds__(128)
void attn_mma_kernel()
{
    extern __shared__ char smem[];
    const uint32_t sb = smem_u32(smem);
    const int tid  = threadIdx.x;
    const int wid  = tid >> 5;
    const int lane = tid & 31;
    const int qb = blockIdx.x;                 // 0..31
    const int bh = blockIdx.y;
    const int b  = bh >> 4;
    const int h  = bh & 15;
    const int q0 = qb * 64;

    const size_t qgbase = (size_t)(b * S_LEN + q0) * D_MODEL + h * DK;
    const size_t kgbase = (size_t)(b * S_LEN) * D_MODEL + h * DK;

    // ---- issue cp.async for K/V tile kt into stage stg ----
    auto issue_tile = [&](int stg, int kt) {
        const uint32_t sbase = sb + STG0 + stg * STG_B;
        const size_t g0 = kgbase + (size_t)(kt * 64) * D_MODEL;
#pragma unroll
        for (int it = 0; it < 4; it++) {
            int slot = tid + it * 128;         // 0..511
            int r  = slot >> 3;
            int c8 = (slot & 7) * 8;
            uint32_t soff = (uint32_t)(r * AROW + c8) * 2;
            const size_t go = g0 + (size_t)r * D_MODEL + c8;
            CP16(sbase + soff,             (const char*)(g_Khi + go));
            CP16(sbase + A_ARR + soff,     (const char*)(g_Klo + go));
            CP16(sbase + 2 * A_ARR + soff, (const char*)(g_Vhi + go));
            CP16(sbase + 3 * A_ARR + soff, (const char*)(g_Vlo + go));
        }
    };

    issue_tile(0, 0);
    CP_COMMIT();

    // ---- load Q tile (plain) ----
#pragma unroll
    for (int it = 0; it < 4; it++) {
        int slot = tid + it * 128;
        int r  = slot >> 3;
        int c8 = (slot & 7) * 8;
        uint32_t soff = (uint32_t)(r * AROW + c8) * 2;
        const size_t go = qgbase + (size_t)r * D_MODEL + c8;
        *(uint4*)(smem + SQ_HI + soff) = *(const uint4*)(g_Qhi + go);
        *(uint4*)(smem + SQ_LO + soff) = *(const uint4*)(g_Qlo + go);
    }
    __syncthreads();

    // ---- Q fragments in registers ----
    uint32_t qh[4][4], ql[4][4];
#pragma unroll
    for (int t = 0; t < 4; t++) {
        uint32_t addr = sb + SQ_HI +
            (uint32_t)((wid * 16 + (lane & 15)) * AROW + t * 16 + ((lane >> 4) << 3)) * 2;
        ldsm_x4(qh[t], addr);
        ldsm_x4(ql[t], addr + A_ARR);
    }

    float oacc[8][4];
#pragma unroll
    for (int nt = 0; nt < 8; nt++)
#pragma unroll
        for (int j = 0; j < 4; j++) oacc[nt][j] = 0.f;
    float m0 = -1e30f, m1 = -1e30f, l0 = 0.f, l1 = 0.f;

    const int row_lo = q0 + wid * 16 + (lane >> 2);
    const int ntiles = qb + 1;

    for (int kt = 0; kt < ntiles; kt++) {
        if (kt + 1 < ntiles) {
            issue_tile((kt + 1) & 1, kt + 1);
            CP_COMMIT();
            CP_WAIT1();
        } else {
            CP_WAIT0();
        }
        __syncthreads();

        const uint32_t st = sb + STG0 + (kt & 1) * STG_B;

        // ---- scores S = Q @ K^T (3 split products, fp32 acc) ----
        float sc[8][4];
#pragma unroll
        for (int nt = 0; nt < 8; nt++)
#pragma unroll
            for (int j = 0; j < 4; j++) sc[nt][j] = 0.f;

#pragma unroll
        for (int t = 0; t < 4; t++) {
#pragma unroll
            for (int g = 0; g < 4; g++) {
                uint32_t addr = st +
                    (uint32_t)((g * 16 + (lane & 15)) * AROW + t * 16 + ((lane >> 4) << 3)) * 2;
                uint32_t kh4[4], kl4[4];
                ldsm_x4(kh4, addr);
                ldsm_x4(kl4, addr + A_ARR);
                mma_bf16(sc[2 * g],     qh[t], kh4[0], kh4[2]);
                mma_bf16(sc[2 * g],     qh[t], kl4[0], kl4[2]);
                mma_bf16(sc[2 * g],     ql[t], kh4[0], kh4[2]);
                mma_bf16(sc[2 * g + 1], qh[t], kh4[1], kh4[3]);
                mma_bf16(sc[2 * g + 1], qh[t], kl4[1], kl4[3]);
                mma_bf16(sc[2 * g + 1], ql[t], kh4[1], kh4[3]);
            }
        }

        // ---- causal mask on diagonal tile ----
        if (kt == qb) {
#pragma unroll
            for (int nt = 0; nt < 8; nt++) {
                int col = kt * 64 + nt * 8 + (lane & 3) * 2;
                if (col     > row_lo)     sc[nt][0] = -1e30f;
                if (col + 1 > row_lo)     sc[nt][1] = -1e30f;
                if (col     > row_lo + 8) sc[nt][2] = -1e30f;
                if (col + 1 > row_lo + 8) sc[nt][3] = -1e30f;
            }
        }

        // ---- online softmax ----
        float mx0 = -1e30f, mx1 = -1e30f;
#pragma unroll
        for (int nt = 0; nt < 8; nt++) {
            mx0 = fmaxf(mx0, fmaxf(sc[nt][0], sc[nt][1]));
            mx1 = fmaxf(mx1, fmaxf(sc[nt][2], sc[nt][3]));
        }
        mx0 = fmaxf(mx0, __shfl_xor_sync(0xffffffffu, mx0, 1));
        mx0 = fmaxf(mx0, __shfl_xor_sync(0xffffffffu, mx0, 2));
        mx1 = fmaxf(mx1, __shfl_xor_sync(0xffffffffu, mx1, 1));
        mx1 = fmaxf(mx1, __shfl_xor_sync(0xffffffffu, mx1, 2));

        float mn0 = fmaxf(m0, mx0);
        float mn1 = fmaxf(m1, mx1);
        float corr0 = __expf(m0 - mn0);
        float corr1 = __expf(m1 - mn1);
        m0 = mn0; m1 = mn1;

        float sum0 = 0.f, sum1 = 0.f;
#pragma unroll
        for (int nt = 0; nt < 8; nt++) {
            sc[nt][0] = __expf(sc[nt][0] - mn0);
            sc[nt][1] = __expf(sc[nt][1] - mn0);
            sc[nt][2] = __expf(sc[nt][2] - mn1);
            sc[nt][3] = __expf(sc[nt][3] - mn1);
            sum0 += sc[nt][0] + sc[nt][1];
            sum1 += sc[nt][2] + sc[nt][3];
        }
        sum0 += __shfl_xor_sync(0xffffffffu, sum0, 1);
        sum0 += __shfl_xor_sync(0xffffffffu, sum0, 2);
        sum1 += __shfl_xor_sync(0xffffffffu, sum1, 1);
        sum1 += __shfl_xor_sync(0xffffffffu, sum1, 2);
        l0 = l0 * corr0 + sum0;
        l1 = l1 * corr1 + sum1;

        // rescale O
#pragma unroll
        for (int nt = 0; nt < 8; nt++) {
            oacc[nt][0] *= corr0; oacc[nt][1] *= corr0;
            oacc[nt][2] *= corr1; oacc[nt][3] *= corr1;
        }

        // ---- pack P (accumulator layout == A-fragment layout) ----
        uint32_t ph[4][4], pl[4][4];
        float r0, r1;
#pragma unroll
        for (int t = 0; t < 4; t++) {
            ph[t][0] = pack2_hi(sc[2 * t][0], sc[2 * t][1], r0, r1);
            pl[t][0] = pack2(r0, r1);
            ph[t][1] = pack2_hi(sc[2 * t][2], sc[2 * t][3], r0, r1);
            pl[t][1] = pack2(r0, r1);
            ph[t][2] = pack2_hi(sc[2 * t + 1][0], sc[2 * t + 1][1], r0, r1);
            pl[t][2] = pack2(r0, r1);
            ph[t][3] = pack2_hi(sc[2 * t + 1][2], sc[2 * t + 1][3], r0, r1);
            pl[t][3] = pack2(r0, r1);
        }

        // ---- O += P @ V (V^T via ldmatrix.trans) ----
#pragma unroll
        for (int t = 0; t < 4; t++) {
#pragma unroll
            for (int g = 0; g < 4; g++) {
                uint32_t addr = st + 2 * A_ARR +
                    (uint32_t)((t * 16 + (lane & 7) + ((lane >> 3) & 1) * 8) * AROW +
                               g * 16 + ((lane >> 4) << 3)) * 2;
                uint32_t vh4[4], vl4[4];
                ldsm_x4t(vh4, addr);
                ldsm_x4t(vl4, addr + A_ARR);
                mma_bf16(oacc[2 * g],     ph[t], vh4[0], vh4[1]);
                mma_bf16(oacc[2 * g],     ph[t], vl4[0], vl4[1]);
                mma_bf16(oacc[2 * g],     pl[t], vh4[0], vh4[1]);
                mma_bf16(oacc[2 * g + 1], ph[t], vh4[2], vh4[3]);
                mma_bf16(oacc[2 * g + 1], ph[t], vl4[2], vl4[3]);
                mma_bf16(oacc[2 * g + 1], pl[t], vh4[2], vh4[3]);
            }
        }
        __syncthreads();
    }

    // ---- write O / l ----
    float inv0 = 1.0f / l0;
    float inv1 = 1.0f / l1;
    float* O0 = g_attn + (size_t)(b * S_LEN + row_lo) * D_MODEL + h * DK;
    float* O1 = O0 + (size_t)8 * D_MODEL;
#pragma unroll
    for (int nt = 0; nt < 8; nt++) {
        int col = nt * 8 + (lane & 3) * 2;
        *(float2*)(O0 + col) = make_float2(oacc[nt][0] * inv0, oacc[nt][1] * inv0);
        *(float2*)(O1 + col) = make_float2(oacc[nt][2] * inv1, oacc[nt][3] * inv1);
    }
}

// ---------------- launch ------------------------------------------------------
extern "C" void kernel_launch(void* const* d_in, const int* in_sizes, int n_in,
                              void* d_out, int out_size)
{
    const float* x  = (const float*)d_in[0];
    const float* Wq = (const float*)d_in[1];
    const float* bq = (const float*)d_in[2];
    const float* Wk = (const float*)d_in[3];
    const float* bk = (const float*)d_in[4];
    const float* Wv = (const float*)d_in[5];
    const float* bv = (const float*)d_in[6];
    const float* Wo = (const float*)d_in[7];
    const float* bo = (const float*)d_in[8];
    float* out = (float*)d_out;

    static int configured = 0;
    if (!configured) {
        cudaFuncSetAttribute(tc_gemm_qkv, cudaFuncAttributeMaxDynamicSharedMemorySize, GSMEM_TOTAL);
        cudaFuncSetAttribute(tc_gemm_out, cudaFuncAttributeMaxDynamicSharedMemorySize, GSMEM_TOTAL);
        cudaFuncSetAttribute(attn_mma_kernel, cudaFuncAttributeMaxDynamicSharedMemorySize, A_SMEM);
        configured = 1;
    }

    // 1) Q,K,V projections (bf16 split mma.sync)
    dim3 g_qkv(D_MODEL / GBN, M_TOT / GBM, 3);
    tc_gemm_qkv<<<g_qkv, 256, GSMEM_TOTAL>>>(x, Wq, bq, Wk, bk, Wv, bv);

    // 2) RoPE + scale + hi/lo split
    int n_pairs = BATCH * S_LEN * NHEAD * 32;
    prep_kernel<<<(n_pairs + 255) / 256, 256>>>();

    // 3) causal attention on tensor pipe
    dim3 g_att(S_LEN / 64, BATCH * NHEAD);
    attn_mma_kernel<<<g_att, 128, A_SMEM>>>();

    // 4) output projection (bf16 split mma.sync)
    dim3 g_out(D_MODEL / GBN, M_TOT / GBM);
    tc_gemm_out<<<g_out, 256, GSMEM_TOTAL>>>(Wo, bo, out);
}

// round 5
// speedup vs baseline: 2.8693x; 1.0621x over previous
#include <cuda_runtime.h>
#include <cuda_bf16.h>
#include <math.h>
#include <stdint.h>

#define D_MODEL 1024
#define S_LEN   2048
#define BATCH   2
#define NHEAD   16
#define DK      64
#define M_TOT   (BATCH * S_LEN)   // 4096
#define SCALE   0.125f            // 1/sqrt(64)

// ---------------- scratch (device globals; no allocations allowed) ----------
__device__ __nv_bfloat16 g_Xhi[M_TOT * D_MODEL];
__device__ __nv_bfloat16 g_Xlo[M_TOT * D_MODEL];
__device__ __nv_bfloat16 g_Wqhi[D_MODEL * D_MODEL];
__device__ __nv_bfloat16 g_Wqlo[D_MODEL * D_MODEL];
__device__ __nv_bfloat16 g_Wkhi[D_MODEL * D_MODEL];
__device__ __nv_bfloat16 g_Wklo[D_MODEL * D_MODEL];
__device__ __nv_bfloat16 g_Wvhi[D_MODEL * D_MODEL];
__device__ __nv_bfloat16 g_Wvlo[D_MODEL * D_MODEL];
__device__ __nv_bfloat16 g_Wohi[D_MODEL * D_MODEL];
__device__ __nv_bfloat16 g_Wolo[D_MODEL * D_MODEL];
__device__ __nv_bfloat16 g_Qhi[M_TOT * D_MODEL];
__device__ __nv_bfloat16 g_Qlo[M_TOT * D_MODEL];
__device__ __nv_bfloat16 g_Khi[M_TOT * D_MODEL];
__device__ __nv_bfloat16 g_Klo[M_TOT * D_MODEL];
__device__ __nv_bfloat16 g_Vhi[M_TOT * D_MODEL];
__device__ __nv_bfloat16 g_Vlo[M_TOT * D_MODEL];
__device__ __nv_bfloat16 g_attnhi[M_TOT * D_MODEL];
__device__ __nv_bfloat16 g_attnlo[M_TOT * D_MODEL];
__device__ float g_cos[S_LEN * 32];
__device__ float g_sin[S_LEN * 32];

// ---------------- common helpers --------------------------------------------
__device__ __forceinline__ uint32_t smem_u32(const void* p) {
    uint32_t a;
    asm("{ .reg .u64 t; cvta.to.shared.u64 t, %1; cvt.u32.u64 %0, t; }" : "=r"(a) : "l"(p));
    return a;
}

__device__ __forceinline__ void ldsm_x4(uint32_t* r, uint32_t addr) {
    asm volatile("ldmatrix.sync.aligned.m8n8.x4.shared.b16 {%0,%1,%2,%3}, [%4];"
                 : "=r"(r[0]), "=r"(r[1]), "=r"(r[2]), "=r"(r[3]) : "r"(addr));
}

__device__ __forceinline__ void ldsm_x4t(uint32_t* r, uint32_t addr) {
    asm volatile("ldmatrix.sync.aligned.m8n8.x4.trans.shared.b16 {%0,%1,%2,%3}, [%4];"
                 : "=r"(r[0]), "=r"(r[1]), "=r"(r[2]), "=r"(r[3]) : "r"(addr));
}

__device__ __forceinline__ void mma_bf16(float* c, const uint32_t* a,
                                         uint32_t b0, uint32_t b1) {
    asm volatile("mma.sync.aligned.m16n8k16.row.col.f32.bf16.bf16.f32 "
                 "{%0,%1,%2,%3}, {%4,%5,%6,%7}, {%8,%9}, {%0,%1,%2,%3};"
                 : "+f"(c[0]), "+f"(c[1]), "+f"(c[2]), "+f"(c[3])
                 : "r"(a[0]), "r"(a[1]), "r"(a[2]), "r"(a[3]), "r"(b0), "r"(b1));
}

__device__ __forceinline__ uint32_t pack2_hi(float a, float b, float& ra, float& rb) {
    __nv_bfloat16 ha = __float2bfloat16_rn(a);
    __nv_bfloat16 hb = __float2bfloat16_rn(b);
    ra = a - __bfloat162float(ha);
    rb = b - __bfloat162float(hb);
    union { __nv_bfloat162 h; uint32_t u; } c;
    c.h = __halves2bfloat162(ha, hb);
    return c.u;
}

__device__ __forceinline__ uint32_t pack2(float a, float b) {
    union { __nv_bfloat162 h; uint32_t u; } c;
    c.h = __halves2bfloat162(__float2bfloat16_rn(a), __float2bfloat16_rn(b));
    return c.u;
}

#define CP16(saddr, gptr) \
    asm volatile("cp.async.cg.shared.global [%0], [%1], 16;" :: "r"(saddr), "l"(gptr))
#define CP_COMMIT() asm volatile("cp.async.commit_group;" ::: "memory")
#define CP_WAIT0()  asm volatile("cp.async.wait_group 0;" ::: "memory")
#define CP_WAIT1()  asm volatile("cp.async.wait_group 1;" ::: "memory")

// ---------------- rope table + input split -----------------------------------
__global__ void rope_table_kernel()
{
    int idx = blockIdx.x * blockDim.x + threadIdx.x;
    if (idx >= S_LEN * 32) return;
    int s = idx >> 5, i = idx & 31;
    float inv_freq = __expf(-(float)(2 * i) * (9.210340371976184f / 64.0f));
    float ang = (float)s * inv_freq;
    g_cos[idx] = cosf(ang);
    g_sin[idx] = sinf(ang);
}

// split x (1M float4) + Wq,Wk,Wv,Wo (256K float4 each) into bf16 hi/lo
__global__ void split_all(const float* __restrict__ x,  const float* __restrict__ Wq,
                          const float* __restrict__ Wk, const float* __restrict__ Wv,
                          const float* __restrict__ Wo)
{
    int t = blockIdx.x * blockDim.x + threadIdx.x;   // 0..2M-1
    const float* src;
    __nv_bfloat16 *dh, *dl;
    size_t off;
    if (t < (1 << 20)) { src = x; dh = g_Xhi; dl = g_Xlo; off = t; }
    else {
        int r = t - (1 << 20);
        int w = r >> 18;
        off = (size_t)(r & ((1 << 18) - 1));
        if      (w == 0) { src = Wq; dh = g_Wqhi; dl = g_Wqlo; }
        else if (w == 1) { src = Wk; dh = g_Wkhi; dl = g_Wklo; }
        else if (w == 2) { src = Wv; dh = g_Wvhi; dl = g_Wvlo; }
        else             { src = Wo; dh = g_Wohi; dl = g_Wolo; }
    }
    float4 v = ((const float4*)src)[off];
    float r0, r1, r2, r3;
    uint2 hi, lo;
    hi.x = pack2_hi(v.x, v.y, r0, r1);
    hi.y = pack2_hi(v.z, v.w, r2, r3);
    lo.x = pack2(r0, r1);
    lo.y = pack2(r2, r3);
    ((uint2*)dh)[off] = hi;
    ((uint2*)dl)[off] = lo;
}

// =================== bf16 split GEMM v2 (cp.async, pre-split inputs) =========
#define GBK 32
#define GCHUNKS (D_MODEL / GBK)           // 32
#define ROWH   40                         // 80B row stride, conflict-free
#define ARR_B  (128 * ROWH * 2)           // 10240
#define STG_B  (4 * ARR_B)                // 40960
#define GSMEM_TOTAL (2 * STG_B)           // 81920

__device__ __forceinline__ void gemm_v2_core(
    const __nv_bfloat16* __restrict__ Ahi, const __nv_bfloat16* __restrict__ Alo,
    const __nv_bfloat16* __restrict__ Bhi, const __nv_bfloat16* __restrict__ Blo,
    int bm, int bn, float (&acc)[4][4][4])
{
    extern __shared__ char smem[];
    const uint32_t sb = smem_u32(smem);
    const int tid  = threadIdx.x;
    const int wid  = tid >> 5;
    const int lane = tid & 31;
    const int warp_m = (wid >> 2) * 64;
    const int warp_n = (wid & 3) * 32;

#pragma unroll
    for (int i = 0; i < 4; i++)
#pragma unroll
        for (int j = 0; j < 4; j++)
#pragma unroll
            for (int k = 0; k < 4; k++) acc[i][j][k] = 0.f;

    auto issue = [&](int stg, int c) {
        const uint32_t st = sb + stg * STG_B;
        const int k0 = c * GBK;
#pragma unroll
        for (int it = 0; it < 2; it++) {
            int slot = tid + it * 256;            // 0..511
            int r  = slot >> 2;                   // 0..127
            int c8 = (slot & 3) * 8;              // halves
            uint32_t soff = (uint32_t)(r * ROWH + c8) * 2;
            size_t ga = (size_t)(bm + r) * D_MODEL + k0 + c8;
            size_t gb = (size_t)(bn + r) * D_MODEL + k0 + c8;
            CP16(st + soff,             (const char*)(Ahi + ga));
            CP16(st + ARR_B + soff,     (const char*)(Alo + ga));
            CP16(st + 2 * ARR_B + soff, (const char*)(Bhi + gb));
            CP16(st + 3 * ARR_B + soff, (const char*)(Blo + gb));
        }
    };

    issue(0, 0);
    CP_COMMIT();

    const int qrow = lane & 15;
    const int qcol = (lane >> 4) << 3;

    for (int c = 0; c < GCHUNKS; c++) {
        if (c + 1 < GCHUNKS) { issue((c + 1) & 1, c + 1); CP_COMMIT(); CP_WAIT1(); }
        else                 { CP_WAIT0(); }
        __syncthreads();

        const uint32_t st = sb + (c & 1) * STG_B;
        const uint32_t aBase = st + (uint32_t)((warp_m + qrow) * ROWH + qcol) * 2;
        const uint32_t bBase = st + 2 * ARR_B + (uint32_t)((warp_n + qrow) * ROWH + qcol) * 2;

#pragma unroll
        for (int ks = 0; ks < 2; ks++) {
            const uint32_t ko = (uint32_t)(ks * 16) * 2;
            uint32_t bh[2][4], bl[2][4];
#pragma unroll
            for (int nt = 0; nt < 2; nt++) {
                ldsm_x4(bh[nt], bBase + nt * (16 * ROWH * 2) + ko);
                ldsm_x4(bl[nt], bBase + ARR_B + nt * (16 * ROWH * 2) + ko);
            }
#pragma unroll
            for (int mi = 0; mi < 4; mi++) {
                uint32_t ah[4], al[4];
                ldsm_x4(ah, aBase + mi * (16 * ROWH * 2) + ko);
                ldsm_x4(al, aBase + ARR_B + mi * (16 * ROWH * 2) + ko);
#pragma unroll
                for (int nt = 0; nt < 2; nt++)
#pragma unroll
                    for (int nj = 0; nj < 2; nj++) {
                        float* cc = acc[mi][nt * 2 + nj];
                        mma_bf16(cc, ah, bh[nt][nj], bh[nt][nj + 2]);
                        mma_bf16(cc, ah, bl[nt][nj], bl[nt][nj + 2]);
                        mma_bf16(cc, al, bh[nt][nj], bh[nt][nj + 2]);
                    }
            }
        }
        __syncthreads();
    }
}

// QKV GEMM + fused bias + RoPE + scale + hi/lo split epilogue
__global__ __launch_bounds__(256, 2)
void tc_qkv_v2(const float* __restrict__ bq, const float* __restrict__ bk,
               const float* __restrict__ bv)
{
    const int z = blockIdx.z;
    const __nv_bfloat16 *Bh, *Bl;
    const float* bias;
    __nv_bfloat16 *Dh, *Dl;
    if (z == 0)      { Bh = g_Wqhi; Bl = g_Wqlo; bias = bq; Dh = g_Qhi; Dl = g_Qlo; }
    else if (z == 1) { Bh = g_Wkhi; Bl = g_Wklo; bias = bk; Dh = g_Khi; Dl = g_Klo; }
    else             { Bh = g_Wvhi; Bl = g_Wvlo; bias = bv; Dh = g_Vhi; Dl = g_Vlo; }

    const int bm = blockIdx.y * 128;
    const int bn = blockIdx.x * 128;
    float acc[4][4][4];
    gemm_v2_core(g_Xhi, g_Xlo, Bh, Bl, bm, bn, acc);

    const int wid  = threadIdx.x >> 5;
    const int lane = threadIdx.x & 31;
    const int warp_m = (wid >> 2) * 64;
    const int warp_n = (wid & 3) * 32;
    const int erow = lane >> 2;
    const int ecol = (lane & 3) * 2;

#pragma unroll
    for (int mi = 0; mi < 4; mi++)
#pragma unroll
        for (int nt = 0; nt < 2; nt++)
#pragma unroll
            for (int nj = 0; nj < 2; nj++) {
                float* cc = acc[mi][nt * 2 + nj];
                int m = bm + warp_m + mi * 16 + erow;
                int n = bn + warp_n + nt * 16 + nj * 8 + ecol;
                float v0 = cc[0] + bias[n], v1 = cc[1] + bias[n + 1];
                float w0 = cc[2] + bias[n], w1 = cc[3] + bias[n + 1];
                if (z < 2) {
                    int i  = (n & 63) >> 1;
                    int s0 = (m & 2047) * 32 + i;
                    int s1 = ((m + 8) & 2047) * 32 + i;
                    float cs0 = g_cos[s0], sn0 = g_sin[s0];
                    float cs1 = g_cos[s1], sn1 = g_sin[s1];
                    float t0 = v0 * cs0 - v1 * sn0, t1 = v0 * sn0 + v1 * cs0;
                    float u0 = w0 * cs1 - w1 * sn1, u1 = w0 * sn1 + w1 * cs1;
                    if (z == 0) { t0 *= SCALE; t1 *= SCALE; u0 *= SCALE; u1 *= SCALE; }
                    v0 = t0; v1 = t1; w0 = u0; w1 = u1;
                }
                float r0, r1;
                uint32_t h0 = pack2_hi(v0, v1, r0, r1), l0v = pack2(r0, r1);
                uint32_t h1 = pack2_hi(w0, w1, r0, r1), l1v = pack2(r0, r1);
                size_t o0 = (size_t)m * D_MODEL + n;
                size_t o1 = (size_t)(m + 8) * D_MODEL + n;
                *(uint32_t*)(Dh + o0) = h0;
                *(uint32_t*)(Dl + o0) = l0v;
                *(uint32_t*)(Dh + o1) = h1;
                *(uint32_t*)(Dl + o1) = l1v;
            }
}

// output projection: bf16 split inputs, fp32 out + bias
__global__ __launch_bounds__(256, 2)
void tc_out_v2(const float* __restrict__ bo, float* __restrict__ out)
{
    const int bm = blockIdx.y * 128;
    const int bn = blockIdx.x * 128;
    float acc[4][4][4];
    gemm_v2_core(g_attnhi, g_attnlo, g_Wohi, g_Wolo, bm, bn, acc);

    const int wid  = threadIdx.x >> 5;
    const int lane = threadIdx.x & 31;
    const int warp_m = (wid >> 2) * 64;
    const int warp_n = (wid & 3) * 32;
    const int erow = lane >> 2;
    const int ecol = (lane & 3) * 2;

#pragma unroll
    for (int mi = 0; mi < 4; mi++)
#pragma unroll
        for (int nt = 0; nt < 2; nt++)
#pragma unroll
            for (int nj = 0; nj < 2; nj++) {
                float* cc = acc[mi][nt * 2 + nj];
                int m = bm + warp_m + mi * 16 + erow;
                int n = bn + warp_n + nt * 16 + nj * 8 + ecol;
                float2 v0 = make_float2(cc[0] + bo[n], cc[1] + bo[n + 1]);
                float2 v1 = make_float2(cc[2] + bo[n], cc[3] + bo[n + 1]);
                *(float2*)(out + (size_t)m * D_MODEL + n)       = v0;
                *(float2*)(out + (size_t)(m + 8) * D_MODEL + n) = v1;
            }
}

// ---------------- tensor-core causal flash attention -------------------------
#define AROW   72
#define A_ARR  (64 * AROW * 2)
#define SQ_HI  0
#define SQ_LO  A_ARR
#define STG0   (2 * A_ARR)
#define ASTG_B (4 * A_ARR)
#define A_SMEM (2 * A_ARR + 2 * ASTG_B)   // 92160

__global__ __launch_bounds__(128)
void attn_mma_kernel()
{
    extern __shared__ char smem[];
    const uint32_t sb = smem_u32(smem);
    const int tid  = threadIdx.x;
    const int wid  = tid >> 5;
    const int lane = tid & 31;
    const int qb = blockIdx.x;
    const int bh = blockIdx.y;
    const int b  = bh >> 4;
    const int h  = bh & 15;
    const int q0 = qb * 64;

    const size_t qgbase = (size_t)(b * S_LEN + q0) * D_MODEL + h * DK;
    const size_t kgbase = (size_t)(b * S_LEN) * D_MODEL + h * DK;

    auto issue_tile = [&](int stg, int kt) {
        const uint32_t sbase = sb + STG0 + stg * ASTG_B;
        const size_t g0 = kgbase + (size_t)(kt * 64) * D_MODEL;
#pragma unroll
        for (int it = 0; it < 4; it++) {
            int slot = tid + it * 128;
            int r  = slot >> 3;
            int c8 = (slot & 7) * 8;
            uint32_t soff = (uint32_t)(r * AROW + c8) * 2;
            const size_t go = g0 + (size_t)r * D_MODEL + c8;
            CP16(sbase + soff,             (const char*)(g_Khi + go));
            CP16(sbase + A_ARR + soff,     (const char*)(g_Klo + go));
            CP16(sbase + 2 * A_ARR + soff, (const char*)(g_Vhi + go));
            CP16(sbase + 3 * A_ARR + soff, (const char*)(g_Vlo + go));
        }
    };

    issue_tile(0, 0);
    CP_COMMIT();

#pragma unroll
    for (int it = 0; it < 4; it++) {
        int slot = tid + it * 128;
        int r  = slot >> 3;
        int c8 = (slot & 7) * 8;
        uint32_t soff = (uint32_t)(r * AROW + c8) * 2;
        const size_t go = qgbase + (size_t)r * D_MODEL + c8;
        *(uint4*)(smem + SQ_HI + soff) = *(const uint4*)(g_Qhi + go);
        *(uint4*)(smem + SQ_LO + soff) = *(const uint4*)(g_Qlo + go);
    }
    __syncthreads();

    uint32_t qh[4][4], ql[4][4];
#pragma unroll
    for (int t = 0; t < 4; t++) {
        uint32_t addr = sb + SQ_HI +
            (uint32_t)((wid * 16 + (lane & 15)) * AROW + t * 16 + ((lane >> 4) << 3)) * 2;
        ldsm_x4(qh[t], addr);
        ldsm_x4(ql[t], addr + A_ARR);
    }

    float oacc[8][4];
#pragma unroll
    for (int nt = 0; nt < 8; nt++)
#pragma unroll
        for (int j = 0; j < 4; j++) oacc[nt][j] = 0.f;
    float m0 = -1e30f, m1 = -1e30f, l0 = 0.f, l1 = 0.f;

    const int row_lo = q0 + wid * 16 + (lane >> 2);
    const int ntiles = qb + 1;

    for (int kt = 0; kt < ntiles; kt++) {
        if (kt + 1 < ntiles) { issue_tile((kt + 1) & 1, kt + 1); CP_COMMIT(); CP_WAIT1(); }
        else                 { CP_WAIT0(); }
        __syncthreads();

        const uint32_t st = sb + STG0 + (kt & 1) * ASTG_B;

        float sc[8][4];
#pragma unroll
        for (int nt = 0; nt < 8; nt++)
#pragma unroll
            for (int j = 0; j < 4; j++) sc[nt][j] = 0.f;

#pragma unroll
        for (int t = 0; t < 4; t++) {
#pragma unroll
            for (int g = 0; g < 4; g++) {
                uint32_t addr = st +
                    (uint32_t)((g * 16 + (lane & 15)) * AROW + t * 16 + ((lane >> 4) << 3)) * 2;
                uint32_t kh4[4], kl4[4];
                ldsm_x4(kh4, addr);
                ldsm_x4(kl4, addr + A_ARR);
                mma_bf16(sc[2 * g],     qh[t], kh4[0], kh4[2]);
                mma_bf16(sc[2 * g],     qh[t], kl4[0], kl4[2]);
                mma_bf16(sc[2 * g],     ql[t], kh4[0], kh4[2]);
                mma_bf16(sc[2 * g + 1], qh[t], kh4[1], kh4[3]);
                mma_bf16(sc[2 * g + 1], qh[t], kl4[1], kl4[3]);
                mma_bf16(sc[2 * g + 1], ql[t], kh4[1], kh4[3]);
            }
        }

        if (kt == qb) {
#pragma unroll
            for (int nt = 0; nt < 8; nt++) {
                int col = kt * 64 + nt * 8 + (lane & 3) * 2;
                if (col     > row_lo)     sc[nt][0] = -1e30f;
                if (col + 1 > row_lo)     sc[nt][1] = -1e30f;
                if (col     > row_lo + 8) sc[nt][2] = -1e30f;
                if (col + 1 > row_lo + 8) sc[nt][3] = -1e30f;
            }
        }

        float mx0 = -1e30f, mx1 = -1e30f;
#pragma unroll
        for (int nt = 0; nt < 8; nt++) {
            mx0 = fmaxf(mx0, fmaxf(sc[nt][0], sc[nt][1]));
            mx1 = fmaxf(mx1, fmaxf(sc[nt][2], sc[nt][3]));
        }
        mx0 = fmaxf(mx0, __shfl_xor_sync(0xffffffffu, mx0, 1));
        mx0 = fmaxf(mx0, __shfl_xor_sync(0xffffffffu, mx0, 2));
        mx1 = fmaxf(mx1, __shfl_xor_sync(0xffffffffu, mx1, 1));
        mx1 = fmaxf(mx1, __shfl_xor_sync(0xffffffffu, mx1, 2));

        float mn0 = fmaxf(m0, mx0);
        float mn1 = fmaxf(m1, mx1);
        float corr0 = __expf(m0 - mn0);
        float corr1 = __expf(m1 - mn1);
        m0 = mn0; m1 = mn1;

        float sum0 = 0.f, sum1 = 0.f;
#pragma unroll
        for (int nt = 0; nt < 8; nt++) {
            sc[nt][0] = __expf(sc[nt][0] - mn0);
            sc[nt][1] = __expf(sc[nt][1] - mn0);
            sc[nt][2] = __expf(sc[nt][2] - mn1);
            sc[nt][3] = __expf(sc[nt][3] - mn1);
            sum0 += sc[nt][0] + sc[nt][1];
            sum1 += sc[nt][2] + sc[nt][3];
        }
        sum0 += __shfl_xor_sync(0xffffffffu, sum0, 1);
        sum0 += __shfl_xor_sync(0xffffffffu, sum0, 2);
        sum1 += __shfl_xor_sync(0xffffffffu, sum1, 1);
        sum1 += __shfl_xor_sync(0xffffffffu, sum1, 2);
        l0 = l0 * corr0 + sum0;
        l1 = l1 * corr1 + sum1;

#pragma unroll
        for (int nt = 0; nt < 8; nt++) {
            oacc[nt][0] *= corr0; oacc[nt][1] *= corr0;
            oacc[nt][2] *= corr1; oacc[nt][3] *= corr1;
        }

        uint32_t ph[4][4], pl[4][4];
        float r0, r1;
#pragma unroll
        for (int t = 0; t < 4; t++) {
            ph[t][0] = pack2_hi(sc[2 * t][0], sc[2 * t][1], r0, r1);
            pl[t][0] = pack2(r0, r1);
            ph[t][1] = pack2_hi(sc[2 * t][2], sc[2 * t][3], r0, r1);
            pl[t][1] = pack2(r0, r1);
            ph[t][2] = pack2_hi(sc[2 * t + 1][0], sc[2 * t + 1][1], r0, r1);
            pl[t][2] = pack2(r0, r1);
            ph[t][3] = pack2_hi(sc[2 * t + 1][2], sc[2 * t + 1][3], r0, r1);
            pl[t][3] = pack2(r0, r1);
        }

#pragma unroll
        for (int t = 0; t < 4; t++) {
#pragma unroll
            for (int g = 0; g < 4; g++) {
                uint32_t addr = st + 2 * A_ARR +
                    (uint32_t)((t * 16 + (lane & 7) + ((lane >> 3) & 1) * 8) * AROW +
                               g * 16 + ((lane >> 4) << 3)) * 2;
                uint32_t vh4[4], vl4[4];
                ldsm_x4t(vh4, addr);
                ldsm_x4t(vl4, addr + A_ARR);
                mma_bf16(oacc[2 * g],     ph[t], vh4[0], vh4[1]);
                mma_bf16(oacc[2 * g],     ph[t], vl4[0], vl4[1]);
                mma_bf16(oacc[2 * g],     pl[t], vh4[0], vh4[1]);
                mma_bf16(oacc[2 * g + 1], ph[t], vh4[2], vh4[3]);
                mma_bf16(oacc[2 * g + 1], ph[t], vl4[2], vl4[3]);
                mma_bf16(oacc[2 * g + 1], pl[t], vh4[2], vh4[3]);
            }
        }
        __syncthreads();
    }

    // ---- epilogue: normalize + hi/lo split to global bf16 ----
    float inv0 = 1.0f / l0;
    float inv1 = 1.0f / l1;
    size_t base0 = (size_t)(b * S_LEN + row_lo) * D_MODEL + h * DK;
    size_t base1 = base0 + (size_t)8 * D_MODEL;
    float r0, r1;
#pragma unroll
    for (int nt = 0; nt < 8; nt++) {
        int col = nt * 8 + (lane & 3) * 2;
        uint32_t h0 = pack2_hi(oacc[nt][0] * inv0, oacc[nt][1] * inv0, r0, r1);
        uint32_t l0v = pack2(r0, r1);
        uint32_t h1 = pack2_hi(oacc[nt][2] * inv1, oacc[nt][3] * inv1, r0, r1);
        uint32_t l1v = pack2(r0, r1);
        *(uint32_t*)(g_attnhi + base0 + col) = h0;
        *(uint32_t*)(g_attnlo + base0 + col) = l0v;
        *(uint32_t*)(g_attnhi + base1 + col) = h1;
        *(uint32_t*)(g_attnlo + base1 + col) = l1v;
    }
}

// ---------------- launch ------------------------------------------------------
extern "C" void kernel_launch(void* const* d_in, const int* in_sizes, int n_in,
                              void* d_out, int out_size)
{
    const float* x  = (const float*)d_in[0];
    const float* Wq = (const float*)d_in[1];
    const float* bq = (const float*)d_in[2];
    const float* Wk = (const float*)d_in[3];
    const float* bk = (const float*)d_in[4];
    const float* Wv = (const float*)d_in[5];
    const float* bv = (const float*)d_in[6];
    const float* Wo = (const float*)d_in[7];
    const float* bo = (const float*)d_in[8];
    float* out = (float*)d_out;

    static int configured = 0;
    if (!configured) {
        cudaFuncSetAttribute(tc_qkv_v2, cudaFuncAttributeMaxDynamicSharedMemorySize, GSMEM_TOTAL);
        cudaFuncSetAttribute(tc_out_v2, cudaFuncAttributeMaxDynamicSharedMemorySize, GSMEM_TOTAL);
        cudaFuncSetAttribute(attn_mma_kernel, cudaFuncAttributeMaxDynamicSharedMemorySize, A_SMEM);
        configured = 1;
    }

    // 0) rope table + hi/lo split of x and weights
    rope_table_kernel<<<(S_LEN * 32 + 255) / 256, 256>>>();
    split_all<<<(2 * 1024 * 1024) / 256, 256>>>(x, Wq, Wk, Wv, Wo);

    // 1) QKV projections + fused RoPE/scale/split epilogue
    dim3 g_qkv(D_MODEL / 128, M_TOT / 128, 3);
    tc_qkv_v2<<<g_qkv, 256, GSMEM_TOTAL>>>(bq, bk, bv);

    // 2) causal attention on tensor pipe
    dim3 g_att(S_LEN / 64, BATCH * NHEAD);
    attn_mma_kernel<<<g_att, 128, A_SMEM>>>();

    // 3) output projection
    dim3 g_out(D_MODEL / 128, M_TOT / 128);
    tc_out_v2<<<g_out, 256, GSMEM_TOTAL>>>(bo, out);
}

// round 6
// speedup vs baseline: 2.8708x; 1.0005x over previous
#include <cuda_runtime.h>
#include <cuda_bf16.h>
#include <math.h>
#include <stdint.h>

#define D_MODEL 1024
#define S_LEN   2048
#define BATCH   2
#define NHEAD   16
#define DK      64
#define M_TOT   (BATCH * S_LEN)   // 4096
#define SCALE   0.125f            // 1/sqrt(64)

// ---------------- scratch (device globals; no allocations allowed) ----------
__device__ __nv_bfloat16 g_Xhi[M_TOT * D_MODEL];
__device__ __nv_bfloat16 g_Xlo[M_TOT * D_MODEL];
__device__ __nv_bfloat16 g_Wqhi[D_MODEL * D_MODEL];
__device__ __nv_bfloat16 g_Wqlo[D_MODEL * D_MODEL];
__device__ __nv_bfloat16 g_Wkhi[D_MODEL * D_MODEL];
__device__ __nv_bfloat16 g_Wklo[D_MODEL * D_MODEL];
__device__ __nv_bfloat16 g_Wvhi[D_MODEL * D_MODEL];
__device__ __nv_bfloat16 g_Wvlo[D_MODEL * D_MODEL];
__device__ __nv_bfloat16 g_Wohi[D_MODEL * D_MODEL];
__device__ __nv_bfloat16 g_Wolo[D_MODEL * D_MODEL];
__device__ __nv_bfloat16 g_Qhi[M_TOT * D_MODEL];
__device__ __nv_bfloat16 g_Qlo[M_TOT * D_MODEL];
__device__ __nv_bfloat16 g_Khi[M_TOT * D_MODEL];
__device__ __nv_bfloat16 g_Klo[M_TOT * D_MODEL];
__device__ __nv_bfloat16 g_Vhi[M_TOT * D_MODEL];
__device__ __nv_bfloat16 g_Vlo[M_TOT * D_MODEL];
__device__ __nv_bfloat16 g_attnhi[M_TOT * D_MODEL];
__device__ __nv_bfloat16 g_attnlo[M_TOT * D_MODEL];
__device__ float g_cos[S_LEN * 32];
__device__ float g_sin[S_LEN * 32];

// ---------------- common helpers --------------------------------------------
__device__ __forceinline__ uint32_t smem_u32(const void* p) {
    uint32_t a;
    asm("{ .reg .u64 t; cvta.to.shared.u64 t, %1; cvt.u32.u64 %0, t; }" : "=r"(a) : "l"(p));
    return a;
}

__device__ __forceinline__ void ldsm_x4(uint32_t* r, uint32_t addr) {
    asm volatile("ldmatrix.sync.aligned.m8n8.x4.shared.b16 {%0,%1,%2,%3}, [%4];"
                 : "=r"(r[0]), "=r"(r[1]), "=r"(r[2]), "=r"(r[3]) : "r"(addr));
}

__device__ __forceinline__ void ldsm_x4t(uint32_t* r, uint32_t addr) {
    asm volatile("ldmatrix.sync.aligned.m8n8.x4.trans.shared.b16 {%0,%1,%2,%3}, [%4];"
                 : "=r"(r[0]), "=r"(r[1]), "=r"(r[2]), "=r"(r[3]) : "r"(addr));
}

__device__ __forceinline__ void mma_bf16(float* c, const uint32_t* a,
                                         uint32_t b0, uint32_t b1) {
    asm volatile("mma.sync.aligned.m16n8k16.row.col.f32.bf16.bf16.f32 "
                 "{%0,%1,%2,%3}, {%4,%5,%6,%7}, {%8,%9}, {%0,%1,%2,%3};"
                 : "+f"(c[0]), "+f"(c[1]), "+f"(c[2]), "+f"(c[3])
                 : "r"(a[0]), "r"(a[1]), "r"(a[2]), "r"(a[3]), "r"(b0), "r"(b1));
}

__device__ __forceinline__ uint32_t pack2_hi(float a, float b, float& ra, float& rb) {
    __nv_bfloat16 ha = __float2bfloat16_rn(a);
    __nv_bfloat16 hb = __float2bfloat16_rn(b);
    ra = a - __bfloat162float(ha);
    rb = b - __bfloat162float(hb);
    union { __nv_bfloat162 h; uint32_t u; } c;
    c.h = __halves2bfloat162(ha, hb);
    return c.u;
}

__device__ __forceinline__ uint32_t pack2(float a, float b) {
    union { __nv_bfloat162 h; uint32_t u; } c;
    c.h = __halves2bfloat162(__float2bfloat16_rn(a), __float2bfloat16_rn(b));
    return c.u;
}

#define CP16(saddr, gptr) \
    asm volatile("cp.async.cg.shared.global [%0], [%1], 16;" :: "r"(saddr), "l"(gptr))
#define CP_COMMIT() asm volatile("cp.async.commit_group;" ::: "memory")
#define CP_WAIT0()  asm volatile("cp.async.wait_group 0;" ::: "memory")
#define CP_WAIT1()  asm volatile("cp.async.wait_group 1;" ::: "memory")

// ---------------- rope table + input split -----------------------------------
__global__ void rope_table_kernel()
{
    int idx = blockIdx.x * blockDim.x + threadIdx.x;
    if (idx >= S_LEN * 32) return;
    int s = idx >> 5, i = idx & 31;
    float inv_freq = __expf(-(float)(2 * i) * (9.210340371976184f / 64.0f));
    float ang = (float)s * inv_freq;
    g_cos[idx] = cosf(ang);
    g_sin[idx] = sinf(ang);
}

__global__ void split_all(const float* __restrict__ x,  const float* __restrict__ Wq,
                          const float* __restrict__ Wk, const float* __restrict__ Wv,
                          const float* __restrict__ Wo)
{
    int t = blockIdx.x * blockDim.x + threadIdx.x;   // 0..2M-1
    const float* src;
    __nv_bfloat16 *dh, *dl;
    size_t off;
    if (t < (1 << 20)) { src = x; dh = g_Xhi; dl = g_Xlo; off = t; }
    else {
        int r = t - (1 << 20);
        int w = r >> 18;
        off = (size_t)(r & ((1 << 18) - 1));
        if      (w == 0) { src = Wq; dh = g_Wqhi; dl = g_Wqlo; }
        else if (w == 1) { src = Wk; dh = g_Wkhi; dl = g_Wklo; }
        else if (w == 2) { src = Wv; dh = g_Wvhi; dl = g_Wvlo; }
        else             { src = Wo; dh = g_Wohi; dl = g_Wolo; }
    }
    float4 v = ((const float4*)src)[off];
    float r0, r1, r2, r3;
    uint2 hi, lo;
    hi.x = pack2_hi(v.x, v.y, r0, r1);
    hi.y = pack2_hi(v.z, v.w, r2, r3);
    lo.x = pack2(r0, r1);
    lo.y = pack2(r2, r3);
    ((uint2*)dh)[off] = hi;
    ((uint2*)dl)[off] = lo;
}

// =================== bf16 split GEMM v2 (cp.async, pre-split inputs) =========
#define GBK 32
#define GCHUNKS (D_MODEL / GBK)           // 32
#define ROWH   40
#define ARR_B  (128 * ROWH * 2)           // 10240
#define STG_B  (4 * ARR_B)                // 40960
#define GSMEM_TOTAL (2 * STG_B)           // 81920

__device__ __forceinline__ void gemm_v2_core(
    const __nv_bfloat16* __restrict__ Ahi, const __nv_bfloat16* __restrict__ Alo,
    const __nv_bfloat16* __restrict__ Bhi, const __nv_bfloat16* __restrict__ Blo,
    int bm, int bn, float (&acc)[4][4][4])
{
    extern __shared__ char smem[];
    const uint32_t sb = smem_u32(smem);
    const int tid  = threadIdx.x;
    const int wid  = tid >> 5;
    const int lane = tid & 31;
    const int warp_m = (wid >> 2) * 64;
    const int warp_n = (wid & 3) * 32;

#pragma unroll
    for (int i = 0; i < 4; i++)
#pragma unroll
        for (int j = 0; j < 4; j++)
#pragma unroll
            for (int k = 0; k < 4; k++) acc[i][j][k] = 0.f;

    auto issue = [&](int stg, int c) {
        const uint32_t st = sb + stg * STG_B;
        const int k0 = c * GBK;
#pragma unroll
        for (int it = 0; it < 2; it++) {
            int slot = tid + it * 256;
            int r  = slot >> 2;
            int c8 = (slot & 3) * 8;
            uint32_t soff = (uint32_t)(r * ROWH + c8) * 2;
            size_t ga = (size_t)(bm + r) * D_MODEL + k0 + c8;
            size_t gb = (size_t)(bn + r) * D_MODEL + k0 + c8;
            CP16(st + soff,             (const char*)(Ahi + ga));
            CP16(st + ARR_B + soff,     (const char*)(Alo + ga));
            CP16(st + 2 * ARR_B + soff, (const char*)(Bhi + gb));
            CP16(st + 3 * ARR_B + soff, (const char*)(Blo + gb));
        }
    };

    issue(0, 0);
    CP_COMMIT();

    const int qrow = lane & 15;
    const int qcol = (lane >> 4) << 3;

    for (int c = 0; c < GCHUNKS; c++) {
        if (c + 1 < GCHUNKS) { issue((c + 1) & 1, c + 1); CP_COMMIT(); CP_WAIT1(); }
        else                 { CP_WAIT0(); }
        __syncthreads();

        const uint32_t st = sb + (c & 1) * STG_B;
        const uint32_t aBase = st + (uint32_t)((warp_m + qrow) * ROWH + qcol) * 2;
        const uint32_t bBase = st + 2 * ARR_B + (uint32_t)((warp_n + qrow) * ROWH + qcol) * 2;

#pragma unroll
        for (int ks = 0; ks < 2; ks++) {
            const uint32_t ko = (uint32_t)(ks * 16) * 2;
            uint32_t bh[2][4], bl[2][4];
#pragma unroll
            for (int nt = 0; nt < 2; nt++) {
                ldsm_x4(bh[nt], bBase + nt * (16 * ROWH * 2) + ko);
                ldsm_x4(bl[nt], bBase + ARR_B + nt * (16 * ROWH * 2) + ko);
            }
#pragma unroll
            for (int mi = 0; mi < 4; mi++) {
                uint32_t ah[4], al[4];
                ldsm_x4(ah, aBase + mi * (16 * ROWH * 2) + ko);
                ldsm_x4(al, aBase + ARR_B + mi * (16 * ROWH * 2) + ko);
#pragma unroll
                for (int nt = 0; nt < 2; nt++)
#pragma unroll
                    for (int nj = 0; nj < 2; nj++) {
                        float* cc = acc[mi][nt * 2 + nj];
                        mma_bf16(cc, ah, bh[nt][nj], bh[nt][nj + 2]);
                        mma_bf16(cc, ah, bl[nt][nj], bl[nt][nj + 2]);
                        mma_bf16(cc, al, bh[nt][nj], bh[nt][nj + 2]);
                    }
            }
        }
        __syncthreads();
    }
}

__global__ __launch_bounds__(256, 2)
void tc_qkv_v2(const float* __restrict__ bq, const float* __restrict__ bk,
               const float* __restrict__ bv)
{
    const int z = blockIdx.z;
    const __nv_bfloat16 *Bh, *Bl;
    const float* bias;
    __nv_bfloat16 *Dh, *Dl;
    if (z == 0)      { Bh = g_Wqhi; Bl = g_Wqlo; bias = bq; Dh = g_Qhi; Dl = g_Qlo; }
    else if (z == 1) { Bh = g_Wkhi; Bl = g_Wklo; bias = bk; Dh = g_Khi; Dl = g_Klo; }
    else             { Bh = g_Wvhi; Bl = g_Wvlo; bias = bv; Dh = g_Vhi; Dl = g_Vlo; }

    const int bm = blockIdx.y * 128;
    const int bn = blockIdx.x * 128;
    float acc[4][4][4];
    gemm_v2_core(g_Xhi, g_Xlo, Bh, Bl, bm, bn, acc);

    const int wid  = threadIdx.x >> 5;
    const int lane = threadIdx.x & 31;
    const int warp_m = (wid >> 2) * 64;
    const int warp_n = (wid & 3) * 32;
    const int erow = lane >> 2;
    const int ecol = (lane & 3) * 2;

#pragma unroll
    for (int mi = 0; mi < 4; mi++)
#pragma unroll
        for (int nt = 0; nt < 2; nt++)
#pragma unroll
            for (int nj = 0; nj < 2; nj++) {
                float* cc = acc[mi][nt * 2 + nj];
                int m = bm + warp_m + mi * 16 + erow;
                int n = bn + warp_n + nt * 16 + nj * 8 + ecol;
                float v0 = cc[0] + bias[n], v1 = cc[1] + bias[n + 1];
                float w0 = cc[2] + bias[n], w1 = cc[3] + bias[n + 1];
                if (z < 2) {
                    int i  = (n & 63) >> 1;
                    int s0 = (m & 2047) * 32 + i;
                    int s1 = ((m + 8) & 2047) * 32 + i;
                    float cs0 = g_cos[s0], sn0 = g_sin[s0];
                    float cs1 = g_cos[s1], sn1 = g_sin[s1];
                    float t0 = v0 * cs0 - v1 * sn0, t1 = v0 * sn0 + v1 * cs0;
                    float u0 = w0 * cs1 - w1 * sn1, u1 = w0 * sn1 + w1 * cs1;
                    if (z == 0) { t0 *= SCALE; t1 *= SCALE; u0 *= SCALE; u1 *= SCALE; }
                    v0 = t0; v1 = t1; w0 = u0; w1 = u1;
                }
                float r0, r1;
                uint32_t h0 = pack2_hi(v0, v1, r0, r1), l0v = pack2(r0, r1);
                uint32_t h1 = pack2_hi(w0, w1, r0, r1), l1v = pack2(r0, r1);
                size_t o0 = (size_t)m * D_MODEL + n;
                size_t o1 = (size_t)(m + 8) * D_MODEL + n;
                *(uint32_t*)(Dh + o0) = h0;
                *(uint32_t*)(Dl + o0) = l0v;
                *(uint32_t*)(Dh + o1) = h1;
                *(uint32_t*)(Dl + o1) = l1v;
            }
}

__global__ __launch_bounds__(256, 2)
void tc_out_v2(const float* __restrict__ bo, float* __restrict__ out)
{
    const int bm = blockIdx.y * 128;
    const int bn = blockIdx.x * 128;
    float acc[4][4][4];
    gemm_v2_core(g_attnhi, g_attnlo, g_Wohi, g_Wolo, bm, bn, acc);

    const int wid  = threadIdx.x >> 5;
    const int lane = threadIdx.x & 31;
    const int warp_m = (wid >> 2) * 64;
    const int warp_n = (wid & 3) * 32;
    const int erow = lane >> 2;
    const int ecol = (lane & 3) * 2;

#pragma unroll
    for (int mi = 0; mi < 4; mi++)
#pragma unroll
        for (int nt = 0; nt < 2; nt++)
#pragma unroll
            for (int nj = 0; nj < 2; nj++) {
                float* cc = acc[mi][nt * 2 + nj];
                int m = bm + warp_m + mi * 16 + erow;
                int n = bn + warp_n + nt * 16 + nj * 8 + ecol;
                float2 v0 = make_float2(cc[0] + bo[n], cc[1] + bo[n + 1]);
                float2 v1 = make_float2(cc[2] + bo[n], cc[3] + bo[n + 1]);
                *(float2*)(out + (size_t)m * D_MODEL + n)       = v0;
                *(float2*)(out + (size_t)(m + 8) * D_MODEL + n) = v1;
            }
}

// ---------------- tensor-core causal flash attention v3 ----------------------
// 256 threads (8 warps), 128 q rows/block, 64-key tiles, 2 CTAs/SM target.
#define AROW   72
#define A_ARR  (64 * AROW * 2)            // 9216  (one K/V array)
#define AQ_ARR (128 * AROW * 2)           // 18432 (one Q array)
#define SQ_HI  0
#define SQ_LO  AQ_ARR
#define STG0   (2 * AQ_ARR)               // 36864
#define ASTG_B (4 * A_ARR)                // 36864 (Khi,Klo,Vhi,Vlo)
#define A_SMEM (2 * AQ_ARR + 2 * ASTG_B)  // 110592

__global__ __launch_bounds__(256, 2)
void attn_mma_kernel()
{
    extern __shared__ char smem[];
    const uint32_t sb = smem_u32(smem);
    const int tid  = threadIdx.x;
    const int wid  = tid >> 5;                 // 0..7
    const int lane = tid & 31;
    const int qb = (int)gridDim.x - 1 - (int)blockIdx.x;  // heavy blocks first
    const int bh = blockIdx.y;
    const int b  = bh >> 4;
    const int h  = bh & 15;
    const int q0 = qb * 128;

    const size_t qgbase = (size_t)(b * S_LEN + q0) * D_MODEL + h * DK;
    const size_t kgbase = (size_t)(b * S_LEN) * D_MODEL + h * DK;

    auto issue_tile = [&](int stg, int kt) {
        const uint32_t sbase = sb + STG0 + stg * ASTG_B;
        const size_t g0 = kgbase + (size_t)(kt * 64) * D_MODEL;
#pragma unroll
        for (int it = 0; it < 2; it++) {
            int slot = tid + it * 256;         // 0..511
            int r  = slot >> 3;                // 0..63
            int c8 = (slot & 7) * 8;
            uint32_t soff = (uint32_t)(r * AROW + c8) * 2;
            const size_t go = g0 + (size_t)r * D_MODEL + c8;
            CP16(sbase + soff,             (const char*)(g_Khi + go));
            CP16(sbase + A_ARR + soff,     (const char*)(g_Klo + go));
            CP16(sbase + 2 * A_ARR + soff, (const char*)(g_Vhi + go));
            CP16(sbase + 3 * A_ARR + soff, (const char*)(g_Vlo + go));
        }
    };

    issue_tile(0, 0);
    CP_COMMIT();

    // load Q tile (128 rows) hi/lo
#pragma unroll
    for (int it = 0; it < 4; it++) {
        int slot = tid + it * 256;             // 0..1023
        int r  = slot >> 3;                    // 0..127
        int c8 = (slot & 7) * 8;
        uint32_t soff = (uint32_t)(r * AROW + c8) * 2;
        const size_t go = qgbase + (size_t)r * D_MODEL + c8;
        *(uint4*)(smem + SQ_HI + soff) = *(const uint4*)(g_Qhi + go);
        *(uint4*)(smem + SQ_LO + soff) = *(const uint4*)(g_Qlo + go);
    }
    __syncthreads();

    float oacc[8][4];
#pragma unroll
    for (int nt = 0; nt < 8; nt++)
#pragma unroll
        for (int j = 0; j < 4; j++) oacc[nt][j] = 0.f;
    float m0 = -1e30f, m1 = -1e30f, l0 = 0.f, l1 = 0.f;

    const int row_lo   = q0 + wid * 16 + (lane >> 2);
    const int wrow_min = q0 + wid * 16;
    const int ntiles = 2 * qb + 2;

    const uint32_t qBase = sb + SQ_HI +
        (uint32_t)((wid * 16 + (lane & 15)) * AROW + ((lane >> 4) << 3)) * 2;

    for (int kt = 0; kt < ntiles; kt++) {
        if (kt + 1 < ntiles) { issue_tile((kt + 1) & 1, kt + 1); CP_COMMIT(); CP_WAIT1(); }
        else                 { CP_WAIT0(); }
        __syncthreads();

        const uint32_t st = sb + STG0 + (kt & 1) * ASTG_B;

        float sc[8][4];
#pragma unroll
        for (int nt = 0; nt < 8; nt++)
#pragma unroll
            for (int j = 0; j < 4; j++) sc[nt][j] = 0.f;

#pragma unroll
        for (int t = 0; t < 4; t++) {
            uint32_t qh4[4], ql4[4];
            ldsm_x4(qh4, qBase + (uint32_t)(t * 16) * 2);
            ldsm_x4(ql4, qBase + AQ_ARR + (uint32_t)(t * 16) * 2);
#pragma unroll
            for (int g = 0; g < 4; g++) {
                uint32_t addr = st +
                    (uint32_t)((g * 16 + (lane & 15)) * AROW + t * 16 + ((lane >> 4) << 3)) * 2;
                uint32_t kh4[4], kl4[4];
                ldsm_x4(kh4, addr);
                ldsm_x4(kl4, addr + A_ARR);
                mma_bf16(sc[2 * g],     qh4, kh4[0], kh4[2]);
                mma_bf16(sc[2 * g],     qh4, kl4[0], kl4[2]);
                mma_bf16(sc[2 * g],     ql4, kh4[0], kh4[2]);
                mma_bf16(sc[2 * g + 1], qh4, kh4[1], kh4[3]);
                mma_bf16(sc[2 * g + 1], qh4, kl4[1], kl4[3]);
                mma_bf16(sc[2 * g + 1], ql4, kh4[1], kh4[3]);
            }
        }

        // causal mask whenever this tile's max col can exceed this warp's min row
        if (kt * 64 + 63 > wrow_min) {
#pragma unroll
            for (int nt = 0; nt < 8; nt++) {
                int col = kt * 64 + nt * 8 + (lane & 3) * 2;
                if (col     > row_lo)     sc[nt][0] = -1e30f;
                if (col + 1 > row_lo)     sc[nt][1] = -1e30f;
                if (col     > row_lo + 8) sc[nt][2] = -1e30f;
                if (col + 1 > row_lo + 8) sc[nt][3] = -1e30f;
            }
        }

        float mx0 = -1e30f, mx1 = -1e30f;
#pragma unroll
        for (int nt = 0; nt < 8; nt++) {
            mx0 = fmaxf(mx0, fmaxf(sc[nt][0], sc[nt][1]));
            mx1 = fmaxf(mx1, fmaxf(sc[nt][2], sc[nt][3]));
        }
        mx0 = fmaxf(mx0, __shfl_xor_sync(0xffffffffu, mx0, 1));
        mx0 = fmaxf(mx0, __shfl_xor_sync(0xffffffffu, mx0, 2));
        mx1 = fmaxf(mx1, __shfl_xor_sync(0xffffffffu, mx1, 1));
        mx1 = fmaxf(mx1, __shfl_xor_sync(0xffffffffu, mx1, 2));

        float mn0 = fmaxf(m0, mx0);
        float mn1 = fmaxf(m1, mx1);
        float corr0 = __expf(m0 - mn0);
        float corr1 = __expf(m1 - mn1);
        m0 = mn0; m1 = mn1;

        float sum0 = 0.f, sum1 = 0.f;
#pragma unroll
        for (int nt = 0; nt < 8; nt++) {
            sc[nt][0] = __expf(sc[nt][0] - mn0);
            sc[nt][1] = __expf(sc[nt][1] - mn0);
            sc[nt][2] = __expf(sc[nt][2] - mn1);
            sc[nt][3] = __expf(sc[nt][3] - mn1);
            sum0 += sc[nt][0] + sc[nt][1];
            sum1 += sc[nt][2] + sc[nt][3];
        }
        sum0 += __shfl_xor_sync(0xffffffffu, sum0, 1);
        sum0 += __shfl_xor_sync(0xffffffffu, sum0, 2);
        sum1 += __shfl_xor_sync(0xffffffffu, sum1, 1);
        sum1 += __shfl_xor_sync(0xffffffffu, sum1, 2);
        l0 = l0 * corr0 + sum0;
        l1 = l1 * corr1 + sum1;

#pragma unroll
        for (int nt = 0; nt < 8; nt++) {
            oacc[nt][0] *= corr0; oacc[nt][1] *= corr0;
            oacc[nt][2] *= corr1; oacc[nt][3] *= corr1;
        }

        uint32_t ph[4][4], pl[4][4];
        float r0, r1;
#pragma unroll
        for (int t = 0; t < 4; t++) {
            ph[t][0] = pack2_hi(sc[2 * t][0], sc[2 * t][1], r0, r1);
            pl[t][0] = pack2(r0, r1);
            ph[t][1] = pack2_hi(sc[2 * t][2], sc[2 * t][3], r0, r1);
            pl[t][1] = pack2(r0, r1);
            ph[t][2] = pack2_hi(sc[2 * t + 1][0], sc[2 * t + 1][1], r0, r1);
            pl[t][2] = pack2(r0, r1);
            ph[t][3] = pack2_hi(sc[2 * t + 1][2], sc[2 * t + 1][3], r0, r1);
            pl[t][3] = pack2(r0, r1);
        }

#pragma unroll
        for (int t = 0; t < 4; t++) {
#pragma unroll
            for (int g = 0; g < 4; g++) {
                uint32_t addr = st + 2 * A_ARR +
                    (uint32_t)((t * 16 + (lane & 7) + ((lane >> 3) & 1) * 8) * AROW +
                               g * 16 + ((lane >> 4) << 3)) * 2;
                uint32_t vh4[4], vl4[4];
                ldsm_x4t(vh4, addr);
                ldsm_x4t(vl4, addr + A_ARR);
                mma_bf16(oacc[2 * g],     ph[t], vh4[0], vh4[1]);
                mma_bf16(oacc[2 * g],     ph[t], vl4[0], vl4[1]);
                mma_bf16(oacc[2 * g],     pl[t], vh4[0], vh4[1]);
                mma_bf16(oacc[2 * g + 1], ph[t], vh4[2], vh4[3]);
                mma_bf16(oacc[2 * g + 1], ph[t], vl4[2], vl4[3]);
                mma_bf16(oacc[2 * g + 1], pl[t], vh4[2], vh4[3]);
            }
        }
        __syncthreads();
    }

    // ---- epilogue: normalize + hi/lo split to global bf16 ----
    float inv0 = 1.0f / l0;
    float inv1 = 1.0f / l1;
    size_t base0 = (size_t)(b * S_LEN + row_lo) * D_MODEL + h * DK;
    size_t base1 = base0 + (size_t)8 * D_MODEL;
    float r0, r1;
#pragma unroll
    for (int nt = 0; nt < 8; nt++) {
        int col = nt * 8 + (lane & 3) * 2;
        uint32_t h0 = pack2_hi(oacc[nt][0] * inv0, oacc[nt][1] * inv0, r0, r1);
        uint32_t l0v = pack2(r0, r1);
        uint32_t h1 = pack2_hi(oacc[nt][2] * inv1, oacc[nt][3] * inv1, r0, r1);
        uint32_t l1v = pack2(r0, r1);
        *(uint32_t*)(g_attnhi + base0 + col) = h0;
        *(uint32_t*)(g_attnlo + base0 + col) = l0v;
        *(uint32_t*)(g_attnhi + base1 + col) = h1;
        *(uint32_t*)(g_attnlo + base1 + col) = l1v;
    }
}

// ---------------- launch ------------------------------------------------------
extern "C" void kernel_launch(void* const* d_in, const int* in_sizes, int n_in,
                              void* d_out, int out_size)
{
    const float* x  = (const float*)d_in[0];
    const float* Wq = (const float*)d_in[1];
    const float* bq = (const float*)d_in[2];
    const float* Wk = (const float*)d_in[3];
    const float* bk = (const float*)d_in[4];
    const float* Wv = (const float*)d_in[5];
    const float* bv = (const float*)d_in[6];
    const float* Wo = (const float*)d_in[7];
    const float* bo = (const float*)d_in[8];
    float* out = (float*)d_out;

    static int configured = 0;
    if (!configured) {
        cudaFuncSetAttribute(tc_qkv_v2, cudaFuncAttributeMaxDynamicSharedMemorySize, GSMEM_TOTAL);
        cudaFuncSetAttribute(tc_out_v2, cudaFuncAttributeMaxDynamicSharedMemorySize, GSMEM_TOTAL);
        cudaFuncSetAttribute(attn_mma_kernel, cudaFuncAttributeMaxDynamicSharedMemorySize, A_SMEM);
        configured = 1;
    }

    // 0) rope table + hi/lo split of x and weights
    rope_table_kernel<<<(S_LEN * 32 + 255) / 256, 256>>>();
    split_all<<<(2 * 1024 * 1024) / 256, 256>>>(x, Wq, Wk, Wv, Wo);

    // 1) QKV projections + fused RoPE/scale/split epilogue
    dim3 g_qkv(D_MODEL / 128, M_TOT / 128, 3);
    tc_qkv_v2<<<g_qkv, 256, GSMEM_TOTAL>>>(bq, bk, bv);

    // 2) causal attention on tensor pipe (128 q rows/block, heavy-first)
    dim3 g_att(S_LEN / 128, BATCH * NHEAD);
    attn_mma_kernel<<<g_att, 256, A_SMEM>>>();

    // 3) output projection
    dim3 g_out(D_MODEL / 128, M_TOT / 128);
    tc_out_v2<<<g_out, 256, GSMEM_TOTAL>>>(bo, out);
}

// round 7
// speedup vs baseline: 3.1196x; 1.0866x over previous
#include <cuda_runtime.h>
#include <cuda_bf16.h>
#include <cuda_fp16.h>
#include <math.h>
#include <stdint.h>

#define D_MODEL 1024
#define S_LEN   2048
#define BATCH   2
#define NHEAD   16
#define DK      64
#define M_TOT   (BATCH * S_LEN)   // 4096
#define SCALE   0.125f            // 1/sqrt(64)

// ---------------- scratch (device globals; no allocations allowed) ----------
__device__ __nv_bfloat16 g_Xhi[M_TOT * D_MODEL];
__device__ __nv_bfloat16 g_Xlo[M_TOT * D_MODEL];
__device__ __nv_bfloat16 g_Wqhi[D_MODEL * D_MODEL];
__device__ __nv_bfloat16 g_Wqlo[D_MODEL * D_MODEL];
__device__ __nv_bfloat16 g_Wkhi[D_MODEL * D_MODEL];
__device__ __nv_bfloat16 g_Wklo[D_MODEL * D_MODEL];
__device__ __nv_bfloat16 g_Wvhi[D_MODEL * D_MODEL];
__device__ __nv_bfloat16 g_Wvlo[D_MODEL * D_MODEL];
__device__ __nv_bfloat16 g_Wohi[D_MODEL * D_MODEL];
__device__ __nv_bfloat16 g_Wolo[D_MODEL * D_MODEL];
__device__ __half g_Qhi[M_TOT * D_MODEL];
__device__ __half g_Qlo[M_TOT * D_MODEL];
__device__ __half g_Kh [M_TOT * D_MODEL];
__device__ __half g_Vh [M_TOT * D_MODEL];
__device__ __nv_bfloat16 g_attnhi[M_TOT * D_MODEL];
__device__ __nv_bfloat16 g_attnlo[M_TOT * D_MODEL];
__device__ float g_cos[S_LEN * 32];
__device__ float g_sin[S_LEN * 32];

// ---------------- common helpers --------------------------------------------
__device__ __forceinline__ uint32_t smem_u32(const void* p) {
    uint32_t a;
    asm("{ .reg .u64 t; cvta.to.shared.u64 t, %1; cvt.u32.u64 %0, t; }" : "=r"(a) : "l"(p));
    return a;
}

__device__ __forceinline__ void ldsm_x4(uint32_t* r, uint32_t addr) {
    asm volatile("ldmatrix.sync.aligned.m8n8.x4.shared.b16 {%0,%1,%2,%3}, [%4];"
                 : "=r"(r[0]), "=r"(r[1]), "=r"(r[2]), "=r"(r[3]) : "r"(addr));
}

__device__ __forceinline__ void ldsm_x4t(uint32_t* r, uint32_t addr) {
    asm volatile("ldmatrix.sync.aligned.m8n8.x4.trans.shared.b16 {%0,%1,%2,%3}, [%4];"
                 : "=r"(r[0]), "=r"(r[1]), "=r"(r[2]), "=r"(r[3]) : "r"(addr));
}

__device__ __forceinline__ void mma_bf16(float* c, const uint32_t* a,
                                         uint32_t b0, uint32_t b1) {
    asm volatile("mma.sync.aligned.m16n8k16.row.col.f32.bf16.bf16.f32 "
                 "{%0,%1,%2,%3}, {%4,%5,%6,%7}, {%8,%9}, {%0,%1,%2,%3};"
                 : "+f"(c[0]), "+f"(c[1]), "+f"(c[2]), "+f"(c[3])
                 : "r"(a[0]), "r"(a[1]), "r"(a[2]), "r"(a[3]), "r"(b0), "r"(b1));
}

__device__ __forceinline__ void mma_f16(float* c, const uint32_t* a,
                                        uint32_t b0, uint32_t b1) {
    asm volatile("mma.sync.aligned.m16n8k16.row.col.f32.f16.f16.f32 "
                 "{%0,%1,%2,%3}, {%4,%5,%6,%7}, {%8,%9}, {%0,%1,%2,%3};"
                 : "+f"(c[0]), "+f"(c[1]), "+f"(c[2]), "+f"(c[3])
                 : "r"(a[0]), "r"(a[1]), "r"(a[2]), "r"(a[3]), "r"(b0), "r"(b1));
}

__device__ __forceinline__ uint32_t pack2_hi(float a, float b, float& ra, float& rb) {
    __nv_bfloat16 ha = __float2bfloat16_rn(a);
    __nv_bfloat16 hb = __float2bfloat16_rn(b);
    ra = a - __bfloat162float(ha);
    rb = b - __bfloat162float(hb);
    union { __nv_bfloat162 h; uint32_t u; } c;
    c.h = __halves2bfloat162(ha, hb);
    return c.u;
}

__device__ __forceinline__ uint32_t pack2(float a, float b) {
    union { __nv_bfloat162 h; uint32_t u; } c;
    c.h = __halves2bfloat162(__float2bfloat16_rn(a), __float2bfloat16_rn(b));
    return c.u;
}

__device__ __forceinline__ uint32_t pack2h_hi(float a, float b, float& ra, float& rb) {
    __half ha = __float2half_rn(a);
    __half hb = __float2half_rn(b);
    ra = a - __half2float(ha);
    rb = b - __half2float(hb);
    union { __half2 h; uint32_t u; } c;
    c.h = __halves2half2(ha, hb);
    return c.u;
}

__device__ __forceinline__ uint32_t pack2h(float a, float b) {
    union { __half2 h; uint32_t u; } c;
    c.h = __halves2half2(__float2half_rn(a), __float2half_rn(b));
    return c.u;
}

#define CP16(saddr, gptr) \
    asm volatile("cp.async.cg.shared.global [%0], [%1], 16;" :: "r"(saddr), "l"(gptr))
#define CP_COMMIT() asm volatile("cp.async.commit_group;" ::: "memory")
#define CP_WAIT0()  asm volatile("cp.async.wait_group 0;" ::: "memory")
#define CP_WAIT1()  asm volatile("cp.async.wait_group 1;" ::: "memory")

// ---------------- rope table + input split -----------------------------------
__global__ void rope_table_kernel()
{
    int idx = blockIdx.x * blockDim.x + threadIdx.x;
    if (idx >= S_LEN * 32) return;
    int s = idx >> 5, i = idx & 31;
    float inv_freq = __expf(-(float)(2 * i) * (9.210340371976184f / 64.0f));
    float ang = (float)s * inv_freq;
    g_cos[idx] = cosf(ang);
    g_sin[idx] = sinf(ang);
}

__global__ void split_all(const float* __restrict__ x,  const float* __restrict__ Wq,
                          const float* __restrict__ Wk, const float* __restrict__ Wv,
                          const float* __restrict__ Wo)
{
    int t = blockIdx.x * blockDim.x + threadIdx.x;   // 0..2M-1
    const float* src;
    __nv_bfloat16 *dh, *dl;
    size_t off;
    if (t < (1 << 20)) { src = x; dh = g_Xhi; dl = g_Xlo; off = t; }
    else {
        int r = t - (1 << 20);
        int w = r >> 18;
        off = (size_t)(r & ((1 << 18) - 1));
        if      (w == 0) { src = Wq; dh = g_Wqhi; dl = g_Wqlo; }
        else if (w == 1) { src = Wk; dh = g_Wkhi; dl = g_Wklo; }
        else if (w == 2) { src = Wv; dh = g_Wvhi; dl = g_Wvlo; }
        else             { src = Wo; dh = g_Wohi; dl = g_Wolo; }
    }
    float4 v = ((const float4*)src)[off];
    float r0, r1, r2, r3;
    uint2 hi, lo;
    hi.x = pack2_hi(v.x, v.y, r0, r1);
    hi.y = pack2_hi(v.z, v.w, r2, r3);
    lo.x = pack2(r0, r1);
    lo.y = pack2(r2, r3);
    ((uint2*)dh)[off] = hi;
    ((uint2*)dl)[off] = lo;
}

// =================== bf16 split GEMM v2 (cp.async, pre-split inputs) =========
#define GBK 32
#define GCHUNKS (D_MODEL / GBK)           // 32
#define ROWH   40
#define ARR_B  (128 * ROWH * 2)           // 10240
#define STG_B  (4 * ARR_B)                // 40960
#define GSMEM_TOTAL (2 * STG_B)           // 81920

__device__ __forceinline__ void gemm_v2_core(
    const __nv_bfloat16* __restrict__ Ahi, const __nv_bfloat16* __restrict__ Alo,
    const __nv_bfloat16* __restrict__ Bhi, const __nv_bfloat16* __restrict__ Blo,
    int bm, int bn, float (&acc)[4][4][4])
{
    extern __shared__ char smem[];
    const uint32_t sb = smem_u32(smem);
    const int tid  = threadIdx.x;
    const int wid  = tid >> 5;
    const int lane = tid & 31;
    const int warp_m = (wid >> 2) * 64;
    const int warp_n = (wid & 3) * 32;

#pragma unroll
    for (int i = 0; i < 4; i++)
#pragma unroll
        for (int j = 0; j < 4; j++)
#pragma unroll
            for (int k = 0; k < 4; k++) acc[i][j][k] = 0.f;

    auto issue = [&](int stg, int c) {
        const uint32_t st = sb + stg * STG_B;
        const int k0 = c * GBK;
#pragma unroll
        for (int it = 0; it < 2; it++) {
            int slot = tid + it * 256;
            int r  = slot >> 2;
            int c8 = (slot & 3) * 8;
            uint32_t soff = (uint32_t)(r * ROWH + c8) * 2;
            size_t ga = (size_t)(bm + r) * D_MODEL + k0 + c8;
            size_t gb = (size_t)(bn + r) * D_MODEL + k0 + c8;
            CP16(st + soff,             (const char*)(Ahi + ga));
            CP16(st + ARR_B + soff,     (const char*)(Alo + ga));
            CP16(st + 2 * ARR_B + soff, (const char*)(Bhi + gb));
            CP16(st + 3 * ARR_B + soff, (const char*)(Blo + gb));
        }
    };

    issue(0, 0);
    CP_COMMIT();

    const int qrow = lane & 15;
    const int qcol = (lane >> 4) << 3;

    for (int c = 0; c < GCHUNKS; c++) {
        if (c + 1 < GCHUNKS) { issue((c + 1) & 1, c + 1); CP_COMMIT(); CP_WAIT1(); }
        else                 { CP_WAIT0(); }
        __syncthreads();

        const uint32_t st = sb + (c & 1) * STG_B;
        const uint32_t aBase = st + (uint32_t)((warp_m + qrow) * ROWH + qcol) * 2;
        const uint32_t bBase = st + 2 * ARR_B + (uint32_t)((warp_n + qrow) * ROWH + qcol) * 2;

#pragma unroll
        for (int ks = 0; ks < 2; ks++) {
            const uint32_t ko = (uint32_t)(ks * 16) * 2;
            uint32_t bh[2][4], bl[2][4];
#pragma unroll
            for (int nt = 0; nt < 2; nt++) {
                ldsm_x4(bh[nt], bBase + nt * (16 * ROWH * 2) + ko);
                ldsm_x4(bl[nt], bBase + ARR_B + nt * (16 * ROWH * 2) + ko);
            }
#pragma unroll
            for (int mi = 0; mi < 4; mi++) {
                uint32_t ah[4], al[4];
                ldsm_x4(ah, aBase + mi * (16 * ROWH * 2) + ko);
                ldsm_x4(al, aBase + ARR_B + mi * (16 * ROWH * 2) + ko);
#pragma unroll
                for (int nt = 0; nt < 2; nt++)
#pragma unroll
                    for (int nj = 0; nj < 2; nj++) {
                        float* cc = acc[mi][nt * 2 + nj];
                        mma_bf16(cc, ah, bh[nt][nj], bh[nt][nj + 2]);
                        mma_bf16(cc, ah, bl[nt][nj], bl[nt][nj + 2]);
                        mma_bf16(cc, al, bh[nt][nj], bh[nt][nj + 2]);
                    }
            }
        }
        __syncthreads();
    }
}

// QKV GEMM: fused bias + RoPE; Q -> fp16 hi/lo, K/V -> plain fp16
__global__ __launch_bounds__(256, 2)
void tc_qkv_v2(const float* __restrict__ bq, const float* __restrict__ bk,
               const float* __restrict__ bv)
{
    const int z = blockIdx.z;
    const __nv_bfloat16 *Bh, *Bl;
    const float* bias;
    if (z == 0)      { Bh = g_Wqhi; Bl = g_Wqlo; bias = bq; }
    else if (z == 1) { Bh = g_Wkhi; Bl = g_Wklo; bias = bk; }
    else             { Bh = g_Wvhi; Bl = g_Wvlo; bias = bv; }

    const int bm = blockIdx.y * 128;
    const int bn = blockIdx.x * 128;
    float acc[4][4][4];
    gemm_v2_core(g_Xhi, g_Xlo, Bh, Bl, bm, bn, acc);

    const int wid  = threadIdx.x >> 5;
    const int lane = threadIdx.x & 31;
    const int warp_m = (wid >> 2) * 64;
    const int warp_n = (wid & 3) * 32;
    const int erow = lane >> 2;
    const int ecol = (lane & 3) * 2;

#pragma unroll
    for (int mi = 0; mi < 4; mi++)
#pragma unroll
        for (int nt = 0; nt < 2; nt++)
#pragma unroll
            for (int nj = 0; nj < 2; nj++) {
                float* cc = acc[mi][nt * 2 + nj];
                int m = bm + warp_m + mi * 16 + erow;
                int n = bn + warp_n + nt * 16 + nj * 8 + ecol;
                float v0 = cc[0] + bias[n], v1 = cc[1] + bias[n + 1];
                float w0 = cc[2] + bias[n], w1 = cc[3] + bias[n + 1];
                if (z < 2) {
                    int i  = (n & 63) >> 1;
                    int s0 = (m & 2047) * 32 + i;
                    int s1 = ((m + 8) & 2047) * 32 + i;
                    float cs0 = g_cos[s0], sn0 = g_sin[s0];
                    float cs1 = g_cos[s1], sn1 = g_sin[s1];
                    float t0 = v0 * cs0 - v1 * sn0, t1 = v0 * sn0 + v1 * cs0;
                    float u0 = w0 * cs1 - w1 * sn1, u1 = w0 * sn1 + w1 * cs1;
                    if (z == 0) { t0 *= SCALE; t1 *= SCALE; u0 *= SCALE; u1 *= SCALE; }
                    v0 = t0; v1 = t1; w0 = u0; w1 = u1;
                }
                size_t o0 = (size_t)m * D_MODEL + n;
                size_t o1 = (size_t)(m + 8) * D_MODEL + n;
                if (z == 0) {
                    float r0, r1;
                    uint32_t h0 = pack2h_hi(v0, v1, r0, r1);
                    uint32_t l0v = pack2h(r0, r1);
                    uint32_t h1 = pack2h_hi(w0, w1, r0, r1);
                    uint32_t l1v = pack2h(r0, r1);
                    *(uint32_t*)(g_Qhi + o0) = h0;
                    *(uint32_t*)(g_Qlo + o0) = l0v;
                    *(uint32_t*)(g_Qhi + o1) = h1;
                    *(uint32_t*)(g_Qlo + o1) = l1v;
                } else {
                    __half* D = (z == 1) ? g_Kh : g_Vh;
                    *(uint32_t*)(D + o0) = pack2h(v0, v1);
                    *(uint32_t*)(D + o1) = pack2h(w0, w1);
                }
            }
}

__global__ __launch_bounds__(256, 2)
void tc_out_v2(const float* __restrict__ bo, float* __restrict__ out)
{
    const int bm = blockIdx.y * 128;
    const int bn = blockIdx.x * 128;
    float acc[4][4][4];
    gemm_v2_core(g_attnhi, g_attnlo, g_Wohi, g_Wolo, bm, bn, acc);

    const int wid  = threadIdx.x >> 5;
    const int lane = threadIdx.x & 31;
    const int warp_m = (wid >> 2) * 64;
    const int warp_n = (wid & 3) * 32;
    const int erow = lane >> 2;
    const int ecol = (lane & 3) * 2;

#pragma unroll
    for (int mi = 0; mi < 4; mi++)
#pragma unroll
        for (int nt = 0; nt < 2; nt++)
#pragma unroll
            for (int nj = 0; nj < 2; nj++) {
                float* cc = acc[mi][nt * 2 + nj];
                int m = bm + warp_m + mi * 16 + erow;
                int n = bn + warp_n + nt * 16 + nj * 8 + ecol;
                float2 v0 = make_float2(cc[0] + bo[n], cc[1] + bo[n + 1]);
                float2 v1 = make_float2(cc[2] + bo[n], cc[3] + bo[n + 1]);
                *(float2*)(out + (size_t)m * D_MODEL + n)       = v0;
                *(float2*)(out + (size_t)(m + 8) * D_MODEL + n) = v1;
            }
}

// ---------------- tensor-core causal flash attention v4 (fp16, 2+2 products) -
// 256 threads (8 warps), 128 q rows/block, 64-key tiles, K/V unsplit fp16.
#define AROW   72
#define A_ARR  (64 * AROW * 2)            // 9216  (one K or V array)
#define AQ_ARR (128 * AROW * 2)           // 18432 (one Q array)
#define SQ_HI  0
#define SQ_LO  AQ_ARR
#define STG0   (2 * AQ_ARR)               // 36864
#define ASTG_B (2 * A_ARR)                // 18432 (Kh, Vh)
#define A_SMEM (2 * AQ_ARR + 2 * ASTG_B)  // 73728

__global__ __launch_bounds__(256, 2)
void attn_mma_kernel()
{
    extern __shared__ char smem[];
    const uint32_t sb = smem_u32(smem);
    const int tid  = threadIdx.x;
    const int wid  = tid >> 5;                 // 0..7
    const int lane = tid & 31;
    const int qb = (int)gridDim.x - 1 - (int)blockIdx.x;  // heavy blocks first
    const int bh = blockIdx.y;
    const int b  = bh >> 4;
    const int h  = bh & 15;
    const int q0 = qb * 128;

    const size_t qgbase = (size_t)(b * S_LEN + q0) * D_MODEL + h * DK;
    const size_t kgbase = (size_t)(b * S_LEN) * D_MODEL + h * DK;

    auto issue_tile = [&](int stg, int kt) {
        const uint32_t sbase = sb + STG0 + stg * ASTG_B;
        const size_t g0 = kgbase + (size_t)(kt * 64) * D_MODEL;
#pragma unroll
        for (int it = 0; it < 2; it++) {
            int slot = tid + it * 256;         // 0..511
            int r  = slot >> 3;                // 0..63
            int c8 = (slot & 7) * 8;
            uint32_t soff = (uint32_t)(r * AROW + c8) * 2;
            const size_t go = g0 + (size_t)r * D_MODEL + c8;
            CP16(sbase + soff,         (const char*)(g_Kh + go));
            CP16(sbase + A_ARR + soff, (const char*)(g_Vh + go));
        }
    };

    issue_tile(0, 0);
    CP_COMMIT();

    // load Q tile (128 rows) hi/lo
#pragma unroll
    for (int it = 0; it < 4; it++) {
        int slot = tid + it * 256;             // 0..1023
        int r  = slot >> 3;                    // 0..127
        int c8 = (slot & 7) * 8;
        uint32_t soff = (uint32_t)(r * AROW + c8) * 2;
        const size_t go = qgbase + (size_t)r * D_MODEL + c8;
        *(uint4*)(smem + SQ_HI + soff) = *(const uint4*)(g_Qhi + go);
        *(uint4*)(smem + SQ_LO + soff) = *(const uint4*)(g_Qlo + go);
    }
    __syncthreads();

    float oacc[8][4];
#pragma unroll
    for (int nt = 0; nt < 8; nt++)
#pragma unroll
        for (int j = 0; j < 4; j++) oacc[nt][j] = 0.f;
    float m0 = -1e30f, m1 = -1e30f, l0 = 0.f, l1 = 0.f;

    const int row_lo   = q0 + wid * 16 + (lane >> 2);
    const int wrow_min = q0 + wid * 16;
    const int ntiles = 2 * qb + 2;

    const uint32_t qBase = sb + SQ_HI +
        (uint32_t)((wid * 16 + (lane & 15)) * AROW + ((lane >> 4) << 3)) * 2;

    for (int kt = 0; kt < ntiles; kt++) {
        if (kt + 1 < ntiles) { issue_tile((kt + 1) & 1, kt + 1); CP_COMMIT(); CP_WAIT1(); }
        else                 { CP_WAIT0(); }
        __syncthreads();

        const uint32_t st = sb + STG0 + (kt & 1) * ASTG_B;

        float sc[8][4];
#pragma unroll
        for (int nt = 0; nt < 8; nt++)
#pragma unroll
            for (int j = 0; j < 4; j++) sc[nt][j] = 0.f;

        // S = (Qhi + Qlo) @ Kh^T : 2 fp16 products
#pragma unroll
        for (int t = 0; t < 4; t++) {
            uint32_t qh4[4], ql4[4];
            ldsm_x4(qh4, qBase + (uint32_t)(t * 16) * 2);
            ldsm_x4(ql4, qBase + AQ_ARR + (uint32_t)(t * 16) * 2);
#pragma unroll
            for (int g = 0; g < 4; g++) {
                uint32_t addr = st +
                    (uint32_t)((g * 16 + (lane & 15)) * AROW + t * 16 + ((lane >> 4) << 3)) * 2;
                uint32_t kh4[4];
                ldsm_x4(kh4, addr);
                mma_f16(sc[2 * g],     qh4, kh4[0], kh4[2]);
                mma_f16(sc[2 * g],     ql4, kh4[0], kh4[2]);
                mma_f16(sc[2 * g + 1], qh4, kh4[1], kh4[3]);
                mma_f16(sc[2 * g + 1], ql4, kh4[1], kh4[3]);
            }
        }

        if (kt * 64 + 63 > wrow_min) {
#pragma unroll
            for (int nt = 0; nt < 8; nt++) {
                int col = kt * 64 + nt * 8 + (lane & 3) * 2;
                if (col     > row_lo)     sc[nt][0] = -1e30f;
                if (col + 1 > row_lo)     sc[nt][1] = -1e30f;
                if (col     > row_lo + 8) sc[nt][2] = -1e30f;
                if (col + 1 > row_lo + 8) sc[nt][3] = -1e30f;
            }
        }

        float mx0 = -1e30f, mx1 = -1e30f;
#pragma unroll
        for (int nt = 0; nt < 8; nt++) {
            mx0 = fmaxf(mx0, fmaxf(sc[nt][0], sc[nt][1]));
            mx1 = fmaxf(mx1, fmaxf(sc[nt][2], sc[nt][3]));
        }
        mx0 = fmaxf(mx0, __shfl_xor_sync(0xffffffffu, mx0, 1));
        mx0 = fmaxf(mx0, __shfl_xor_sync(0xffffffffu, mx0, 2));
        mx1 = fmaxf(mx1, __shfl_xor_sync(0xffffffffu, mx1, 1));
        mx1 = fmaxf(mx1, __shfl_xor_sync(0xffffffffu, mx1, 2));

        float mn0 = fmaxf(m0, mx0);
        float mn1 = fmaxf(m1, mx1);
        float corr0 = __expf(m0 - mn0);
        float corr1 = __expf(m1 - mn1);
        m0 = mn0; m1 = mn1;

        float sum0 = 0.f, sum1 = 0.f;
#pragma unroll
        for (int nt = 0; nt < 8; nt++) {
            sc[nt][0] = __expf(sc[nt][0] - mn0);
            sc[nt][1] = __expf(sc[nt][1] - mn0);
            sc[nt][2] = __expf(sc[nt][2] - mn1);
            sc[nt][3] = __expf(sc[nt][3] - mn1);
            sum0 += sc[nt][0] + sc[nt][1];
            sum1 += sc[nt][2] + sc[nt][3];
        }
        sum0 += __shfl_xor_sync(0xffffffffu, sum0, 1);
        sum0 += __shfl_xor_sync(0xffffffffu, sum0, 2);
        sum1 += __shfl_xor_sync(0xffffffffu, sum1, 1);
        sum1 += __shfl_xor_sync(0xffffffffu, sum1, 2);
        l0 = l0 * corr0 + sum0;
        l1 = l1 * corr1 + sum1;

#pragma unroll
        for (int nt = 0; nt < 8; nt++) {
            oacc[nt][0] *= corr0; oacc[nt][1] *= corr0;
            oacc[nt][2] *= corr1; oacc[nt][3] *= corr1;
        }

        // pack P to fp16 hi/lo (accumulator layout == A-fragment layout)
        uint32_t ph[4][4], pl[4][4];
        float r0, r1;
#pragma unroll
        for (int t = 0; t < 4; t++) {
            ph[t][0] = pack2h_hi(sc[2 * t][0], sc[2 * t][1], r0, r1);
            pl[t][0] = pack2h(r0, r1);
            ph[t][1] = pack2h_hi(sc[2 * t][2], sc[2 * t][3], r0, r1);
            pl[t][1] = pack2h(r0, r1);
            ph[t][2] = pack2h_hi(sc[2 * t + 1][0], sc[2 * t + 1][1], r0, r1);
            pl[t][2] = pack2h(r0, r1);
            ph[t][3] = pack2h_hi(sc[2 * t + 1][2], sc[2 * t + 1][3], r0, r1);
            pl[t][3] = pack2h(r0, r1);
        }

        // O += (Phi + Plo) @ Vh : 2 fp16 products
#pragma unroll
        for (int t = 0; t < 4; t++) {
#pragma unroll
            for (int g = 0; g < 4; g++) {
                uint32_t addr = st + A_ARR +
                    (uint32_t)((t * 16 + (lane & 7) + ((lane >> 3) & 1) * 8) * AROW +
                               g * 16 + ((lane >> 4) << 3)) * 2;
                uint32_t vh4[4];
                ldsm_x4t(vh4, addr);
                mma_f16(oacc[2 * g],     ph[t], vh4[0], vh4[1]);
                mma_f16(oacc[2 * g],     pl[t], vh4[0], vh4[1]);
                mma_f16(oacc[2 * g + 1], ph[t], vh4[2], vh4[3]);
                mma_f16(oacc[2 * g + 1], pl[t], vh4[2], vh4[3]);
            }
        }
        __syncthreads();
    }

    // ---- epilogue: normalize + bf16 hi/lo split to global (for out-proj) ----
    float inv0 = 1.0f / l0;
    float inv1 = 1.0f / l1;
    size_t base0 = (size_t)(b * S_LEN + row_lo) * D_MODEL + h * DK;
    size_t base1 = base0 + (size_t)8 * D_MODEL;
    float r0, r1;
#pragma unroll
    for (int nt = 0; nt < 8; nt++) {
        int col = nt * 8 + (lane & 3) * 2;
        uint32_t h0 = pack2_hi(oacc[nt][0] * inv0, oacc[nt][1] * inv0, r0, r1);
        uint32_t l0v = pack2(r0, r1);
        uint32_t h1 = pack2_hi(oacc[nt][2] * inv1, oacc[nt][3] * inv1, r0, r1);
        uint32_t l1v = pack2(r0, r1);
        *(uint32_t*)(g_attnhi + base0 + col) = h0;
        *(uint32_t*)(g_attnlo + base0 + col) = l0v;
        *(uint32_t*)(g_attnhi + base1 + col) = h1;
        *(uint32_t*)(g_attnlo + base1 + col) = l1v;
    }
}

// ---------------- launch ------------------------------------------------------
extern "C" void kernel_launch(void* const* d_in, const int* in_sizes, int n_in,
                              void* d_out, int out_size)
{
    const float* x  = (const float*)d_in[0];
    const float* Wq = (const float*)d_in[1];
    const float* bq = (const float*)d_in[2];
    const float* Wk = (const float*)d_in[3];
    const float* bk = (const float*)d_in[4];
    const float* Wv = (const float*)d_in[5];
    const float* bv = (const float*)d_in[6];
    const float* Wo = (const float*)d_in[7];
    const float* bo = (const float*)d_in[8];
    float* out = (float*)d_out;

    static int configured = 0;
    if (!configured) {
        cudaFuncSetAttribute(tc_qkv_v2, cudaFuncAttributeMaxDynamicSharedMemorySize, GSMEM_TOTAL);
        cudaFuncSetAttribute(tc_out_v2, cudaFuncAttributeMaxDynamicSharedMemorySize, GSMEM_TOTAL);
        cudaFuncSetAttribute(attn_mma_kernel, cudaFuncAttributeMaxDynamicSharedMemorySize, A_SMEM);
        configured = 1;
    }

    // 0) rope table + hi/lo split of x and weights
    rope_table_kernel<<<(S_LEN * 32 + 255) / 256, 256>>>();
    split_all<<<(2 * 1024 * 1024) / 256, 256>>>(x, Wq, Wk, Wv, Wo);

    // 1) QKV projections + fused RoPE/scale epilogue (Q->fp16 hi/lo, K/V->fp16)
    dim3 g_qkv(D_MODEL / 128, M_TOT / 128, 3);
    tc_qkv_v2<<<g_qkv, 256, GSMEM_TOTAL>>>(bq, bk, bv);

    // 2) causal attention (fp16 left-split, 2+2 products)
    dim3 g_att(S_LEN / 128, BATCH * NHEAD);
    attn_mma_kernel<<<g_att, 256, A_SMEM>>>();

    // 3) output projection
    dim3 g_out(D_MODEL / 128, M_TOT / 128);
    tc_out_v2<<<g_out, 256, GSMEM_TOTAL>>>(bo, out);
}

// round 8
// speedup vs baseline: 4.0181x; 1.2880x over previous
#include <cuda_runtime.h>
#include <cuda_bf16.h>
#include <cuda_fp16.h>
#include <math.h>
#include <stdint.h>

#define D_MODEL 1024
#define S_LEN   2048
#define BATCH   2
#define NHEAD   16
#define DK      64
#define M_TOT   (BATCH * S_LEN)   // 4096
#define SCALE   0.125f            // 1/sqrt(64)

// ---------------- scratch (device globals; no allocations allowed) ----------
__device__ __half g_Xhi[M_TOT * D_MODEL];
__device__ __half g_Xlo[M_TOT * D_MODEL];
__device__ __half g_Wq[D_MODEL * D_MODEL];
__device__ __half g_Wk[D_MODEL * D_MODEL];
__device__ __half g_Wv[D_MODEL * D_MODEL];
__device__ __half g_Wo[D_MODEL * D_MODEL];
__device__ __half g_Qhi[M_TOT * D_MODEL];
__device__ __half g_Qlo[M_TOT * D_MODEL];
__device__ __half g_Kh [M_TOT * D_MODEL];
__device__ __half g_Vh [M_TOT * D_MODEL];
__device__ __half g_attnhi[M_TOT * D_MODEL];
__device__ __half g_attnlo[M_TOT * D_MODEL];
__device__ float g_cos[S_LEN * 32];
__device__ float g_sin[S_LEN * 32];

// ---------------- common helpers --------------------------------------------
__device__ __forceinline__ uint32_t smem_u32(const void* p) {
    uint32_t a;
    asm("{ .reg .u64 t; cvta.to.shared.u64 t, %1; cvt.u32.u64 %0, t; }" : "=r"(a) : "l"(p));
    return a;
}

__device__ __forceinline__ void ldsm_x4(uint32_t* r, uint32_t addr) {
    asm volatile("ldmatrix.sync.aligned.m8n8.x4.shared.b16 {%0,%1,%2,%3}, [%4];"
                 : "=r"(r[0]), "=r"(r[1]), "=r"(r[2]), "=r"(r[3]) : "r"(addr));
}

__device__ __forceinline__ void ldsm_x4t(uint32_t* r, uint32_t addr) {
    asm volatile("ldmatrix.sync.aligned.m8n8.x4.trans.shared.b16 {%0,%1,%2,%3}, [%4];"
                 : "=r"(r[0]), "=r"(r[1]), "=r"(r[2]), "=r"(r[3]) : "r"(addr));
}

__device__ __forceinline__ void mma_f16(float* c, const uint32_t* a,
                                        uint32_t b0, uint32_t b1) {
    asm volatile("mma.sync.aligned.m16n8k16.row.col.f32.f16.f16.f32 "
                 "{%0,%1,%2,%3}, {%4,%5,%6,%7}, {%8,%9}, {%0,%1,%2,%3};"
                 : "+f"(c[0]), "+f"(c[1]), "+f"(c[2]), "+f"(c[3])
                 : "r"(a[0]), "r"(a[1]), "r"(a[2]), "r"(a[3]), "r"(b0), "r"(b1));
}

__device__ __forceinline__ uint32_t pack2h_hi(float a, float b, float& ra, float& rb) {
    __half ha = __float2half_rn(a);
    __half hb = __float2half_rn(b);
    ra = a - __half2float(ha);
    rb = b - __half2float(hb);
    union { __half2 h; uint32_t u; } c;
    c.h = __halves2half2(ha, hb);
    return c.u;
}

__device__ __forceinline__ uint32_t pack2h(float a, float b) {
    union { __half2 h; uint32_t u; } c;
    c.h = __halves2half2(__float2half_rn(a), __float2half_rn(b));
    return c.u;
}

#define CP16(saddr, gptr) \
    asm volatile("cp.async.cg.shared.global [%0], [%1], 16;" :: "r"(saddr), "l"(gptr))
#define CP_COMMIT() asm volatile("cp.async.commit_group;" ::: "memory")
#define CP_WAIT0()  asm volatile("cp.async.wait_group 0;" ::: "memory")
#define CP_WAIT1()  asm volatile("cp.async.wait_group 1;" ::: "memory")

// ---------------- rope table + input split -----------------------------------
__global__ void rope_table_kernel()
{
    int idx = blockIdx.x * blockDim.x + threadIdx.x;
    if (idx >= S_LEN * 32) return;
    int s = idx >> 5, i = idx & 31;
    float inv_freq = __expf(-(float)(2 * i) * (9.210340371976184f / 64.0f));
    float ang = (float)s * inv_freq;
    g_cos[idx] = cosf(ang);
    g_sin[idx] = sinf(ang);
}

// x -> fp16 hi/lo; weights -> plain fp16
__global__ void split_all(const float* __restrict__ x,  const float* __restrict__ Wq,
                          const float* __restrict__ Wk, const float* __restrict__ Wv,
                          const float* __restrict__ Wo)
{
    int t = blockIdx.x * blockDim.x + threadIdx.x;   // 0..2M-1
    if (t < (1 << 20)) {
        float4 v = ((const float4*)x)[t];
        float r0, r1, r2, r3;
        uint2 hi, lo;
        hi.x = pack2h_hi(v.x, v.y, r0, r1);
        hi.y = pack2h_hi(v.z, v.w, r2, r3);
        lo.x = pack2h(r0, r1);
        lo.y = pack2h(r2, r3);
        ((uint2*)g_Xhi)[t] = hi;
        ((uint2*)g_Xlo)[t] = lo;
    } else {
        int r = t - (1 << 20);
        int w = r >> 18;
        size_t off = (size_t)(r & ((1 << 18) - 1));
        const float* src;
        __half* dst;
        if      (w == 0) { src = Wq; dst = g_Wq; }
        else if (w == 1) { src = Wk; dst = g_Wk; }
        else if (w == 2) { src = Wv; dst = g_Wv; }
        else             { src = Wo; dst = g_Wo; }
        float4 v = ((const float4*)src)[off];
        uint2 o;
        o.x = pack2h(v.x, v.y);
        o.y = pack2h(v.z, v.w);
        ((uint2*)dst)[off] = o;
    }
}

// =================== fp16 left-split GEMM (2 products) =======================
#define GBK 32
#define GCHUNKS (D_MODEL / GBK)           // 32
#define ROWH   40
#define GARR_B (128 * ROWH * 2)           // 10240
#define GSTG_B (3 * GARR_B)               // 30720 (Ahi, Alo, B)
#define GSMEM_TOTAL (2 * GSTG_B)          // 61440

__device__ __forceinline__ void gemm_v3_core(
    const __half* __restrict__ Ahi, const __half* __restrict__ Alo,
    const __half* __restrict__ B,
    int bm, int bn, float (&acc)[4][4][4])
{
    extern __shared__ char smem[];
    const uint32_t sb = smem_u32(smem);
    const int tid  = threadIdx.x;
    const int wid  = tid >> 5;
    const int lane = tid & 31;
    const int warp_m = (wid >> 2) * 64;
    const int warp_n = (wid & 3) * 32;

#pragma unroll
    for (int i = 0; i < 4; i++)
#pragma unroll
        for (int j = 0; j < 4; j++)
#pragma unroll
            for (int k = 0; k < 4; k++) acc[i][j][k] = 0.f;

    auto issue = [&](int stg, int c) {
        const uint32_t st = sb + stg * GSTG_B;
        const int k0 = c * GBK;
#pragma unroll
        for (int it = 0; it < 2; it++) {
            int slot = tid + it * 256;
            int r  = slot >> 2;
            int c8 = (slot & 3) * 8;
            uint32_t soff = (uint32_t)(r * ROWH + c8) * 2;
            size_t ga = (size_t)(bm + r) * D_MODEL + k0 + c8;
            size_t gb = (size_t)(bn + r) * D_MODEL + k0 + c8;
            CP16(st + soff,              (const char*)(Ahi + ga));
            CP16(st + GARR_B + soff,     (const char*)(Alo + ga));
            CP16(st + 2 * GARR_B + soff, (const char*)(B + gb));
        }
    };

    issue(0, 0);
    CP_COMMIT();

    const int qrow = lane & 15;
    const int qcol = (lane >> 4) << 3;

    for (int c = 0; c < GCHUNKS; c++) {
        if (c + 1 < GCHUNKS) { issue((c + 1) & 1, c + 1); CP_COMMIT(); CP_WAIT1(); }
        else                 { CP_WAIT0(); }
        __syncthreads();

        const uint32_t st = sb + (c & 1) * GSTG_B;
        const uint32_t aBase = st + (uint32_t)((warp_m + qrow) * ROWH + qcol) * 2;
        const uint32_t bBase = st + 2 * GARR_B + (uint32_t)((warp_n + qrow) * ROWH + qcol) * 2;

#pragma unroll
        for (int ks = 0; ks < 2; ks++) {
            const uint32_t ko = (uint32_t)(ks * 16) * 2;
            uint32_t bf[2][4];
#pragma unroll
            for (int nt = 0; nt < 2; nt++)
                ldsm_x4(bf[nt], bBase + nt * (16 * ROWH * 2) + ko);
#pragma unroll
            for (int mi = 0; mi < 4; mi++) {
                uint32_t ah[4], al[4];
                ldsm_x4(ah, aBase + mi * (16 * ROWH * 2) + ko);
                ldsm_x4(al, aBase + GARR_B + mi * (16 * ROWH * 2) + ko);
#pragma unroll
                for (int nt = 0; nt < 2; nt++)
#pragma unroll
                    for (int nj = 0; nj < 2; nj++) {
                        float* cc = acc[mi][nt * 2 + nj];
                        mma_f16(cc, ah, bf[nt][nj], bf[nt][nj + 2]);
                        mma_f16(cc, al, bf[nt][nj], bf[nt][nj + 2]);
                    }
            }
        }
        __syncthreads();
    }
}

// QKV GEMM: fused bias + RoPE; Q -> fp16 hi/lo, K/V -> plain fp16
__global__ __launch_bounds__(256, 2)
void tc_qkv_v3(const float* __restrict__ bq, const float* __restrict__ bk,
               const float* __restrict__ bv)
{
    const int z = blockIdx.z;
    const __half* W;
    const float* bias;
    if (z == 0)      { W = g_Wq; bias = bq; }
    else if (z == 1) { W = g_Wk; bias = bk; }
    else             { W = g_Wv; bias = bv; }

    const int bm = blockIdx.y * 128;
    const int bn = blockIdx.x * 128;
    float acc[4][4][4];
    gemm_v3_core(g_Xhi, g_Xlo, W, bm, bn, acc);

    const int wid  = threadIdx.x >> 5;
    const int lane = threadIdx.x & 31;
    const int warp_m = (wid >> 2) * 64;
    const int warp_n = (wid & 3) * 32;
    const int erow = lane >> 2;
    const int ecol = (lane & 3) * 2;

#pragma unroll
    for (int mi = 0; mi < 4; mi++)
#pragma unroll
        for (int nt = 0; nt < 2; nt++)
#pragma unroll
            for (int nj = 0; nj < 2; nj++) {
                float* cc = acc[mi][nt * 2 + nj];
                int m = bm + warp_m + mi * 16 + erow;
                int n = bn + warp_n + nt * 16 + nj * 8 + ecol;
                float v0 = cc[0] + bias[n], v1 = cc[1] + bias[n + 1];
                float w0 = cc[2] + bias[n], w1 = cc[3] + bias[n + 1];
                if (z < 2) {
                    int i  = (n & 63) >> 1;
                    int s0 = (m & 2047) * 32 + i;
                    int s1 = ((m + 8) & 2047) * 32 + i;
                    float cs0 = g_cos[s0], sn0 = g_sin[s0];
                    float cs1 = g_cos[s1], sn1 = g_sin[s1];
                    float t0 = v0 * cs0 - v1 * sn0, t1 = v0 * sn0 + v1 * cs0;
                    float u0 = w0 * cs1 - w1 * sn1, u1 = w0 * sn1 + w1 * cs1;
                    if (z == 0) { t0 *= SCALE; t1 *= SCALE; u0 *= SCALE; u1 *= SCALE; }
                    v0 = t0; v1 = t1; w0 = u0; w1 = u1;
                }
                size_t o0 = (size_t)m * D_MODEL + n;
                size_t o1 = (size_t)(m + 8) * D_MODEL + n;
                if (z == 0) {
                    float r0, r1;
                    uint32_t h0 = pack2h_hi(v0, v1, r0, r1);
                    uint32_t l0v = pack2h(r0, r1);
                    uint32_t h1 = pack2h_hi(w0, w1, r0, r1);
                    uint32_t l1v = pack2h(r0, r1);
                    *(uint32_t*)(g_Qhi + o0) = h0;
                    *(uint32_t*)(g_Qlo + o0) = l0v;
                    *(uint32_t*)(g_Qhi + o1) = h1;
                    *(uint32_t*)(g_Qlo + o1) = l1v;
                } else {
                    __half* D = (z == 1) ? g_Kh : g_Vh;
                    *(uint32_t*)(D + o0) = pack2h(v0, v1);
                    *(uint32_t*)(D + o1) = pack2h(w0, w1);
                }
            }
}

__global__ __launch_bounds__(256, 2)
void tc_out_v3(const float* __restrict__ bo, float* __restrict__ out)
{
    const int bm = blockIdx.y * 128;
    const int bn = blockIdx.x * 128;
    float acc[4][4][4];
    gemm_v3_core(g_attnhi, g_attnlo, g_Wo, bm, bn, acc);

    const int wid  = threadIdx.x >> 5;
    const int lane = threadIdx.x & 31;
    const int warp_m = (wid >> 2) * 64;
    const int warp_n = (wid & 3) * 32;
    const int erow = lane >> 2;
    const int ecol = (lane & 3) * 2;

#pragma unroll
    for (int mi = 0; mi < 4; mi++)
#pragma unroll
        for (int nt = 0; nt < 2; nt++)
#pragma unroll
            for (int nj = 0; nj < 2; nj++) {
                float* cc = acc[mi][nt * 2 + nj];
                int m = bm + warp_m + mi * 16 + erow;
                int n = bn + warp_n + nt * 16 + nj * 8 + ecol;
                float2 v0 = make_float2(cc[0] + bo[n], cc[1] + bo[n + 1]);
                float2 v1 = make_float2(cc[2] + bo[n], cc[3] + bo[n + 1]);
                *(float2*)(out + (size_t)m * D_MODEL + n)       = v0;
                *(float2*)(out + (size_t)(m + 8) * D_MODEL + n) = v1;
            }
}

// ---------------- tensor-core causal flash attention v4 (unchanged R7) ------
#define AROW   72
#define A_ARR  (64 * AROW * 2)            // 9216
#define AQ_ARR (128 * AROW * 2)           // 18432
#define SQ_HI  0
#define SQ_LO  AQ_ARR
#define STG0   (2 * AQ_ARR)               // 36864
#define ASTG_B (2 * A_ARR)                // 18432 (Kh, Vh)
#define A_SMEM (2 * AQ_ARR + 2 * ASTG_B)  // 73728

__global__ __launch_bounds__(256, 2)
void attn_mma_kernel()
{
    extern __shared__ char smem[];
    const uint32_t sb = smem_u32(smem);
    const int tid  = threadIdx.x;
    const int wid  = tid >> 5;
    const int lane = tid & 31;
    const int qb = (int)gridDim.x - 1 - (int)blockIdx.x;
    const int bh = blockIdx.y;
    const int b  = bh >> 4;
    const int h  = bh & 15;
    const int q0 = qb * 128;

    const size_t qgbase = (size_t)(b * S_LEN + q0) * D_MODEL + h * DK;
    const size_t kgbase = (size_t)(b * S_LEN) * D_MODEL + h * DK;

    auto issue_tile = [&](int stg, int kt) {
        const uint32_t sbase = sb + STG0 + stg * ASTG_B;
        const size_t g0 = kgbase + (size_t)(kt * 64) * D_MODEL;
#pragma unroll
        for (int it = 0; it < 2; it++) {
            int slot = tid + it * 256;
            int r  = slot >> 3;
            int c8 = (slot & 7) * 8;
            uint32_t soff = (uint32_t)(r * AROW + c8) * 2;
            const size_t go = g0 + (size_t)r * D_MODEL + c8;
            CP16(sbase + soff,         (const char*)(g_Kh + go));
            CP16(sbase + A_ARR + soff, (const char*)(g_Vh + go));
        }
    };

    issue_tile(0, 0);
    CP_COMMIT();

#pragma unroll
    for (int it = 0; it < 4; it++) {
        int slot = tid + it * 256;
        int r  = slot >> 3;
        int c8 = (slot & 7) * 8;
        uint32_t soff = (uint32_t)(r * AROW + c8) * 2;
        const size_t go = qgbase + (size_t)r * D_MODEL + c8;
        *(uint4*)(smem + SQ_HI + soff) = *(const uint4*)(g_Qhi + go);
        *(uint4*)(smem + SQ_LO + soff) = *(const uint4*)(g_Qlo + go);
    }
    __syncthreads();

    float oacc[8][4];
#pragma unroll
    for (int nt = 0; nt < 8; nt++)
#pragma unroll
        for (int j = 0; j < 4; j++) oacc[nt][j] = 0.f;
    float m0 = -1e30f, m1 = -1e30f, l0 = 0.f, l1 = 0.f;

    const int row_lo   = q0 + wid * 16 + (lane >> 2);
    const int wrow_min = q0 + wid * 16;
    const int ntiles = 2 * qb + 2;

    const uint32_t qBase = sb + SQ_HI +
        (uint32_t)((wid * 16 + (lane & 15)) * AROW + ((lane >> 4) << 3)) * 2;

    for (int kt = 0; kt < ntiles; kt++) {
        if (kt + 1 < ntiles) { issue_tile((kt + 1) & 1, kt + 1); CP_COMMIT(); CP_WAIT1(); }
        else                 { CP_WAIT0(); }
        __syncthreads();

        const uint32_t st = sb + STG0 + (kt & 1) * ASTG_B;

        float sc[8][4];
#pragma unroll
        for (int nt = 0; nt < 8; nt++)
#pragma unroll
            for (int j = 0; j < 4; j++) sc[nt][j] = 0.f;

#pragma unroll
        for (int t = 0; t < 4; t++) {
            uint32_t qh4[4], ql4[4];
            ldsm_x4(qh4, qBase + (uint32_t)(t * 16) * 2);
            ldsm_x4(ql4, qBase + AQ_ARR + (uint32_t)(t * 16) * 2);
#pragma unroll
            for (int g = 0; g < 4; g++) {
                uint32_t addr = st +
                    (uint32_t)((g * 16 + (lane & 15)) * AROW + t * 16 + ((lane >> 4) << 3)) * 2;
                uint32_t kh4[4];
                ldsm_x4(kh4, addr);
                mma_f16(sc[2 * g],     qh4, kh4[0], kh4[2]);
                mma_f16(sc[2 * g],     ql4, kh4[0], kh4[2]);
                mma_f16(sc[2 * g + 1], qh4, kh4[1], kh4[3]);
                mma_f16(sc[2 * g + 1], ql4, kh4[1], kh4[3]);
            }
        }

        if (kt * 64 + 63 > wrow_min) {
#pragma unroll
            for (int nt = 0; nt < 8; nt++) {
                int col = kt * 64 + nt * 8 + (lane & 3) * 2;
                if (col     > row_lo)     sc[nt][0] = -1e30f;
                if (col + 1 > row_lo)     sc[nt][1] = -1e30f;
                if (col     > row_lo + 8) sc[nt][2] = -1e30f;
                if (col + 1 > row_lo + 8) sc[nt][3] = -1e30f;
            }
        }

        float mx0 = -1e30f, mx1 = -1e30f;
#pragma unroll
        for (int nt = 0; nt < 8; nt++) {
            mx0 = fmaxf(mx0, fmaxf(sc[nt][0], sc[nt][1]));
            mx1 = fmaxf(mx1, fmaxf(sc[nt][2], sc[nt][3]));
        }
        mx0 = fmaxf(mx0, __shfl_xor_sync(0xffffffffu, mx0, 1));
        mx0 = fmaxf(mx0, __shfl_xor_sync(0xffffffffu, mx0, 2));
        mx1 = fmaxf(mx1, __shfl_xor_sync(0xffffffffu, mx1, 1));
        mx1 = fmaxf(mx1, __shfl_xor_sync(0xffffffffu, mx1, 2));

        float mn0 = fmaxf(m0, mx0);
        float mn1 = fmaxf(m1, mx1);
        float corr0 = __expf(m0 - mn0);
        float corr1 = __expf(m1 - mn1);
        m0 = mn0; m1 = mn1;

        float sum0 = 0.f, sum1 = 0.f;
#pragma unroll
        for (int nt = 0; nt < 8; nt++) {
            sc[nt][0] = __expf(sc[nt][0] - mn0);
            sc[nt][1] = __expf(sc[nt][1] - mn0);
            sc[nt][2] = __expf(sc[nt][2] - mn1);
            sc[nt][3] = __expf(sc[nt][3] - mn1);
            sum0 += sc[nt][0] + sc[nt][1];
            sum1 += sc[nt][2] + sc[nt][3];
        }
        sum0 += __shfl_xor_sync(0xffffffffu, sum0, 1);
        sum0 += __shfl_xor_sync(0xffffffffu, sum0, 2);
        sum1 += __shfl_xor_sync(0xffffffffu, sum1, 1);
        sum1 += __shfl_xor_sync(0xffffffffu, sum1, 2);
        l0 = l0 * corr0 + sum0;
        l1 = l1 * corr1 + sum1;

#pragma unroll
        for (int nt = 0; nt < 8; nt++) {
            oacc[nt][0] *= corr0; oacc[nt][1] *= corr0;
            oacc[nt][2] *= corr1; oacc[nt][3] *= corr1;
        }

        uint32_t ph[4][4], pl[4][4];
        float r0, r1;
#pragma unroll
        for (int t = 0; t < 4; t++) {
            ph[t][0] = pack2h_hi(sc[2 * t][0], sc[2 * t][1], r0, r1);
            pl[t][0] = pack2h(r0, r1);
            ph[t][1] = pack2h_hi(sc[2 * t][2], sc[2 * t][3], r0, r1);
            pl[t][1] = pack2h(r0, r1);
            ph[t][2] = pack2h_hi(sc[2 * t + 1][0], sc[2 * t + 1][1], r0, r1);
            pl[t][2] = pack2h(r0, r1);
            ph[t][3] = pack2h_hi(sc[2 * t + 1][2], sc[2 * t + 1][3], r0, r1);
            pl[t][3] = pack2h(r0, r1);
        }

#pragma unroll
        for (int t = 0; t < 4; t++) {
#pragma unroll
            for (int g = 0; g < 4; g++) {
                uint32_t addr = st + A_ARR +
                    (uint32_t)((t * 16 + (lane & 7) + ((lane >> 3) & 1) * 8) * AROW +
                               g * 16 + ((lane >> 4) << 3)) * 2;
                uint32_t vh4[4];
                ldsm_x4t(vh4, addr);
                mma_f16(oacc[2 * g],     ph[t], vh4[0], vh4[1]);
                mma_f16(oacc[2 * g],     pl[t], vh4[0], vh4[1]);
                mma_f16(oacc[2 * g + 1], ph[t], vh4[2], vh4[3]);
                mma_f16(oacc[2 * g + 1], pl[t], vh4[2], vh4[3]);
            }
        }
        __syncthreads();
    }

    // ---- epilogue: normalize + fp16 hi/lo split to global (for out-proj) ----
    float inv0 = 1.0f / l0;
    float inv1 = 1.0f / l1;
    size_t base0 = (size_t)(b * S_LEN + row_lo) * D_MODEL + h * DK;
    size_t base1 = base0 + (size_t)8 * D_MODEL;
    float r0, r1;
#pragma unroll
    for (int nt = 0; nt < 8; nt++) {
        int col = nt * 8 + (lane & 3) * 2;
        uint32_t h0 = pack2h_hi(oacc[nt][0] * inv0, oacc[nt][1] * inv0, r0, r1);
        uint32_t l0v = pack2h(r0, r1);
        uint32_t h1 = pack2h_hi(oacc[nt][2] * inv1, oacc[nt][3] * inv1, r0, r1);
        uint32_t l1v = pack2h(r0, r1);
        *(uint32_t*)(g_attnhi + base0 + col) = h0;
        *(uint32_t*)(g_attnlo + base0 + col) = l0v;
        *(uint32_t*)(g_attnhi + base1 + col) = h1;
        *(uint32_t*)(g_attnlo + base1 + col) = l1v;
    }
}

// ---------------- launch ------------------------------------------------------
extern "C" void kernel_launch(void* const* d_in, const int* in_sizes, int n_in,
                              void* d_out, int out_size)
{
    const float* x  = (const float*)d_in[0];
    const float* Wq = (const float*)d_in[1];
    const float* bq = (const float*)d_in[2];
    const float* Wk = (const float*)d_in[3];
    const float* bk = (const float*)d_in[4];
    const float* Wv = (const float*)d_in[5];
    const float* bv = (const float*)d_in[6];
    const float* Wo = (const float*)d_in[7];
    const float* bo = (const float*)d_in[8];
    float* out = (float*)d_out;

    static int configured = 0;
    if (!configured) {
        cudaFuncSetAttribute(tc_qkv_v3, cudaFuncAttributeMaxDynamicSharedMemorySize, GSMEM_TOTAL);
        cudaFuncSetAttribute(tc_out_v3, cudaFuncAttributeMaxDynamicSharedMemorySize, GSMEM_TOTAL);
        cudaFuncSetAttribute(attn_mma_kernel, cudaFuncAttributeMaxDynamicSharedMemorySize, A_SMEM);
        configured = 1;
    }

    // 0) rope table + fp16 split of x, fp16 cast of weights
    rope_table_kernel<<<(S_LEN * 32 + 255) / 256, 256>>>();
    split_all<<<(2 * 1024 * 1024) / 256, 256>>>(x, Wq, Wk, Wv, Wo);

    // 1) QKV projections (2-product fp16) + fused RoPE/scale epilogue
    dim3 g_qkv(D_MODEL / 128, M_TOT / 128, 3);
    tc_qkv_v3<<<g_qkv, 256, GSMEM_TOTAL>>>(bq, bk, bv);

    // 2) causal attention (fp16 left-split, 2+2 products)
    dim3 g_att(S_LEN / 128, BATCH * NHEAD);
    attn_mma_kernel<<<g_att, 256, A_SMEM>>>();

    // 3) output projection (2-product fp16)
    dim3 g_out(D_MODEL / 128, M_TOT / 128);
    tc_out_v3<<<g_out, 256, GSMEM_TOTAL>>>(bo, out);
}

// round 9
// speedup vs baseline: 4.6315x; 1.1527x over previous
#include <cuda_runtime.h>
#include <cuda_bf16.h>
#include <cuda_fp16.h>
#include <math.h>
#include <stdint.h>

#define D_MODEL 1024
#define S_LEN   2048
#define BATCH   2
#define NHEAD   16
#define DK      64
#define M_TOT   (BATCH * S_LEN)   // 4096
#define QSCALE  0.1803368801111244f   // (1/8) * log2(e)

// ---------------- scratch (device globals; no allocations allowed) ----------
__device__ __half g_Xhi[M_TOT * D_MODEL];
__device__ __half g_Xlo[M_TOT * D_MODEL];
__device__ __half g_Wq[D_MODEL * D_MODEL];
__device__ __half g_Wk[D_MODEL * D_MODEL];
__device__ __half g_Wv[D_MODEL * D_MODEL];
__device__ __half g_Wo[D_MODEL * D_MODEL];
__device__ __half g_Qhi[M_TOT * D_MODEL];
__device__ __half g_Qlo[M_TOT * D_MODEL];
__device__ __half g_Kh [M_TOT * D_MODEL];
__device__ __half g_Vh [M_TOT * D_MODEL];
__device__ __half g_attnhi[M_TOT * D_MODEL];
__device__ __half g_attnlo[M_TOT * D_MODEL];
__device__ float g_cos[S_LEN * 32];
__device__ float g_sin[S_LEN * 32];

// ---------------- common helpers --------------------------------------------
__device__ __forceinline__ uint32_t smem_u32(const void* p) {
    uint32_t a;
    asm("{ .reg .u64 t; cvta.to.shared.u64 t, %1; cvt.u32.u64 %0, t; }" : "=r"(a) : "l"(p));
    return a;
}

__device__ __forceinline__ float ex2f(float x) {
    float y;
    asm("ex2.approx.f32 %0, %1;" : "=f"(y) : "f"(x));
    return y;
}

__device__ __forceinline__ void ldsm_x4(uint32_t* r, uint32_t addr) {
    asm volatile("ldmatrix.sync.aligned.m8n8.x4.shared.b16 {%0,%1,%2,%3}, [%4];"
                 : "=r"(r[0]), "=r"(r[1]), "=r"(r[2]), "=r"(r[3]) : "r"(addr));
}

__device__ __forceinline__ void ldsm_x4t(uint32_t* r, uint32_t addr) {
    asm volatile("ldmatrix.sync.aligned.m8n8.x4.trans.shared.b16 {%0,%1,%2,%3}, [%4];"
                 : "=r"(r[0]), "=r"(r[1]), "=r"(r[2]), "=r"(r[3]) : "r"(addr));
}

__device__ __forceinline__ void mma_f16(float* c, const uint32_t* a,
                                        uint32_t b0, uint32_t b1) {
    asm volatile("mma.sync.aligned.m16n8k16.row.col.f32.f16.f16.f32 "
                 "{%0,%1,%2,%3}, {%4,%5,%6,%7}, {%8,%9}, {%0,%1,%2,%3};"
                 : "+f"(c[0]), "+f"(c[1]), "+f"(c[2]), "+f"(c[3])
                 : "r"(a[0]), "r"(a[1]), "r"(a[2]), "r"(a[3]), "r"(b0), "r"(b1));
}

__device__ __forceinline__ uint32_t pack2h_hi(float a, float b, float& ra, float& rb) {
    __half ha = __float2half_rn(a);
    __half hb = __float2half_rn(b);
    ra = a - __half2float(ha);
    rb = b - __half2float(hb);
    union { __half2 h; uint32_t u; } c;
    c.h = __halves2half2(ha, hb);
    return c.u;
}

__device__ __forceinline__ uint32_t pack2h(float a, float b) {
    union { __half2 h; uint32_t u; } c;
    c.h = __halves2half2(__float2half_rn(a), __float2half_rn(b));
    return c.u;
}

#define CP16(saddr, gptr) \
    asm volatile("cp.async.cg.shared.global [%0], [%1], 16;" :: "r"(saddr), "l"(gptr))
#define CP_COMMIT() asm volatile("cp.async.commit_group;" ::: "memory")
#define CP_WAIT0()  asm volatile("cp.async.wait_group 0;" ::: "memory")
#define CP_WAIT1()  asm volatile("cp.async.wait_group 1;" ::: "memory")

// ---------------- rope table + input split -----------------------------------
__global__ void rope_table_kernel()
{
    int idx = blockIdx.x * blockDim.x + threadIdx.x;
    if (idx >= S_LEN * 32) return;
    int s = idx >> 5, i = idx & 31;
    float inv_freq = __expf(-(float)(2 * i) * (9.210340371976184f / 64.0f));
    float ang = (float)s * inv_freq;
    g_cos[idx] = cosf(ang);
    g_sin[idx] = sinf(ang);
}

__global__ void split_all(const float* __restrict__ x,  const float* __restrict__ Wq,
                          const float* __restrict__ Wk, const float* __restrict__ Wv,
                          const float* __restrict__ Wo)
{
    int t = blockIdx.x * blockDim.x + threadIdx.x;   // 0..2M-1
    if (t < (1 << 20)) {
        float4 v = ((const float4*)x)[t];
        float r0, r1, r2, r3;
        uint2 hi, lo;
        hi.x = pack2h_hi(v.x, v.y, r0, r1);
        hi.y = pack2h_hi(v.z, v.w, r2, r3);
        lo.x = pack2h(r0, r1);
        lo.y = pack2h(r2, r3);
        ((uint2*)g_Xhi)[t] = hi;
        ((uint2*)g_Xlo)[t] = lo;
    } else {
        int r = t - (1 << 20);
        int w = r >> 18;
        size_t off = (size_t)(r & ((1 << 18) - 1));
        const float* src;
        __half* dst;
        if      (w == 0) { src = Wq; dst = g_Wq; }
        else if (w == 1) { src = Wk; dst = g_Wk; }
        else if (w == 2) { src = Wv; dst = g_Wv; }
        else             { src = Wo; dst = g_Wo; }
        float4 v = ((const float4*)src)[off];
        uint2 o;
        o.x = pack2h(v.x, v.y);
        o.y = pack2h(v.z, v.w);
        ((uint2*)dst)[off] = o;
    }
}

// =================== fp16 left-split GEMM (2 products, BK=64) ================
#define GBK 64
#define GCHUNKS (D_MODEL / GBK)           // 16
#define GROWH  72                         // 144B row stride, conflict-free
#define GARR_B (128 * GROWH * 2)          // 18432
#define GSTG_B (3 * GARR_B)               // 55296 (Ahi, Alo, B)
#define GSMEM_TOTAL (2 * GSTG_B)          // 110592

__device__ __forceinline__ void gemm_v3_core(
    const __half* __restrict__ Ahi, const __half* __restrict__ Alo,
    const __half* __restrict__ B,
    int bm, int bn, float (&acc)[4][4][4])
{
    extern __shared__ char smem[];
    const uint32_t sb = smem_u32(smem);
    const int tid  = threadIdx.x;
    const int wid  = tid >> 5;
    const int lane = tid & 31;
    const int warp_m = (wid >> 2) * 64;
    const int warp_n = (wid & 3) * 32;

#pragma unroll
    for (int i = 0; i < 4; i++)
#pragma unroll
        for (int j = 0; j < 4; j++)
#pragma unroll
            for (int k = 0; k < 4; k++) acc[i][j][k] = 0.f;

    auto issue = [&](int stg, int c) {
        const uint32_t st = sb + stg * GSTG_B;
        const int k0 = c * GBK;
#pragma unroll
        for (int it = 0; it < 4; it++) {
            int slot = tid + it * 256;            // 0..1023
            int r  = slot >> 3;                   // 0..127
            int c8 = (slot & 7) * 8;              // halves
            uint32_t soff = (uint32_t)(r * GROWH + c8) * 2;
            size_t ga = (size_t)(bm + r) * D_MODEL + k0 + c8;
            size_t gb = (size_t)(bn + r) * D_MODEL + k0 + c8;
            CP16(st + soff,              (const char*)(Ahi + ga));
            CP16(st + GARR_B + soff,     (const char*)(Alo + ga));
            CP16(st + 2 * GARR_B + soff, (const char*)(B + gb));
        }
    };

    issue(0, 0);
    CP_COMMIT();

    const int qrow = lane & 15;
    const int qcol = (lane >> 4) << 3;

    for (int c = 0; c < GCHUNKS; c++) {
        if (c + 1 < GCHUNKS) { issue((c + 1) & 1, c + 1); CP_COMMIT(); CP_WAIT1(); }
        else                 { CP_WAIT0(); }
        __syncthreads();

        const uint32_t st = sb + (c & 1) * GSTG_B;
        const uint32_t aBase = st + (uint32_t)((warp_m + qrow) * GROWH + qcol) * 2;
        const uint32_t bBase = st + 2 * GARR_B + (uint32_t)((warp_n + qrow) * GROWH + qcol) * 2;

#pragma unroll
        for (int ks = 0; ks < 4; ks++) {
            const uint32_t ko = (uint32_t)(ks * 16) * 2;
            uint32_t bf[2][4];
#pragma unroll
            for (int nt = 0; nt < 2; nt++)
                ldsm_x4(bf[nt], bBase + nt * (16 * GROWH * 2) + ko);
#pragma unroll
            for (int mi = 0; mi < 4; mi++) {
                uint32_t ah[4], al[4];
                ldsm_x4(ah, aBase + mi * (16 * GROWH * 2) + ko);
                ldsm_x4(al, aBase + GARR_B + mi * (16 * GROWH * 2) + ko);
#pragma unroll
                for (int nt = 0; nt < 2; nt++)
#pragma unroll
                    for (int nj = 0; nj < 2; nj++) {
                        float* cc = acc[mi][nt * 2 + nj];
                        mma_f16(cc, ah, bf[nt][nj], bf[nt][nj + 2]);
                        mma_f16(cc, al, bf[nt][nj], bf[nt][nj + 2]);
                    }
            }
        }
        __syncthreads();
    }
}

// QKV GEMM: fused bias + RoPE; Q -> fp16 hi/lo (log2e-scaled), K/V -> fp16
__global__ __launch_bounds__(256, 2)
void tc_qkv_v3(const float* __restrict__ bq, const float* __restrict__ bk,
               const float* __restrict__ bv)
{
    const int z = blockIdx.z;
    const __half* W;
    const float* bias;
    if (z == 0)      { W = g_Wq; bias = bq; }
    else if (z == 1) { W = g_Wk; bias = bk; }
    else             { W = g_Wv; bias = bv; }

    const int bm = blockIdx.y * 128;
    const int bn = blockIdx.x * 128;
    float acc[4][4][4];
    gemm_v3_core(g_Xhi, g_Xlo, W, bm, bn, acc);

    const int wid  = threadIdx.x >> 5;
    const int lane = threadIdx.x & 31;
    const int warp_m = (wid >> 2) * 64;
    const int warp_n = (wid & 3) * 32;
    const int erow = lane >> 2;
    const int ecol = (lane & 3) * 2;

#pragma unroll
    for (int mi = 0; mi < 4; mi++)
#pragma unroll
        for (int nt = 0; nt < 2; nt++)
#pragma unroll
            for (int nj = 0; nj < 2; nj++) {
                float* cc = acc[mi][nt * 2 + nj];
                int m = bm + warp_m + mi * 16 + erow;
                int n = bn + warp_n + nt * 16 + nj * 8 + ecol;
                float v0 = cc[0] + bias[n], v1 = cc[1] + bias[n + 1];
                float w0 = cc[2] + bias[n], w1 = cc[3] + bias[n + 1];
                if (z < 2) {
                    int i  = (n & 63) >> 1;
                    int s0 = (m & 2047) * 32 + i;
                    int s1 = ((m + 8) & 2047) * 32 + i;
                    float cs0 = g_cos[s0], sn0 = g_sin[s0];
                    float cs1 = g_cos[s1], sn1 = g_sin[s1];
                    float t0 = v0 * cs0 - v1 * sn0, t1 = v0 * sn0 + v1 * cs0;
                    float u0 = w0 * cs1 - w1 * sn1, u1 = w0 * sn1 + w1 * cs1;
                    if (z == 0) { t0 *= QSCALE; t1 *= QSCALE; u0 *= QSCALE; u1 *= QSCALE; }
                    v0 = t0; v1 = t1; w0 = u0; w1 = u1;
                }
                size_t o0 = (size_t)m * D_MODEL + n;
                size_t o1 = (size_t)(m + 8) * D_MODEL + n;
                if (z == 0) {
                    float r0, r1;
                    uint32_t h0 = pack2h_hi(v0, v1, r0, r1);
                    uint32_t l0v = pack2h(r0, r1);
                    uint32_t h1 = pack2h_hi(w0, w1, r0, r1);
                    uint32_t l1v = pack2h(r0, r1);
                    *(uint32_t*)(g_Qhi + o0) = h0;
                    *(uint32_t*)(g_Qlo + o0) = l0v;
                    *(uint32_t*)(g_Qhi + o1) = h1;
                    *(uint32_t*)(g_Qlo + o1) = l1v;
                } else {
                    __half* D = (z == 1) ? g_Kh : g_Vh;
                    *(uint32_t*)(D + o0) = pack2h(v0, v1);
                    *(uint32_t*)(D + o1) = pack2h(w0, w1);
                }
            }
}

__global__ __launch_bounds__(256, 2)
void tc_out_v3(const float* __restrict__ bo, float* __restrict__ out)
{
    const int bm = blockIdx.y * 128;
    const int bn = blockIdx.x * 128;
    float acc[4][4][4];
    gemm_v3_core(g_attnhi, g_attnlo, g_Wo, bm, bn, acc);

    const int wid  = threadIdx.x >> 5;
    const int lane = threadIdx.x & 31;
    const int warp_m = (wid >> 2) * 64;
    const int warp_n = (wid & 3) * 32;
    const int erow = lane >> 2;
    const int ecol = (lane & 3) * 2;

#pragma unroll
    for (int mi = 0; mi < 4; mi++)
#pragma unroll
        for (int nt = 0; nt < 2; nt++)
#pragma unroll
            for (int nj = 0; nj < 2; nj++) {
                float* cc = acc[mi][nt * 2 + nj];
                int m = bm + warp_m + mi * 16 + erow;
                int n = bn + warp_n + nt * 16 + nj * 8 + ecol;
                float2 v0 = make_float2(cc[0] + bo[n], cc[1] + bo[n + 1]);
                float2 v1 = make_float2(cc[2] + bo[n], cc[3] + bo[n + 1]);
                *(float2*)(out + (size_t)m * D_MODEL + n)       = v0;
                *(float2*)(out + (size_t)(m + 8) * D_MODEL + n) = v1;
            }
}

// -------- tensor-core causal flash attention v5 (exp2 domain, P unsplit PV) --
#define AROW   72
#define A_ARR  (64 * AROW * 2)            // 9216
#define AQ_ARR (128 * AROW * 2)           // 18432
#define SQ_HI  0
#define SQ_LO  AQ_ARR
#define STG0   (2 * AQ_ARR)               // 36864
#define ASTG_B (2 * A_ARR)                // 18432 (Kh, Vh)
#define A_SMEM (2 * AQ_ARR + 2 * ASTG_B)  // 73728

__global__ __launch_bounds__(256, 2)
void attn_mma_kernel()
{
    extern __shared__ char smem[];
    const uint32_t sb = smem_u32(smem);
    const int tid  = threadIdx.x;
    const int wid  = tid >> 5;
    const int lane = tid & 31;
    const int qb = (int)gridDim.x - 1 - (int)blockIdx.x;
    const int bh = blockIdx.y;
    const int b  = bh >> 4;
    const int h  = bh & 15;
    const int q0 = qb * 128;

    const size_t qgbase = (size_t)(b * S_LEN + q0) * D_MODEL + h * DK;
    const size_t kgbase = (size_t)(b * S_LEN) * D_MODEL + h * DK;

    auto issue_tile = [&](int stg, int kt) {
        const uint32_t sbase = sb + STG0 + stg * ASTG_B;
        const size_t g0 = kgbase + (size_t)(kt * 64) * D_MODEL;
#pragma unroll
        for (int it = 0; it < 2; it++) {
            int slot = tid + it * 256;
            int r  = slot >> 3;
            int c8 = (slot & 7) * 8;
            uint32_t soff = (uint32_t)(r * AROW + c8) * 2;
            const size_t go = g0 + (size_t)r * D_MODEL + c8;
            CP16(sbase + soff,         (const char*)(g_Kh + go));
            CP16(sbase + A_ARR + soff, (const char*)(g_Vh + go));
        }
    };

    issue_tile(0, 0);
    CP_COMMIT();

#pragma unroll
    for (int it = 0; it < 4; it++) {
        int slot = tid + it * 256;
        int r  = slot >> 3;
        int c8 = (slot & 7) * 8;
        uint32_t soff = (uint32_t)(r * AROW + c8) * 2;
        const size_t go = qgbase + (size_t)r * D_MODEL + c8;
        *(uint4*)(smem + SQ_HI + soff) = *(const uint4*)(g_Qhi + go);
        *(uint4*)(smem + SQ_LO + soff) = *(const uint4*)(g_Qlo + go);
    }
    __syncthreads();

    float oacc[8][4];
#pragma unroll
    for (int nt = 0; nt < 8; nt++)
#pragma unroll
        for (int j = 0; j < 4; j++) oacc[nt][j] = 0.f;
    float m0 = -1e30f, m1 = -1e30f, l0 = 0.f, l1 = 0.f;

    const int row_lo   = q0 + wid * 16 + (lane >> 2);
    const int wrow_min = q0 + wid * 16;
    const int ntiles = 2 * qb + 2;

    const uint32_t qBase = sb + SQ_HI +
        (uint32_t)((wid * 16 + (lane & 15)) * AROW + ((lane >> 4) << 3)) * 2;

    for (int kt = 0; kt < ntiles; kt++) {
        if (kt + 1 < ntiles) { issue_tile((kt + 1) & 1, kt + 1); CP_COMMIT(); CP_WAIT1(); }
        else                 { CP_WAIT0(); }
        __syncthreads();

        const uint32_t st = sb + STG0 + (kt & 1) * ASTG_B;

        float sc[8][4];
#pragma unroll
        for (int nt = 0; nt < 8; nt++)
#pragma unroll
            for (int j = 0; j < 4; j++) sc[nt][j] = 0.f;

        // S(log2) = (Qhi + Qlo) @ Kh^T
#pragma unroll
        for (int t = 0; t < 4; t++) {
            uint32_t qh4[4], ql4[4];
            ldsm_x4(qh4, qBase + (uint32_t)(t * 16) * 2);
            ldsm_x4(ql4, qBase + AQ_ARR + (uint32_t)(t * 16) * 2);
#pragma unroll
            for (int g = 0; g < 4; g++) {
                uint32_t addr = st +
                    (uint32_t)((g * 16 + (lane & 15)) * AROW + t * 16 + ((lane >> 4) << 3)) * 2;
                uint32_t kh4[4];
                ldsm_x4(kh4, addr);
                mma_f16(sc[2 * g],     qh4, kh4[0], kh4[2]);
                mma_f16(sc[2 * g],     ql4, kh4[0], kh4[2]);
                mma_f16(sc[2 * g + 1], qh4, kh4[1], kh4[3]);
                mma_f16(sc[2 * g + 1], ql4, kh4[1], kh4[3]);
            }
        }

        if (kt * 64 + 63 > wrow_min) {
#pragma unroll
            for (int nt = 0; nt < 8; nt++) {
                int col = kt * 64 + nt * 8 + (lane & 3) * 2;
                if (col     > row_lo)     sc[nt][0] = -1e30f;
                if (col + 1 > row_lo)     sc[nt][1] = -1e30f;
                if (col     > row_lo + 8) sc[nt][2] = -1e30f;
                if (col + 1 > row_lo + 8) sc[nt][3] = -1e30f;
            }
        }

        float mx0 = -1e30f, mx1 = -1e30f;
#pragma unroll
        for (int nt = 0; nt < 8; nt++) {
            mx0 = fmaxf(mx0, fmaxf(sc[nt][0], sc[nt][1]));
            mx1 = fmaxf(mx1, fmaxf(sc[nt][2], sc[nt][3]));
        }
        mx0 = fmaxf(mx0, __shfl_xor_sync(0xffffffffu, mx0, 1));
        mx0 = fmaxf(mx0, __shfl_xor_sync(0xffffffffu, mx0, 2));
        mx1 = fmaxf(mx1, __shfl_xor_sync(0xffffffffu, mx1, 1));
        mx1 = fmaxf(mx1, __shfl_xor_sync(0xffffffffu, mx1, 2));

        float mn0 = fmaxf(m0, mx0);
        float mn1 = fmaxf(m1, mx1);
        float corr0 = ex2f(m0 - mn0);
        float corr1 = ex2f(m1 - mn1);
        m0 = mn0; m1 = mn1;

        float sum0 = 0.f, sum1 = 0.f;
#pragma unroll
        for (int nt = 0; nt < 8; nt++) {
            sc[nt][0] = ex2f(sc[nt][0] - mn0);
            sc[nt][1] = ex2f(sc[nt][1] - mn0);
            sc[nt][2] = ex2f(sc[nt][2] - mn1);
            sc[nt][3] = ex2f(sc[nt][3] - mn1);
            sum0 += sc[nt][0] + sc[nt][1];
            sum1 += sc[nt][2] + sc[nt][3];
        }
        sum0 += __shfl_xor_sync(0xffffffffu, sum0, 1);
        sum0 += __shfl_xor_sync(0xffffffffu, sum0, 2);
        sum1 += __shfl_xor_sync(0xffffffffu, sum1, 1);
        sum1 += __shfl_xor_sync(0xffffffffu, sum1, 2);
        l0 = l0 * corr0 + sum0;
        l1 = l1 * corr1 + sum1;

#pragma unroll
        for (int nt = 0; nt < 8; nt++) {
            oacc[nt][0] *= corr0; oacc[nt][1] *= corr0;
            oacc[nt][2] *= corr1; oacc[nt][3] *= corr1;
        }

        // pack P to fp16 (single product)
        uint32_t ph[4][4];
#pragma unroll
        for (int t = 0; t < 4; t++) {
            ph[t][0] = pack2h(sc[2 * t][0],     sc[2 * t][1]);
            ph[t][1] = pack2h(sc[2 * t][2],     sc[2 * t][3]);
            ph[t][2] = pack2h(sc[2 * t + 1][0], sc[2 * t + 1][1]);
            ph[t][3] = pack2h(sc[2 * t + 1][2], sc[2 * t + 1][3]);
        }

        // O += P @ Vh : 1 fp16 product
#pragma unroll
        for (int t = 0; t < 4; t++) {
#pragma unroll
            for (int g = 0; g < 4; g++) {
                uint32_t addr = st + A_ARR +
                    (uint32_t)((t * 16 + (lane & 7) + ((lane >> 3) & 1) * 8) * AROW +
                               g * 16 + ((lane >> 4) << 3)) * 2;
                uint32_t vh4[4];
                ldsm_x4t(vh4, addr);
                mma_f16(oacc[2 * g],     ph[t], vh4[0], vh4[1]);
                mma_f16(oacc[2 * g + 1], ph[t], vh4[2], vh4[3]);
            }
        }
        __syncthreads();
    }

    // ---- epilogue: normalize + fp16 hi/lo split to global (for out-proj) ----
    float inv0 = 1.0f / l0;
    float inv1 = 1.0f / l1;
    size_t base0 = (size_t)(b * S_LEN + row_lo) * D_MODEL + h * DK;
    size_t base1 = base0 + (size_t)8 * D_MODEL;
    float r0, r1;
#pragma unroll
    for (int nt = 0; nt < 8; nt++) {
        int col = nt * 8 + (lane & 3) * 2;
        uint32_t h0 = pack2h_hi(oacc[nt][0] * inv0, oacc[nt][1] * inv0, r0, r1);
        uint32_t l0v = pack2h(r0, r1);
        uint32_t h1 = pack2h_hi(oacc[nt][2] * inv1, oacc[nt][3] * inv1, r0, r1);
        uint32_t l1v = pack2h(r0, r1);
        *(uint32_t*)(g_attnhi + base0 + col) = h0;
        *(uint32_t*)(g_attnlo + base0 + col) = l0v;
        *(uint32_t*)(g_attnhi + base1 + col) = h1;
        *(uint32_t*)(g_attnlo + base1 + col) = l1v;
    }
}

// ---------------- launch ------------------------------------------------------
extern "C" void kernel_launch(void* const* d_in, const int* in_sizes, int n_in,
                              void* d_out, int out_size)
{
    const float* x  = (const float*)d_in[0];
    const float* Wq = (const float*)d_in[1];
    const float* bq = (const float*)d_in[2];
    const float* Wk = (const float*)d_in[3];
    const float* bk = (const float*)d_in[4];
    const float* Wv = (const float*)d_in[5];
    const float* bv = (const float*)d_in[6];
    const float* Wo = (const float*)d_in[7];
    const float* bo = (const float*)d_in[8];
    float* out = (float*)d_out;

    static int configured = 0;
    if (!configured) {
        cudaFuncSetAttribute(tc_qkv_v3, cudaFuncAttributeMaxDynamicSharedMemorySize, GSMEM_TOTAL);
        cudaFuncSetAttribute(tc_out_v3, cudaFuncAttributeMaxDynamicSharedMemorySize, GSMEM_TOTAL);
        cudaFuncSetAttribute(attn_mma_kernel, cudaFuncAttributeMaxDynamicSharedMemorySize, A_SMEM);
        configured = 1;
    }

    // 0) rope table + fp16 split of x, fp16 cast of weights
    rope_table_kernel<<<(S_LEN * 32 + 255) / 256, 256>>>();
    split_all<<<(2 * 1024 * 1024) / 256, 256>>>(x, Wq, Wk, Wv, Wo);

    // 1) QKV projections (2-product fp16, BK=64) + fused RoPE/scale epilogue
    dim3 g_qkv(D_MODEL / 128, M_TOT / 128, 3);
    tc_qkv_v3<<<g_qkv, 256, GSMEM_TOTAL>>>(bq, bk, bv);

    // 2) causal attention (exp2 domain, Q split, P/K/V plain fp16)
    dim3 g_att(S_LEN / 128, BATCH * NHEAD);
    attn_mma_kernel<<<g_att, 256, A_SMEM>>>();

    // 3) output projection (2-product fp16, BK=64)
    dim3 g_out(D_MODEL / 128, M_TOT / 128);
    tc_out_v3<<<g_out, 256, GSMEM_TOTAL>>>(bo, out);
}

// round 10
// speedup vs baseline: 6.3333x; 1.3674x over previous
#include <cuda_runtime.h>
#include <cuda_bf16.h>
#include <cuda_fp16.h>
#include <math.h>
#include <stdint.h>

#define D_MODEL 1024
#define S_LEN   2048
#define BATCH   2
#define NHEAD   16
#define DK      64
#define M_TOT   (BATCH * S_LEN)   // 4096
#define QSCALE  0.1803368801111244f   // (1/8) * log2(e)

// ---------------- scratch (device globals; no allocations allowed) ----------
__device__ __half g_Xh[M_TOT * D_MODEL];
__device__ __half g_Wq[D_MODEL * D_MODEL];
__device__ __half g_Wk[D_MODEL * D_MODEL];
__device__ __half g_Wv[D_MODEL * D_MODEL];
__device__ __half g_Wo[D_MODEL * D_MODEL];
__device__ __half g_Qhi[M_TOT * D_MODEL];
__device__ __half g_Qlo[M_TOT * D_MODEL];
__device__ __half g_Kh [M_TOT * D_MODEL];
__device__ __half g_Vh [M_TOT * D_MODEL];
__device__ __half g_attnh[M_TOT * D_MODEL];
__device__ float g_cos[S_LEN * 32];
__device__ float g_sin[S_LEN * 32];

// ---------------- common helpers --------------------------------------------
__device__ __forceinline__ uint32_t smem_u32(const void* p) {
    uint32_t a;
    asm("{ .reg .u64 t; cvta.to.shared.u64 t, %1; cvt.u32.u64 %0, t; }" : "=r"(a) : "l"(p));
    return a;
}

__device__ __forceinline__ float ex2f(float x) {
    float y;
    asm("ex2.approx.f32 %0, %1;" : "=f"(y) : "f"(x));
    return y;
}

__device__ __forceinline__ void ldsm_x4(uint32_t* r, uint32_t addr) {
    asm volatile("ldmatrix.sync.aligned.m8n8.x4.shared.b16 {%0,%1,%2,%3}, [%4];"
                 : "=r"(r[0]), "=r"(r[1]), "=r"(r[2]), "=r"(r[3]) : "r"(addr));
}

__device__ __forceinline__ void ldsm_x4t(uint32_t* r, uint32_t addr) {
    asm volatile("ldmatrix.sync.aligned.m8n8.x4.trans.shared.b16 {%0,%1,%2,%3}, [%4];"
                 : "=r"(r[0]), "=r"(r[1]), "=r"(r[2]), "=r"(r[3]) : "r"(addr));
}

__device__ __forceinline__ void mma_f16(float* c, const uint32_t* a,
                                        uint32_t b0, uint32_t b1) {
    asm volatile("mma.sync.aligned.m16n8k16.row.col.f32.f16.f16.f32 "
                 "{%0,%1,%2,%3}, {%4,%5,%6,%7}, {%8,%9}, {%0,%1,%2,%3};"
                 : "+f"(c[0]), "+f"(c[1]), "+f"(c[2]), "+f"(c[3])
                 : "r"(a[0]), "r"(a[1]), "r"(a[2]), "r"(a[3]), "r"(b0), "r"(b1));
}

__device__ __forceinline__ uint32_t pack2h_hi(float a, float b, float& ra, float& rb) {
    __half ha = __float2half_rn(a);
    __half hb = __float2half_rn(b);
    ra = a - __half2float(ha);
    rb = b - __half2float(hb);
    union { __half2 h; uint32_t u; } c;
    c.h = __halves2half2(ha, hb);
    return c.u;
}

__device__ __forceinline__ uint32_t pack2h(float a, float b) {
    union { __half2 h; uint32_t u; } c;
    c.h = __halves2half2(__float2half_rn(a), __float2half_rn(b));
    return c.u;
}

#define CP16(saddr, gptr) \
    asm volatile("cp.async.cg.shared.global [%0], [%1], 16;" :: "r"(saddr), "l"(gptr))
#define CP_COMMIT() asm volatile("cp.async.commit_group;" ::: "memory")
#define CP_WAIT0()  asm volatile("cp.async.wait_group 0;" ::: "memory")
#define CP_WAIT1()  asm volatile("cp.async.wait_group 1;" ::: "memory")

// ---------------- rope table + fp16 casts ------------------------------------
__global__ void rope_table_kernel()
{
    int idx = blockIdx.x * blockDim.x + threadIdx.x;
    if (idx >= S_LEN * 32) return;
    int s = idx >> 5, i = idx & 31;
    float inv_freq = __expf(-(float)(2 * i) * (9.210340371976184f / 64.0f));
    float ang = (float)s * inv_freq;
    g_cos[idx] = cosf(ang);
    g_sin[idx] = sinf(ang);
}

// x and all weights -> plain fp16
__global__ void split_all(const float* __restrict__ x,  const float* __restrict__ Wq,
                          const float* __restrict__ Wk, const float* __restrict__ Wv,
                          const float* __restrict__ Wo)
{
    int t = blockIdx.x * blockDim.x + threadIdx.x;   // 0..2M-1
    const float* src;
    __half* dst;
    size_t off;
    if (t < (1 << 20)) { src = x; dst = g_Xh; off = t; }
    else {
        int r = t - (1 << 20);
        int w = r >> 18;
        off = (size_t)(r & ((1 << 18) - 1));
        if      (w == 0) { src = Wq; dst = g_Wq; }
        else if (w == 1) { src = Wk; dst = g_Wk; }
        else if (w == 2) { src = Wv; dst = g_Wv; }
        else             { src = Wo; dst = g_Wo; }
    }
    float4 v = ((const float4*)src)[off];
    uint2 o;
    o.x = pack2h(v.x, v.y);
    o.y = pack2h(v.z, v.w);
    ((uint2*)dst)[off] = o;
}

// =================== fp16 single-product GEMM (BK=64) ========================
#define GBK 64
#define GCHUNKS (D_MODEL / GBK)           // 16
#define GROWH  72                         // 144B row stride, conflict-free
#define GARR_B (128 * GROWH * 2)          // 18432
#define GSTG_B (2 * GARR_B)               // 36864 (A, B)
#define GSMEM_TOTAL (2 * GSTG_B)          // 73728

__device__ __forceinline__ void gemm_v4_core(
    const __half* __restrict__ A, const __half* __restrict__ B,
    int bm, int bn, float (&acc)[4][4][4])
{
    extern __shared__ char smem[];
    const uint32_t sb = smem_u32(smem);
    const int tid  = threadIdx.x;
    const int wid  = tid >> 5;
    const int lane = tid & 31;
    const int warp_m = (wid >> 2) * 64;
    const int warp_n = (wid & 3) * 32;

#pragma unroll
    for (int i = 0; i < 4; i++)
#pragma unroll
        for (int j = 0; j < 4; j++)
#pragma unroll
            for (int k = 0; k < 4; k++) acc[i][j][k] = 0.f;

    auto issue = [&](int stg, int c) {
        const uint32_t st = sb + stg * GSTG_B;
        const int k0 = c * GBK;
#pragma unroll
        for (int it = 0; it < 4; it++) {
            int slot = tid + it * 256;            // 0..1023
            int r  = slot >> 3;                   // 0..127
            int c8 = (slot & 7) * 8;              // halves
            uint32_t soff = (uint32_t)(r * GROWH + c8) * 2;
            size_t ga = (size_t)(bm + r) * D_MODEL + k0 + c8;
            size_t gb = (size_t)(bn + r) * D_MODEL + k0 + c8;
            CP16(st + soff,          (const char*)(A + ga));
            CP16(st + GARR_B + soff, (const char*)(B + gb));
        }
    };

    issue(0, 0);
    CP_COMMIT();

    const int qrow = lane & 15;
    const int qcol = (lane >> 4) << 3;

    for (int c = 0; c < GCHUNKS; c++) {
        if (c + 1 < GCHUNKS) { issue((c + 1) & 1, c + 1); CP_COMMIT(); CP_WAIT1(); }
        else                 { CP_WAIT0(); }
        __syncthreads();

        const uint32_t st = sb + (c & 1) * GSTG_B;
        const uint32_t aBase = st + (uint32_t)((warp_m + qrow) * GROWH + qcol) * 2;
        const uint32_t bBase = st + GARR_B + (uint32_t)((warp_n + qrow) * GROWH + qcol) * 2;

#pragma unroll
        for (int ks = 0; ks < 4; ks++) {
            const uint32_t ko = (uint32_t)(ks * 16) * 2;
            uint32_t bf[2][4];
#pragma unroll
            for (int nt = 0; nt < 2; nt++)
                ldsm_x4(bf[nt], bBase + nt * (16 * GROWH * 2) + ko);
#pragma unroll
            for (int mi = 0; mi < 4; mi++) {
                uint32_t af[4];
                ldsm_x4(af, aBase + mi * (16 * GROWH * 2) + ko);
#pragma unroll
                for (int nt = 0; nt < 2; nt++)
#pragma unroll
                    for (int nj = 0; nj < 2; nj++)
                        mma_f16(acc[mi][nt * 2 + nj], af, bf[nt][nj], bf[nt][nj + 2]);
            }
        }
        __syncthreads();
    }
}

// QKV GEMM: fused bias + RoPE; Q -> fp16 hi/lo (log2e-scaled), K/V -> fp16
__global__ __launch_bounds__(256, 2)
void tc_qkv_v4(const float* __restrict__ bq, const float* __restrict__ bk,
               const float* __restrict__ bv)
{
    const int z = blockIdx.z;
    const __half* W;
    const float* bias;
    if (z == 0)      { W = g_Wq; bias = bq; }
    else if (z == 1) { W = g_Wk; bias = bk; }
    else             { W = g_Wv; bias = bv; }

    const int bm = blockIdx.y * 128;
    const int bn = blockIdx.x * 128;
    float acc[4][4][4];
    gemm_v4_core(g_Xh, W, bm, bn, acc);

    const int wid  = threadIdx.x >> 5;
    const int lane = threadIdx.x & 31;
    const int warp_m = (wid >> 2) * 64;
    const int warp_n = (wid & 3) * 32;
    const int erow = lane >> 2;
    const int ecol = (lane & 3) * 2;

#pragma unroll
    for (int mi = 0; mi < 4; mi++)
#pragma unroll
        for (int nt = 0; nt < 2; nt++)
#pragma unroll
            for (int nj = 0; nj < 2; nj++) {
                float* cc = acc[mi][nt * 2 + nj];
                int m = bm + warp_m + mi * 16 + erow;
                int n = bn + warp_n + nt * 16 + nj * 8 + ecol;
                float v0 = cc[0] + bias[n], v1 = cc[1] + bias[n + 1];
                float w0 = cc[2] + bias[n], w1 = cc[3] + bias[n + 1];
                if (z < 2) {
                    int i  = (n & 63) >> 1;
                    int s0 = (m & 2047) * 32 + i;
                    int s1 = ((m + 8) & 2047) * 32 + i;
                    float cs0 = g_cos[s0], sn0 = g_sin[s0];
                    float cs1 = g_cos[s1], sn1 = g_sin[s1];
                    float t0 = v0 * cs0 - v1 * sn0, t1 = v0 * sn0 + v1 * cs0;
                    float u0 = w0 * cs1 - w1 * sn1, u1 = w0 * sn1 + w1 * cs1;
                    if (z == 0) { t0 *= QSCALE; t1 *= QSCALE; u0 *= QSCALE; u1 *= QSCALE; }
                    v0 = t0; v1 = t1; w0 = u0; w1 = u1;
                }
                size_t o0 = (size_t)m * D_MODEL + n;
                size_t o1 = (size_t)(m + 8) * D_MODEL + n;
                if (z == 0) {
                    float r0, r1;
                    uint32_t h0 = pack2h_hi(v0, v1, r0, r1);
                    uint32_t l0v = pack2h(r0, r1);
                    uint32_t h1 = pack2h_hi(w0, w1, r0, r1);
                    uint32_t l1v = pack2h(r0, r1);
                    *(uint32_t*)(g_Qhi + o0) = h0;
                    *(uint32_t*)(g_Qlo + o0) = l0v;
                    *(uint32_t*)(g_Qhi + o1) = h1;
                    *(uint32_t*)(g_Qlo + o1) = l1v;
                } else {
                    __half* D = (z == 1) ? g_Kh : g_Vh;
                    *(uint32_t*)(D + o0) = pack2h(v0, v1);
                    *(uint32_t*)(D + o1) = pack2h(w0, w1);
                }
            }
}

__global__ __launch_bounds__(256, 2)
void tc_out_v4(const float* __restrict__ bo, float* __restrict__ out)
{
    const int bm = blockIdx.y * 128;
    const int bn = blockIdx.x * 128;
    float acc[4][4][4];
    gemm_v4_core(g_attnh, g_Wo, bm, bn, acc);

    const int wid  = threadIdx.x >> 5;
    const int lane = threadIdx.x & 31;
    const int warp_m = (wid >> 2) * 64;
    const int warp_n = (wid & 3) * 32;
    const int erow = lane >> 2;
    const int ecol = (lane & 3) * 2;

#pragma unroll
    for (int mi = 0; mi < 4; mi++)
#pragma unroll
        for (int nt = 0; nt < 2; nt++)
#pragma unroll
            for (int nj = 0; nj < 2; nj++) {
                float* cc = acc[mi][nt * 2 + nj];
                int m = bm + warp_m + mi * 16 + erow;
                int n = bn + warp_n + nt * 16 + nj * 8 + ecol;
                float2 v0 = make_float2(cc[0] + bo[n], cc[1] + bo[n + 1]);
                float2 v1 = make_float2(cc[2] + bo[n], cc[3] + bo[n + 1]);
                *(float2*)(out + (size_t)m * D_MODEL + n)       = v0;
                *(float2*)(out + (size_t)(m + 8) * D_MODEL + n) = v1;
            }
}

// -------- tensor-core causal flash attention (exp2 domain, Q split) ----------
#define AROW   72
#define A_ARR  (64 * AROW * 2)            // 9216
#define AQ_ARR (128 * AROW * 2)           // 18432
#define SQ_HI  0
#define SQ_LO  AQ_ARR
#define STG0   (2 * AQ_ARR)               // 36864
#define ASTG_B (2 * A_ARR)                // 18432 (Kh, Vh)
#define A_SMEM (2 * AQ_ARR + 2 * ASTG_B)  // 73728

__global__ __launch_bounds__(256, 2)
void attn_mma_kernel()
{
    extern __shared__ char smem[];
    const uint32_t sb = smem_u32(smem);
    const int tid  = threadIdx.x;
    const int wid  = tid >> 5;
    const int lane = tid & 31;
    const int qb = (int)gridDim.x - 1 - (int)blockIdx.x;
    const int bh = blockIdx.y;
    const int b  = bh >> 4;
    const int h  = bh & 15;
    const int q0 = qb * 128;

    const size_t qgbase = (size_t)(b * S_LEN + q0) * D_MODEL + h * DK;
    const size_t kgbase = (size_t)(b * S_LEN) * D_MODEL + h * DK;

    auto issue_tile = [&](int stg, int kt) {
        const uint32_t sbase = sb + STG0 + stg * ASTG_B;
        const size_t g0 = kgbase + (size_t)(kt * 64) * D_MODEL;
#pragma unroll
        for (int it = 0; it < 2; it++) {
            int slot = tid + it * 256;
            int r  = slot >> 3;
            int c8 = (slot & 7) * 8;
            uint32_t soff = (uint32_t)(r * AROW + c8) * 2;
            const size_t go = g0 + (size_t)r * D_MODEL + c8;
            CP16(sbase + soff,         (const char*)(g_Kh + go));
            CP16(sbase + A_ARR + soff, (const char*)(g_Vh + go));
        }
    };

    issue_tile(0, 0);
    CP_COMMIT();

#pragma unroll
    for (int it = 0; it < 4; it++) {
        int slot = tid + it * 256;
        int r  = slot >> 3;
        int c8 = (slot & 7) * 8;
        uint32_t soff = (uint32_t)(r * AROW + c8) * 2;
        const size_t go = qgbase + (size_t)r * D_MODEL + c8;
        *(uint4*)(smem + SQ_HI + soff) = *(const uint4*)(g_Qhi + go);
        *(uint4*)(smem + SQ_LO + soff) = *(const uint4*)(g_Qlo + go);
    }
    __syncthreads();

    float oacc[8][4];
#pragma unroll
    for (int nt = 0; nt < 8; nt++)
#pragma unroll
        for (int j = 0; j < 4; j++) oacc[nt][j] = 0.f;
    float m0 = -1e30f, m1 = -1e30f, l0 = 0.f, l1 = 0.f;

    const int row_lo   = q0 + wid * 16 + (lane >> 2);
    const int wrow_min = q0 + wid * 16;
    const int ntiles = 2 * qb + 2;

    const uint32_t qBase = sb + SQ_HI +
        (uint32_t)((wid * 16 + (lane & 15)) * AROW + ((lane >> 4) << 3)) * 2;

    for (int kt = 0; kt < ntiles; kt++) {
        if (kt + 1 < ntiles) { issue_tile((kt + 1) & 1, kt + 1); CP_COMMIT(); CP_WAIT1(); }
        else                 { CP_WAIT0(); }
        __syncthreads();

        const uint32_t st = sb + STG0 + (kt & 1) * ASTG_B;

        float sc[8][4];
#pragma unroll
        for (int nt = 0; nt < 8; nt++)
#pragma unroll
            for (int j = 0; j < 4; j++) sc[nt][j] = 0.f;

        // S(log2) = (Qhi + Qlo) @ Kh^T
#pragma unroll
        for (int t = 0; t < 4; t++) {
            uint32_t qh4[4], ql4[4];
            ldsm_x4(qh4, qBase + (uint32_t)(t * 16) * 2);
            ldsm_x4(ql4, qBase + AQ_ARR + (uint32_t)(t * 16) * 2);
#pragma unroll
            for (int g = 0; g < 4; g++) {
                uint32_t addr = st +
                    (uint32_t)((g * 16 + (lane & 15)) * AROW + t * 16 + ((lane >> 4) << 3)) * 2;
                uint32_t kh4[4];
                ldsm_x4(kh4, addr);
                mma_f16(sc[2 * g],     qh4, kh4[0], kh4[2]);
                mma_f16(sc[2 * g],     ql4, kh4[0], kh4[2]);
                mma_f16(sc[2 * g + 1], qh4, kh4[1], kh4[3]);
                mma_f16(sc[2 * g + 1], ql4, kh4[1], kh4[3]);
            }
        }

        if (kt * 64 + 63 > wrow_min) {
#pragma unroll
            for (int nt = 0; nt < 8; nt++) {
                int col = kt * 64 + nt * 8 + (lane & 3) * 2;
                if (col     > row_lo)     sc[nt][0] = -1e30f;
                if (col + 1 > row_lo)     sc[nt][1] = -1e30f;
                if (col     > row_lo + 8) sc[nt][2] = -1e30f;
                if (col + 1 > row_lo + 8) sc[nt][3] = -1e30f;
            }
        }

        float mx0 = -1e30f, mx1 = -1e30f;
#pragma unroll
        for (int nt = 0; nt < 8; nt++) {
            mx0 = fmaxf(mx0, fmaxf(sc[nt][0], sc[nt][1]));
            mx1 = fmaxf(mx1, fmaxf(sc[nt][2], sc[nt][3]));
        }
        mx0 = fmaxf(mx0, __shfl_xor_sync(0xffffffffu, mx0, 1));
        mx0 = fmaxf(mx0, __shfl_xor_sync(0xffffffffu, mx0, 2));
        mx1 = fmaxf(mx1, __shfl_xor_sync(0xffffffffu, mx1, 1));
        mx1 = fmaxf(mx1, __shfl_xor_sync(0xffffffffu, mx1, 2));

        float mn0 = fmaxf(m0, mx0);
        float mn1 = fmaxf(m1, mx1);
        float corr0 = ex2f(m0 - mn0);
        float corr1 = ex2f(m1 - mn1);
        m0 = mn0; m1 = mn1;

        float sum0 = 0.f, sum1 = 0.f;
#pragma unroll
        for (int nt = 0; nt < 8; nt++) {
            sc[nt][0] = ex2f(sc[nt][0] - mn0);
            sc[nt][1] = ex2f(sc[nt][1] - mn0);
            sc[nt][2] = ex2f(sc[nt][2] - mn1);
            sc[nt][3] = ex2f(sc[nt][3] - mn1);
            sum0 += sc[nt][0] + sc[nt][1];
            sum1 += sc[nt][2] + sc[nt][3];
        }
        sum0 += __shfl_xor_sync(0xffffffffu, sum0, 1);
        sum0 += __shfl_xor_sync(0xffffffffu, sum0, 2);
        sum1 += __shfl_xor_sync(0xffffffffu, sum1, 1);
        sum1 += __shfl_xor_sync(0xffffffffu, sum1, 2);
        l0 = l0 * corr0 + sum0;
        l1 = l1 * corr1 + sum1;

#pragma unroll
        for (int nt = 0; nt < 8; nt++) {
            oacc[nt][0] *= corr0; oacc[nt][1] *= corr0;
            oacc[nt][2] *= corr1; oacc[nt][3] *= corr1;
        }

        uint32_t ph[4][4];
#pragma unroll
        for (int t = 0; t < 4; t++) {
            ph[t][0] = pack2h(sc[2 * t][0],     sc[2 * t][1]);
            ph[t][1] = pack2h(sc[2 * t][2],     sc[2 * t][3]);
            ph[t][2] = pack2h(sc[2 * t + 1][0], sc[2 * t + 1][1]);
            ph[t][3] = pack2h(sc[2 * t + 1][2], sc[2 * t + 1][3]);
        }

        // O += P @ Vh
#pragma unroll
        for (int t = 0; t < 4; t++) {
#pragma unroll
            for (int g = 0; g < 4; g++) {
                uint32_t addr = st + A_ARR +
                    (uint32_t)((t * 16 + (lane & 7) + ((lane >> 3) & 1) * 8) * AROW +
                               g * 16 + ((lane >> 4) << 3)) * 2;
                uint32_t vh4[4];
                ldsm_x4t(vh4, addr);
                mma_f16(oacc[2 * g],     ph[t], vh4[0], vh4[1]);
                mma_f16(oacc[2 * g + 1], ph[t], vh4[2], vh4[3]);
            }
        }
        __syncthreads();
    }

    // ---- epilogue: normalize + single fp16 to global (for out-proj) ----
    float inv0 = 1.0f / l0;
    float inv1 = 1.0f / l1;
    size_t base0 = (size_t)(b * S_LEN + row_lo) * D_MODEL + h * DK;
    size_t base1 = base0 + (size_t)8 * D_MODEL;
#pragma unroll
    for (int nt = 0; nt < 8; nt++) {
        int col = nt * 8 + (lane & 3) * 2;
        *(uint32_t*)(g_attnh + base0 + col) = pack2h(oacc[nt][0] * inv0, oacc[nt][1] * inv0);
        *(uint32_t*)(g_attnh + base1 + col) = pack2h(oacc[nt][2] * inv1, oacc[nt][3] * inv1);
    }
}

// ---------------- launch ------------------------------------------------------
extern "C" void kernel_launch(void* const* d_in, const int* in_sizes, int n_in,
                              void* d_out, int out_size)
{
    const float* x  = (const float*)d_in[0];
    const float* Wq = (const float*)d_in[1];
    const float* bq = (const float*)d_in[2];
    const float* Wk = (const float*)d_in[3];
    const float* bk = (const float*)d_in[4];
    const float* Wv = (const float*)d_in[5];
    const float* bv = (const float*)d_in[6];
    const float* Wo = (const float*)d_in[7];
    const float* bo = (const float*)d_in[8];
    float* out = (float*)d_out;

    static int configured = 0;
    if (!configured) {
        cudaFuncSetAttribute(tc_qkv_v4, cudaFuncAttributeMaxDynamicSharedMemorySize, GSMEM_TOTAL);
        cudaFuncSetAttribute(tc_out_v4, cudaFuncAttributeMaxDynamicSharedMemorySize, GSMEM_TOTAL);
        cudaFuncSetAttribute(attn_mma_kernel, cudaFuncAttributeMaxDynamicSharedMemorySize, A_SMEM);
        configured = 1;
    }

    // 0) rope table + fp16 casts of x and weights
    rope_table_kernel<<<(S_LEN * 32 + 255) / 256, 256>>>();
    split_all<<<(2 * 1024 * 1024) / 256, 256>>>(x, Wq, Wk, Wv, Wo);

    // 1) QKV projections (single-product fp16) + fused RoPE/scale epilogue
    dim3 g_qkv(D_MODEL / 128, M_TOT / 128, 3);
    tc_qkv_v4<<<g_qkv, 256, GSMEM_TOTAL>>>(bq, bk, bv);

    // 2) causal attention (exp2 domain, Q split, K/V/P plain fp16)
    dim3 g_att(S_LEN / 128, BATCH * NHEAD);
    attn_mma_kernel<<<g_att, 256, A_SMEM>>>();

    // 3) output projection (single-product fp16)
    dim3 g_out(D_MODEL / 128, M_TOT / 128);
    tc_out_v4<<<g_out, 256, GSMEM_TOTAL>>>(bo, out);
}

// round 11
// speedup vs baseline: 6.4534x; 1.0190x over previous
#include <cuda_runtime.h>
#include <cuda_bf16.h>
#include <cuda_fp16.h>
#include <math.h>
#include <stdint.h>

#define D_MODEL 1024
#define S_LEN   2048
#define BATCH   2
#define NHEAD   16
#define DK      64
#define M_TOT   (BATCH * S_LEN)   // 4096
#define QSCALE  0.1803368801111244f   // (1/8) * log2(e)

// ---------------- scratch (device globals; no allocations allowed) ----------
__device__ __half g_Xh[M_TOT * D_MODEL];
__device__ __half g_Wq[D_MODEL * D_MODEL];
__device__ __half g_Wk[D_MODEL * D_MODEL];
__device__ __half g_Wv[D_MODEL * D_MODEL];
__device__ __half g_Wo[D_MODEL * D_MODEL];
__device__ __half g_Qhi[M_TOT * D_MODEL];
__device__ __half g_Qlo[M_TOT * D_MODEL];
__device__ __half g_Kh [M_TOT * D_MODEL];
__device__ __half g_Vh [M_TOT * D_MODEL];
__device__ __half g_attnh[M_TOT * D_MODEL];
__device__ float g_cos[S_LEN * 32];
__device__ float g_sin[S_LEN * 32];

// ---------------- common helpers --------------------------------------------
__device__ __forceinline__ uint32_t smem_u32(const void* p) {
    uint32_t a;
    asm("{ .reg .u64 t; cvta.to.shared.u64 t, %1; cvt.u32.u64 %0, t; }" : "=r"(a) : "l"(p));
    return a;
}

__device__ __forceinline__ float ex2f(float x) {
    float y;
    asm("ex2.approx.f32 %0, %1;" : "=f"(y) : "f"(x));
    return y;
}

__device__ __forceinline__ void ldsm_x4(uint32_t* r, uint32_t addr) {
    asm volatile("ldmatrix.sync.aligned.m8n8.x4.shared.b16 {%0,%1,%2,%3}, [%4];"
                 : "=r"(r[0]), "=r"(r[1]), "=r"(r[2]), "=r"(r[3]) : "r"(addr));
}

__device__ __forceinline__ void ldsm_x4t(uint32_t* r, uint32_t addr) {
    asm volatile("ldmatrix.sync.aligned.m8n8.x4.trans.shared.b16 {%0,%1,%2,%3}, [%4];"
                 : "=r"(r[0]), "=r"(r[1]), "=r"(r[2]), "=r"(r[3]) : "r"(addr));
}

__device__ __forceinline__ void mma_f16(float* c, const uint32_t* a,
                                        uint32_t b0, uint32_t b1) {
    asm volatile("mma.sync.aligned.m16n8k16.row.col.f32.f16.f16.f32 "
                 "{%0,%1,%2,%3}, {%4,%5,%6,%7}, {%8,%9}, {%0,%1,%2,%3};"
                 : "+f"(c[0]), "+f"(c[1]), "+f"(c[2]), "+f"(c[3])
                 : "r"(a[0]), "r"(a[1]), "r"(a[2]), "r"(a[3]), "r"(b0), "r"(b1));
}

__device__ __forceinline__ uint32_t pack2h_hi(float a, float b, float& ra, float& rb) {
    __half ha = __float2half_rn(a);
    __half hb = __float2half_rn(b);
    ra = a - __half2float(ha);
    rb = b - __half2float(hb);
    union { __half2 h; uint32_t u; } c;
    c.h = __halves2half2(ha, hb);
    return c.u;
}

__device__ __forceinline__ uint32_t pack2h(float a, float b) {
    union { __half2 h; uint32_t u; } c;
    c.h = __halves2half2(__float2half_rn(a), __float2half_rn(b));
    return c.u;
}

#define CP16(saddr, gptr) \
    asm volatile("cp.async.cg.shared.global [%0], [%1], 16;" :: "r"(saddr), "l"(gptr))
#define CP_COMMIT() asm volatile("cp.async.commit_group;" ::: "memory")
#define CP_WAIT0()  asm volatile("cp.async.wait_group 0;" ::: "memory")
#define CP_WAIT1()  asm volatile("cp.async.wait_group 1;" ::: "memory")

// ---------------- fused rope table + fp16 casts ------------------------------
__global__ void split_all(const float* __restrict__ x,  const float* __restrict__ Wq,
                          const float* __restrict__ Wk, const float* __restrict__ Wv,
                          const float* __restrict__ Wo)
{
    int t = blockIdx.x * blockDim.x + threadIdx.x;   // 0..2M-1
    if (t < S_LEN * 32) {
        int s = t >> 5, i = t & 31;
        float inv_freq = __expf(-(float)(2 * i) * (9.210340371976184f / 64.0f));
        float ang = (float)s * inv_freq;
        g_cos[t] = cosf(ang);
        g_sin[t] = sinf(ang);
    }
    const float* src;
    __half* dst;
    size_t off;
    if (t < (1 << 20)) { src = x; dst = g_Xh; off = t; }
    else {
        int r = t - (1 << 20);
        int w = r >> 18;
        off = (size_t)(r & ((1 << 18) - 1));
        if      (w == 0) { src = Wq; dst = g_Wq; }
        else if (w == 1) { src = Wk; dst = g_Wk; }
        else if (w == 2) { src = Wv; dst = g_Wv; }
        else             { src = Wo; dst = g_Wo; }
    }
    float4 v = ((const float4*)src)[off];
    uint2 o;
    o.x = pack2h(v.x, v.y);
    o.y = pack2h(v.z, v.w);
    ((uint2*)dst)[off] = o;
}

// ========== fp16 single-product GEMM (BK=64, 3-stage cp.async ring) ==========
#define GBK 64
#define GCHUNKS (D_MODEL / GBK)           // 16
#define GROWH  72                         // 144B row stride, conflict-free
#define GARR_B (128 * GROWH * 2)          // 18432
#define GSTG_B (2 * GARR_B)               // 36864 (A, B)
#define GSMEM_TOTAL (3 * GSTG_B)          // 110592

__device__ __forceinline__ void gemm_v5_core(
    const __half* __restrict__ A, const __half* __restrict__ B,
    int bm, int bn, float (&acc)[4][4][4])
{
    extern __shared__ char smem[];
    const uint32_t sb = smem_u32(smem);
    const int tid  = threadIdx.x;
    const int wid  = tid >> 5;
    const int lane = tid & 31;
    const int warp_m = (wid >> 2) * 64;
    const int warp_n = (wid & 3) * 32;

#pragma unroll
    for (int i = 0; i < 4; i++)
#pragma unroll
        for (int j = 0; j < 4; j++)
#pragma unroll
            for (int k = 0; k < 4; k++) acc[i][j][k] = 0.f;

    auto issue = [&](int stg, int c) {
        const uint32_t st = sb + stg * GSTG_B;
        const int k0 = c * GBK;
#pragma unroll
        for (int it = 0; it < 4; it++) {
            int slot = tid + it * 256;            // 0..1023
            int r  = slot >> 3;                   // 0..127
            int c8 = (slot & 7) * 8;              // halves
            uint32_t soff = (uint32_t)(r * GROWH + c8) * 2;
            size_t ga = (size_t)(bm + r) * D_MODEL + k0 + c8;
            size_t gb = (size_t)(bn + r) * D_MODEL + k0 + c8;
            CP16(st + soff,          (const char*)(A + ga));
            CP16(st + GARR_B + soff, (const char*)(B + gb));
        }
    };

    issue(0, 0);
    CP_COMMIT();
    issue(1, 1);
    CP_COMMIT();

    const int qrow = lane & 15;
    const int qcol = (lane >> 4) << 3;

    for (int c = 0; c < GCHUNKS; c++) {
        if (c + 1 < GCHUNKS) CP_WAIT1(); else CP_WAIT0();
        __syncthreads();
        if (c + 2 < GCHUNKS) { issue((c + 2) % 3, c + 2); CP_COMMIT(); }

        const uint32_t st = sb + (c % 3) * GSTG_B;
        const uint32_t aBase = st + (uint32_t)((warp_m + qrow) * GROWH + qcol) * 2;
        const uint32_t bBase = st + GARR_B + (uint32_t)((warp_n + qrow) * GROWH + qcol) * 2;

#pragma unroll
        for (int ks = 0; ks < 4; ks++) {
            const uint32_t ko = (uint32_t)(ks * 16) * 2;
            uint32_t bf[2][4];
#pragma unroll
            for (int nt = 0; nt < 2; nt++)
                ldsm_x4(bf[nt], bBase + nt * (16 * GROWH * 2) + ko);
#pragma unroll
            for (int mi = 0; mi < 4; mi++) {
                uint32_t af[4];
                ldsm_x4(af, aBase + mi * (16 * GROWH * 2) + ko);
#pragma unroll
                for (int nt = 0; nt < 2; nt++)
#pragma unroll
                    for (int nj = 0; nj < 2; nj++)
                        mma_f16(acc[mi][nt * 2 + nj], af, bf[nt][nj], bf[nt][nj + 2]);
            }
        }
    }
}

// QKV GEMM: fused bias + RoPE; Q -> fp16 hi/lo (log2e-scaled), K/V -> fp16
__global__ __launch_bounds__(256, 2)
void tc_qkv_v5(const float* __restrict__ bq, const float* __restrict__ bk,
               const float* __restrict__ bv)
{
    const int z = blockIdx.z;
    const __half* W;
    const float* bias;
    if (z == 0)      { W = g_Wq; bias = bq; }
    else if (z == 1) { W = g_Wk; bias = bk; }
    else             { W = g_Wv; bias = bv; }

    const int bm = blockIdx.y * 128;
    const int bn = blockIdx.x * 128;
    float acc[4][4][4];
    gemm_v5_core(g_Xh, W, bm, bn, acc);

    const int wid  = threadIdx.x >> 5;
    const int lane = threadIdx.x & 31;
    const int warp_m = (wid >> 2) * 64;
    const int warp_n = (wid & 3) * 32;
    const int erow = lane >> 2;
    const int ecol = (lane & 3) * 2;

#pragma unroll
    for (int mi = 0; mi < 4; mi++)
#pragma unroll
        for (int nt = 0; nt < 2; nt++)
#pragma unroll
            for (int nj = 0; nj < 2; nj++) {
                float* cc = acc[mi][nt * 2 + nj];
                int m = bm + warp_m + mi * 16 + erow;
                int n = bn + warp_n + nt * 16 + nj * 8 + ecol;
                float v0 = cc[0] + bias[n], v1 = cc[1] + bias[n + 1];
                float w0 = cc[2] + bias[n], w1 = cc[3] + bias[n + 1];
                if (z < 2) {
                    int i  = (n & 63) >> 1;
                    int s0 = (m & 2047) * 32 + i;
                    int s1 = ((m + 8) & 2047) * 32 + i;
                    float cs0 = g_cos[s0], sn0 = g_sin[s0];
                    float cs1 = g_cos[s1], sn1 = g_sin[s1];
                    float t0 = v0 * cs0 - v1 * sn0, t1 = v0 * sn0 + v1 * cs0;
                    float u0 = w0 * cs1 - w1 * sn1, u1 = w0 * sn1 + w1 * cs1;
                    if (z == 0) { t0 *= QSCALE; t1 *= QSCALE; u0 *= QSCALE; u1 *= QSCALE; }
                    v0 = t0; v1 = t1; w0 = u0; w1 = u1;
                }
                size_t o0 = (size_t)m * D_MODEL + n;
                size_t o1 = (size_t)(m + 8) * D_MODEL + n;
                if (z == 0) {
                    float r0, r1;
                    uint32_t h0 = pack2h_hi(v0, v1, r0, r1);
                    uint32_t l0v = pack2h(r0, r1);
                    uint32_t h1 = pack2h_hi(w0, w1, r0, r1);
                    uint32_t l1v = pack2h(r0, r1);
                    *(uint32_t*)(g_Qhi + o0) = h0;
                    *(uint32_t*)(g_Qlo + o0) = l0v;
                    *(uint32_t*)(g_Qhi + o1) = h1;
                    *(uint32_t*)(g_Qlo + o1) = l1v;
                } else {
                    __half* D = (z == 1) ? g_Kh : g_Vh;
                    *(uint32_t*)(D + o0) = pack2h(v0, v1);
                    *(uint32_t*)(D + o1) = pack2h(w0, w1);
                }
            }
}

__global__ __launch_bounds__(256, 2)
void tc_out_v5(const float* __restrict__ bo, float* __restrict__ out)
{
    const int bm = blockIdx.y * 128;
    const int bn = blockIdx.x * 128;
    float acc[4][4][4];
    gemm_v5_core(g_attnh, g_Wo, bm, bn, acc);

    const int wid  = threadIdx.x >> 5;
    const int lane = threadIdx.x & 31;
    const int warp_m = (wid >> 2) * 64;
    const int warp_n = (wid & 3) * 32;
    const int erow = lane >> 2;
    const int ecol = (lane & 3) * 2;

#pragma unroll
    for (int mi = 0; mi < 4; mi++)
#pragma unroll
        for (int nt = 0; nt < 2; nt++)
#pragma unroll
            for (int nj = 0; nj < 2; nj++) {
                float* cc = acc[mi][nt * 2 + nj];
                int m = bm + warp_m + mi * 16 + erow;
                int n = bn + warp_n + nt * 16 + nj * 8 + ecol;
                float2 v0 = make_float2(cc[0] + bo[n], cc[1] + bo[n + 1]);
                float2 v1 = make_float2(cc[2] + bo[n], cc[3] + bo[n + 1]);
                *(float2*)(out + (size_t)m * D_MODEL + n)       = v0;
                *(float2*)(out + (size_t)(m + 8) * D_MODEL + n) = v1;
            }
}

// ---- tensor-core causal flash attention (3-stage ring, masked-tile skip) ----
#define AROW   72
#define A_ARR  (64 * AROW * 2)            // 9216
#define AQ_ARR (128 * AROW * 2)           // 18432
#define SQ_HI  0
#define SQ_LO  AQ_ARR
#define STG0   (2 * AQ_ARR)               // 36864
#define ASTG_B (2 * A_ARR)                // 18432 (Kh, Vh)
#define A_SMEM (2 * AQ_ARR + 3 * ASTG_B)  // 92160

__global__ __launch_bounds__(256, 2)
void attn_mma_kernel()
{
    extern __shared__ char smem[];
    const uint32_t sb = smem_u32(smem);
    const int tid  = threadIdx.x;
    const int wid  = tid >> 5;
    const int lane = tid & 31;
    const int qb = (int)gridDim.x - 1 - (int)blockIdx.x;
    const int bh = blockIdx.y;
    const int b  = bh >> 4;
    const int h  = bh & 15;
    const int q0 = qb * 128;

    const size_t qgbase = (size_t)(b * S_LEN + q0) * D_MODEL + h * DK;
    const size_t kgbase = (size_t)(b * S_LEN) * D_MODEL + h * DK;

    auto issue_tile = [&](int stg, int kt) {
        const uint32_t sbase = sb + STG0 + stg * ASTG_B;
        const size_t g0 = kgbase + (size_t)(kt * 64) * D_MODEL;
#pragma unroll
        for (int it = 0; it < 2; it++) {
            int slot = tid + it * 256;
            int r  = slot >> 3;
            int c8 = (slot & 7) * 8;
            uint32_t soff = (uint32_t)(r * AROW + c8) * 2;
            const size_t go = g0 + (size_t)r * D_MODEL + c8;
            CP16(sbase + soff,         (const char*)(g_Kh + go));
            CP16(sbase + A_ARR + soff, (const char*)(g_Vh + go));
        }
    };

    const int ntiles = 2 * qb + 2;

    issue_tile(0, 0);
    CP_COMMIT();
    issue_tile(1, 1);
    CP_COMMIT();

    // load Q tile (128 rows) hi/lo
#pragma unroll
    for (int it = 0; it < 4; it++) {
        int slot = tid + it * 256;
        int r  = slot >> 3;
        int c8 = (slot & 7) * 8;
        uint32_t soff = (uint32_t)(r * AROW + c8) * 2;
        const size_t go = qgbase + (size_t)r * D_MODEL + c8;
        *(uint4*)(smem + SQ_HI + soff) = *(const uint4*)(g_Qhi + go);
        *(uint4*)(smem + SQ_LO + soff) = *(const uint4*)(g_Qlo + go);
    }

    float oacc[8][4];
#pragma unroll
    for (int nt = 0; nt < 8; nt++)
#pragma unroll
        for (int j = 0; j < 4; j++) oacc[nt][j] = 0.f;
    float m0 = -1e30f, m1 = -1e30f, l0 = 0.f, l1 = 0.f;

    const int row_lo   = q0 + wid * 16 + (lane >> 2);
    const int wrow_min = q0 + wid * 16;

    const uint32_t qBase = sb + SQ_HI +
        (uint32_t)((wid * 16 + (lane & 15)) * AROW + ((lane >> 4) << 3)) * 2;

    for (int kt = 0; kt < ntiles; kt++) {
        if (kt + 1 < ntiles) CP_WAIT1(); else CP_WAIT0();
        __syncthreads();
        if (kt + 2 < ntiles) { issue_tile((kt + 2) % 3, kt + 2); CP_COMMIT(); }

        // skip tiles entirely in this warp's causal future
        if (kt * 64 > wrow_min + 15) continue;

        const uint32_t st = sb + STG0 + (kt % 3) * ASTG_B;

        float sc[8][4];
#pragma unroll
        for (int nt = 0; nt < 8; nt++)
#pragma unroll
            for (int j = 0; j < 4; j++) sc[nt][j] = 0.f;

        // S(log2) = (Qhi + Qlo) @ Kh^T
#pragma unroll
        for (int t = 0; t < 4; t++) {
            uint32_t qh4[4], ql4[4];
            ldsm_x4(qh4, qBase + (uint32_t)(t * 16) * 2);
            ldsm_x4(ql4, qBase + AQ_ARR + (uint32_t)(t * 16) * 2);
#pragma unroll
            for (int g = 0; g < 4; g++) {
                uint32_t addr = st +
                    (uint32_t)((g * 16 + (lane & 15)) * AROW + t * 16 + ((lane >> 4) << 3)) * 2;
                uint32_t kh4[4];
                ldsm_x4(kh4, addr);
                mma_f16(sc[2 * g],     qh4, kh4[0], kh4[2]);
                mma_f16(sc[2 * g],     ql4, kh4[0], kh4[2]);
                mma_f16(sc[2 * g + 1], qh4, kh4[1], kh4[3]);
                mma_f16(sc[2 * g + 1], ql4, kh4[1], kh4[3]);
            }
        }

        if (kt * 64 + 63 > wrow_min) {
#pragma unroll
            for (int nt = 0; nt < 8; nt++) {
                int col = kt * 64 + nt * 8 + (lane & 3) * 2;
                if (col     > row_lo)     sc[nt][0] = -1e30f;
                if (col + 1 > row_lo)     sc[nt][1] = -1e30f;
                if (col     > row_lo + 8) sc[nt][2] = -1e30f;
                if (col + 1 > row_lo + 8) sc[nt][3] = -1e30f;
            }
        }

        float mx0 = -1e30f, mx1 = -1e30f;
#pragma unroll
        for (int nt = 0; nt < 8; nt++) {
            mx0 = fmaxf(mx0, fmaxf(sc[nt][0], sc[nt][1]));
            mx1 = fmaxf(mx1, fmaxf(sc[nt][2], sc[nt][3]));
        }
        mx0 = fmaxf(mx0, __shfl_xor_sync(0xffffffffu, mx0, 1));
        mx0 = fmaxf(mx0, __shfl_xor_sync(0xffffffffu, mx0, 2));
        mx1 = fmaxf(mx1, __shfl_xor_sync(0xffffffffu, mx1, 1));
        mx1 = fmaxf(mx1, __shfl_xor_sync(0xffffffffu, mx1, 2));

        float mn0 = fmaxf(m0, mx0);
        float mn1 = fmaxf(m1, mx1);
        float corr0 = ex2f(m0 - mn0);
        float corr1 = ex2f(m1 - mn1);
        m0 = mn0; m1 = mn1;

        float sum0 = 0.f, sum1 = 0.f;
#pragma unroll
        for (int nt = 0; nt < 8; nt++) {
            sc[nt][0] = ex2f(sc[nt][0] - mn0);
            sc[nt][1] = ex2f(sc[nt][1] - mn0);
            sc[nt][2] = ex2f(sc[nt][2] - mn1);
            sc[nt][3] = ex2f(sc[nt][3] - mn1);
            sum0 += sc[nt][0] + sc[nt][1];
            sum1 += sc[nt][2] + sc[nt][3];
        }
        sum0 += __shfl_xor_sync(0xffffffffu, sum0, 1);
        sum0 += __shfl_xor_sync(0xffffffffu, sum0, 2);
        sum1 += __shfl_xor_sync(0xffffffffu, sum1, 1);
        sum1 += __shfl_xor_sync(0xffffffffu, sum1, 2);
        l0 = l0 * corr0 + sum0;
        l1 = l1 * corr1 + sum1;

#pragma unroll
        for (int nt = 0; nt < 8; nt++) {
            oacc[nt][0] *= corr0; oacc[nt][1] *= corr0;
            oacc[nt][2] *= corr1; oacc[nt][3] *= corr1;
        }

        uint32_t ph[4][4];
#pragma unroll
        for (int t = 0; t < 4; t++) {
            ph[t][0] = pack2h(sc[2 * t][0],     sc[2 * t][1]);
            ph[t][1] = pack2h(sc[2 * t][2],     sc[2 * t][3]);
            ph[t][2] = pack2h(sc[2 * t + 1][0], sc[2 * t + 1][1]);
            ph[t][3] = pack2h(sc[2 * t + 1][2], sc[2 * t + 1][3]);
        }

        // O += P @ Vh
#pragma unroll
        for (int t = 0; t < 4; t++) {
#pragma unroll
            for (int g = 0; g < 4; g++) {
                uint32_t addr = st + A_ARR +
                    (uint32_t)((t * 16 + (lane & 7) + ((lane >> 3) & 1) * 8) * AROW +
                               g * 16 + ((lane >> 4) << 3)) * 2;
                uint32_t vh4[4];
                ldsm_x4t(vh4, addr);
                mma_f16(oacc[2 * g],     ph[t], vh4[0], vh4[1]);
                mma_f16(oacc[2 * g + 1], ph[t], vh4[2], vh4[3]);
            }
        }
    }

    // ---- epilogue: normalize + single fp16 to global (for out-proj) ----
    float inv0 = 1.0f / l0;
    float inv1 = 1.0f / l1;
    size_t base0 = (size_t)(b * S_LEN + row_lo) * D_MODEL + h * DK;
    size_t base1 = base0 + (size_t)8 * D_MODEL;
#pragma unroll
    for (int nt = 0; nt < 8; nt++) {
        int col = nt * 8 + (lane & 3) * 2;
        *(uint32_t*)(g_attnh + base0 + col) = pack2h(oacc[nt][0] * inv0, oacc[nt][1] * inv0);
        *(uint32_t*)(g_attnh + base1 + col) = pack2h(oacc[nt][2] * inv1, oacc[nt][3] * inv1);
    }
}

// ---------------- launch ------------------------------------------------------
extern "C" void kernel_launch(void* const* d_in, const int* in_sizes, int n_in,
                              void* d_out, int out_size)
{
    const float* x  = (const float*)d_in[0];
    const float* Wq = (const float*)d_in[1];
    const float* bq = (const float*)d_in[2];
    const float* Wk = (const float*)d_in[3];
    const float* bk = (const float*)d_in[4];
    const float* Wv = (const float*)d_in[5];
    const float* bv = (const float*)d_in[6];
    const float* Wo = (const float*)d_in[7];
    const float* bo = (const float*)d_in[8];
    float* out = (float*)d_out;

    static int configured = 0;
    if (!configured) {
        cudaFuncSetAttribute(tc_qkv_v5, cudaFuncAttributeMaxDynamicSharedMemorySize, GSMEM_TOTAL);
        cudaFuncSetAttribute(tc_out_v5, cudaFuncAttributeMaxDynamicSharedMemorySize, GSMEM_TOTAL);
        cudaFuncSetAttribute(attn_mma_kernel, cudaFuncAttributeMaxDynamicSharedMemorySize, A_SMEM);
        configured = 1;
    }

    // 0) fused rope table + fp16 casts of x and weights
    split_all<<<(2 * 1024 * 1024) / 256, 256>>>(x, Wq, Wk, Wv, Wo);

    // 1) QKV projections (single-product fp16, 3-stage ring) + RoPE epilogue
    dim3 g_qkv(D_MODEL / 128, M_TOT / 128, 3);
    tc_qkv_v5<<<g_qkv, 256, GSMEM_TOTAL>>>(bq, bk, bv);

    // 2) causal attention (exp2 domain, Q split, 3-stage ring, tile skip)
    dim3 g_att(S_LEN / 128, BATCH * NHEAD);
    attn_mma_kernel<<<g_att, 256, A_SMEM>>>();

    // 3) output projection (single-product fp16, 3-stage ring)
    dim3 g_out(D_MODEL / 128, M_TOT / 128);
    tc_out_v5<<<g_out, 256, GSMEM_TOTAL>>>(bo, out);
}

// round 12
// speedup vs baseline: 7.0759x; 1.0965x over previous
#include <cuda_runtime.h>
#include <cuda_bf16.h>
#include <cuda_fp16.h>
#include <math.h>
#include <stdint.h>

#define D_MODEL 1024
#define S_LEN   2048
#define BATCH   2
#define NHEAD   16
#define DK      64
#define M_TOT   (BATCH * S_LEN)   // 4096
#define QSCALE  0.1803368801111244f   // (1/8) * log2(e)

// ---------------- scratch (device globals; no allocations allowed) ----------
__device__ __half g_Xh[M_TOT * D_MODEL];
__device__ __half g_Wq[D_MODEL * D_MODEL];
__device__ __half g_Wk[D_MODEL * D_MODEL];
__device__ __half g_Wv[D_MODEL * D_MODEL];
__device__ __half g_Wo[D_MODEL * D_MODEL];
__device__ __half g_Qh [M_TOT * D_MODEL];
__device__ __half g_Kh [M_TOT * D_MODEL];
__device__ __half g_Vh [M_TOT * D_MODEL];
__device__ __half g_attnh[M_TOT * D_MODEL];
__device__ float g_cos[S_LEN * 32];
__device__ float g_sin[S_LEN * 32];

// ---------------- common helpers --------------------------------------------
__device__ __forceinline__ uint32_t smem_u32(const void* p) {
    uint32_t a;
    asm("{ .reg .u64 t; cvta.to.shared.u64 t, %1; cvt.u32.u64 %0, t; }" : "=r"(a) : "l"(p));
    return a;
}

__device__ __forceinline__ float ex2f(float x) {
    float y;
    asm("ex2.approx.f32 %0, %1;" : "=f"(y) : "f"(x));
    return y;
}

__device__ __forceinline__ void ldsm_x4(uint32_t* r, uint32_t addr) {
    asm volatile("ldmatrix.sync.aligned.m8n8.x4.shared.b16 {%0,%1,%2,%3}, [%4];"
                 : "=r"(r[0]), "=r"(r[1]), "=r"(r[2]), "=r"(r[3]) : "r"(addr));
}

__device__ __forceinline__ void ldsm_x4t(uint32_t* r, uint32_t addr) {
    asm volatile("ldmatrix.sync.aligned.m8n8.x4.trans.shared.b16 {%0,%1,%2,%3}, [%4];"
                 : "=r"(r[0]), "=r"(r[1]), "=r"(r[2]), "=r"(r[3]) : "r"(addr));
}

__device__ __forceinline__ void mma_f16(float* c, const uint32_t* a,
                                        uint32_t b0, uint32_t b1) {
    asm volatile("mma.sync.aligned.m16n8k16.row.col.f32.f16.f16.f32 "
                 "{%0,%1,%2,%3}, {%4,%5,%6,%7}, {%8,%9}, {%0,%1,%2,%3};"
                 : "+f"(c[0]), "+f"(c[1]), "+f"(c[2]), "+f"(c[3])
                 : "r"(a[0]), "r"(a[1]), "r"(a[2]), "r"(a[3]), "r"(b0), "r"(b1));
}

__device__ __forceinline__ uint32_t pack2h(float a, float b) {
    union { __half2 h; uint32_t u; } c;
    c.h = __halves2half2(__float2half_rn(a), __float2half_rn(b));
    return c.u;
}

#define CP16(saddr, gptr) \
    asm volatile("cp.async.cg.shared.global [%0], [%1], 16;" :: "r"(saddr), "l"(gptr))
#define CP_COMMIT() asm volatile("cp.async.commit_group;" ::: "memory")
#define CP_WAIT0()  asm volatile("cp.async.wait_group 0;" ::: "memory")
#define CP_WAIT1()  asm volatile("cp.async.wait_group 1;" ::: "memory")

// ---------------- fused rope table + fp16 casts ------------------------------
__global__ void split_all(const float* __restrict__ x,  const float* __restrict__ Wq,
                          const float* __restrict__ Wk, const float* __restrict__ Wv,
                          const float* __restrict__ Wo)
{
    int t = blockIdx.x * blockDim.x + threadIdx.x;   // 0..2M-1
    if (t < S_LEN * 32) {
        int s = t >> 5, i = t & 31;
        float inv_freq = __expf(-(float)(2 * i) * (9.210340371976184f / 64.0f));
        float ang = (float)s * inv_freq;
        g_cos[t] = cosf(ang);
        g_sin[t] = sinf(ang);
    }
    const float* src;
    __half* dst;
    size_t off;
    if (t < (1 << 20)) { src = x; dst = g_Xh; off = t; }
    else {
        int r = t - (1 << 20);
        int w = r >> 18;
        off = (size_t)(r & ((1 << 18) - 1));
        if      (w == 0) { src = Wq; dst = g_Wq; }
        else if (w == 1) { src = Wk; dst = g_Wk; }
        else if (w == 2) { src = Wv; dst = g_Wv; }
        else             { src = Wo; dst = g_Wo; }
    }
    float4 v = ((const float4*)src)[off];
    uint2 o;
    o.x = pack2h(v.x, v.y);
    o.y = pack2h(v.z, v.w);
    ((uint2*)dst)[off] = o;
}

// ========== fp16 single-product GEMM (BK=64, 3-stage cp.async ring) ==========
#define GBK 64
#define GCHUNKS (D_MODEL / GBK)           // 16
#define GROWH  72                         // 144B row stride, conflict-free
#define GARR_B (128 * GROWH * 2)          // 18432
#define GSTG_B (2 * GARR_B)               // 36864 (A, B)
#define GSMEM_TOTAL (3 * GSTG_B)          // 110592

__device__ __forceinline__ void gemm_v5_core(
    const __half* __restrict__ A, const __half* __restrict__ B,
    int bm, int bn, float (&acc)[4][4][4])
{
    extern __shared__ char smem[];
    const uint32_t sb = smem_u32(smem);
    const int tid  = threadIdx.x;
    const int wid  = tid >> 5;
    const int lane = tid & 31;
    const int warp_m = (wid >> 2) * 64;
    const int warp_n = (wid & 3) * 32;

#pragma unroll
    for (int i = 0; i < 4; i++)
#pragma unroll
        for (int j = 0; j < 4; j++)
#pragma unroll
            for (int k = 0; k < 4; k++) acc[i][j][k] = 0.f;

    auto issue = [&](int stg, int c) {
        const uint32_t st = sb + stg * GSTG_B;
        const int k0 = c * GBK;
#pragma unroll
        for (int it = 0; it < 4; it++) {
            int slot = tid + it * 256;            // 0..1023
            int r  = slot >> 3;                   // 0..127
            int c8 = (slot & 7) * 8;              // halves
            uint32_t soff = (uint32_t)(r * GROWH + c8) * 2;
            size_t ga = (size_t)(bm + r) * D_MODEL + k0 + c8;
            size_t gb = (size_t)(bn + r) * D_MODEL + k0 + c8;
            CP16(st + soff,          (const char*)(A + ga));
            CP16(st + GARR_B + soff, (const char*)(B + gb));
        }
    };

    issue(0, 0);
    CP_COMMIT();
    issue(1, 1);
    CP_COMMIT();

    const int qrow = lane & 15;
    const int qcol = (lane >> 4) << 3;

    for (int c = 0; c < GCHUNKS; c++) {
        if (c + 1 < GCHUNKS) CP_WAIT1(); else CP_WAIT0();
        __syncthreads();
        if (c + 2 < GCHUNKS) { issue((c + 2) % 3, c + 2); CP_COMMIT(); }

        const uint32_t st = sb + (c % 3) * GSTG_B;
        const uint32_t aBase = st + (uint32_t)((warp_m + qrow) * GROWH + qcol) * 2;
        const uint32_t bBase = st + GARR_B + (uint32_t)((warp_n + qrow) * GROWH + qcol) * 2;

#pragma unroll
        for (int ks = 0; ks < 4; ks++) {
            const uint32_t ko = (uint32_t)(ks * 16) * 2;
            uint32_t bf[2][4];
#pragma unroll
            for (int nt = 0; nt < 2; nt++)
                ldsm_x4(bf[nt], bBase + nt * (16 * GROWH * 2) + ko);
#pragma unroll
            for (int mi = 0; mi < 4; mi++) {
                uint32_t af[4];
                ldsm_x4(af, aBase + mi * (16 * GROWH * 2) + ko);
#pragma unroll
                for (int nt = 0; nt < 2; nt++)
#pragma unroll
                    for (int nj = 0; nj < 2; nj++)
                        mma_f16(acc[mi][nt * 2 + nj], af, bf[nt][nj], bf[nt][nj + 2]);
            }
        }
    }
}

// QKV GEMM: fused bias + RoPE; Q (log2e-scaled), K, V -> plain fp16
__global__ __launch_bounds__(256, 2)
void tc_qkv_v6(const float* __restrict__ bq, const float* __restrict__ bk,
               const float* __restrict__ bv)
{
    const int z = blockIdx.z;
    const __half* W;
    const float* bias;
    __half* D;
    if (z == 0)      { W = g_Wq; bias = bq; D = g_Qh; }
    else if (z == 1) { W = g_Wk; bias = bk; D = g_Kh; }
    else             { W = g_Wv; bias = bv; D = g_Vh; }

    const int bm = blockIdx.y * 128;
    const int bn = blockIdx.x * 128;
    float acc[4][4][4];
    gemm_v5_core(g_Xh, W, bm, bn, acc);

    const int wid  = threadIdx.x >> 5;
    const int lane = threadIdx.x & 31;
    const int warp_m = (wid >> 2) * 64;
    const int warp_n = (wid & 3) * 32;
    const int erow = lane >> 2;
    const int ecol = (lane & 3) * 2;

#pragma unroll
    for (int mi = 0; mi < 4; mi++)
#pragma unroll
        for (int nt = 0; nt < 2; nt++)
#pragma unroll
            for (int nj = 0; nj < 2; nj++) {
                float* cc = acc[mi][nt * 2 + nj];
                int m = bm + warp_m + mi * 16 + erow;
                int n = bn + warp_n + nt * 16 + nj * 8 + ecol;
                float v0 = cc[0] + bias[n], v1 = cc[1] + bias[n + 1];
                float w0 = cc[2] + bias[n], w1 = cc[3] + bias[n + 1];
                if (z < 2) {
                    int i  = (n & 63) >> 1;
                    int s0 = (m & 2047) * 32 + i;
                    int s1 = ((m + 8) & 2047) * 32 + i;
                    float cs0 = g_cos[s0], sn0 = g_sin[s0];
                    float cs1 = g_cos[s1], sn1 = g_sin[s1];
                    float t0 = v0 * cs0 - v1 * sn0, t1 = v0 * sn0 + v1 * cs0;
                    float u0 = w0 * cs1 - w1 * sn1, u1 = w0 * sn1 + w1 * cs1;
                    if (z == 0) { t0 *= QSCALE; t1 *= QSCALE; u0 *= QSCALE; u1 *= QSCALE; }
                    v0 = t0; v1 = t1; w0 = u0; w1 = u1;
                }
                size_t o0 = (size_t)m * D_MODEL + n;
                size_t o1 = (size_t)(m + 8) * D_MODEL + n;
                *(uint32_t*)(D + o0) = pack2h(v0, v1);
                *(uint32_t*)(D + o1) = pack2h(w0, w1);
            }
}

__global__ __launch_bounds__(256, 2)
void tc_out_v6(const float* __restrict__ bo, float* __restrict__ out)
{
    const int bm = blockIdx.y * 128;
    const int bn = blockIdx.x * 128;
    float acc[4][4][4];
    gemm_v5_core(g_attnh, g_Wo, bm, bn, acc);

    const int wid  = threadIdx.x >> 5;
    const int lane = threadIdx.x & 31;
    const int warp_m = (wid >> 2) * 64;
    const int warp_n = (wid & 3) * 32;
    const int erow = lane >> 2;
    const int ecol = (lane & 3) * 2;

#pragma unroll
    for (int mi = 0; mi < 4; mi++)
#pragma unroll
        for (int nt = 0; nt < 2; nt++)
#pragma unroll
            for (int nj = 0; nj < 2; nj++) {
                float* cc = acc[mi][nt * 2 + nj];
                int m = bm + warp_m + mi * 16 + erow;
                int n = bn + warp_n + nt * 16 + nj * 8 + ecol;
                float2 v0 = make_float2(cc[0] + bo[n], cc[1] + bo[n + 1]);
                float2 v1 = make_float2(cc[2] + bo[n], cc[3] + bo[n + 1]);
                *(float2*)(out + (size_t)m * D_MODEL + n)       = v0;
                *(float2*)(out + (size_t)(m + 8) * D_MODEL + n) = v1;
            }
}

// ---- tensor-core causal flash attention (single fp16 Q, 3-stage ring) ------
#define AROW   72
#define A_ARR  (64 * AROW * 2)            // 9216
#define AQ_ARR (128 * AROW * 2)           // 18432
#define SQ_OFF 0
#define STG0   AQ_ARR                     // 18432
#define ASTG_B (2 * A_ARR)                // 18432 (Kh, Vh)
#define A_SMEM (AQ_ARR + 3 * ASTG_B)      // 73728

__global__ __launch_bounds__(256, 2)
void attn_mma_kernel()
{
    extern __shared__ char smem[];
    const uint32_t sb = smem_u32(smem);
    const int tid  = threadIdx.x;
    const int wid  = tid >> 5;
    const int lane = tid & 31;
    const int qb = (int)gridDim.x - 1 - (int)blockIdx.x;
    const int bh = blockIdx.y;
    const int b  = bh >> 4;
    const int h  = bh & 15;
    const int q0 = qb * 128;

    const size_t qgbase = (size_t)(b * S_LEN + q0) * D_MODEL + h * DK;
    const size_t kgbase = (size_t)(b * S_LEN) * D_MODEL + h * DK;

    auto issue_tile = [&](int stg, int kt) {
        const uint32_t sbase = sb + STG0 + stg * ASTG_B;
        const size_t g0 = kgbase + (size_t)(kt * 64) * D_MODEL;
#pragma unroll
        for (int it = 0; it < 2; it++) {
            int slot = tid + it * 256;
            int r  = slot >> 3;
            int c8 = (slot & 7) * 8;
            uint32_t soff = (uint32_t)(r * AROW + c8) * 2;
            const size_t go = g0 + (size_t)r * D_MODEL + c8;
            CP16(sbase + soff,         (const char*)(g_Kh + go));
            CP16(sbase + A_ARR + soff, (const char*)(g_Vh + go));
        }
    };

    const int ntiles = 2 * qb + 2;

    issue_tile(0, 0);
    CP_COMMIT();
    issue_tile(1, 1);
    CP_COMMIT();

    // load Q tile (128 rows)
#pragma unroll
    for (int it = 0; it < 2; it++) {
        int slot = tid + it * 256;        // 0..511
        int r  = slot >> 2;               // 0..127
        int c16 = (slot & 3) * 16;        // halves
        uint32_t soff = (uint32_t)(r * AROW + c16) * 2;
        const size_t go = qgbase + (size_t)r * D_MODEL + c16;
        *(uint4*)(smem + SQ_OFF + soff)      = *(const uint4*)(g_Qh + go);
        *(uint4*)(smem + SQ_OFF + soff + 16) = *(const uint4*)(g_Qh + go + 8);
    }

    float oacc[8][4];
#pragma unroll
    for (int nt = 0; nt < 8; nt++)
#pragma unroll
        for (int j = 0; j < 4; j++) oacc[nt][j] = 0.f;
    float m0 = -1e30f, m1 = -1e30f, l0 = 0.f, l1 = 0.f;

    const int row_lo   = q0 + wid * 16 + (lane >> 2);
    const int wrow_min = q0 + wid * 16;

    const uint32_t qBase = sb + SQ_OFF +
        (uint32_t)((wid * 16 + (lane & 15)) * AROW + ((lane >> 4) << 3)) * 2;

    for (int kt = 0; kt < ntiles; kt++) {
        if (kt + 1 < ntiles) CP_WAIT1(); else CP_WAIT0();
        __syncthreads();
        if (kt + 2 < ntiles) { issue_tile((kt + 2) % 3, kt + 2); CP_COMMIT(); }

        // skip tiles entirely in this warp's causal future
        if (kt * 64 > wrow_min + 15) continue;

        const uint32_t st = sb + STG0 + (kt % 3) * ASTG_B;

        float sc[8][4];
#pragma unroll
        for (int nt = 0; nt < 8; nt++)
#pragma unroll
            for (int j = 0; j < 4; j++) sc[nt][j] = 0.f;

        // S(log2) = Qh @ Kh^T
#pragma unroll
        for (int t = 0; t < 4; t++) {
            uint32_t qh4[4];
            ldsm_x4(qh4, qBase + (uint32_t)(t * 16) * 2);
#pragma unroll
            for (int g = 0; g < 4; g++) {
                uint32_t addr = st +
                    (uint32_t)((g * 16 + (lane & 15)) * AROW + t * 16 + ((lane >> 4) << 3)) * 2;
                uint32_t kh4[4];
                ldsm_x4(kh4, addr);
                mma_f16(sc[2 * g],     qh4, kh4[0], kh4[2]);
                mma_f16(sc[2 * g + 1], qh4, kh4[1], kh4[3]);
            }
        }

        if (kt * 64 + 63 > wrow_min) {
#pragma unroll
            for (int nt = 0; nt < 8; nt++) {
                int col = kt * 64 + nt * 8 + (lane & 3) * 2;
                if (col     > row_lo)     sc[nt][0] = -1e30f;
                if (col + 1 > row_lo)     sc[nt][1] = -1e30f;
                if (col     > row_lo + 8) sc[nt][2] = -1e30f;
                if (col + 1 > row_lo + 8) sc[nt][3] = -1e30f;
            }
        }

        float mx0 = -1e30f, mx1 = -1e30f;
#pragma unroll
        for (int nt = 0; nt < 8; nt++) {
            mx0 = fmaxf(mx0, fmaxf(sc[nt][0], sc[nt][1]));
            mx1 = fmaxf(mx1, fmaxf(sc[nt][2], sc[nt][3]));
        }
        mx0 = fmaxf(mx0, __shfl_xor_sync(0xffffffffu, mx0, 1));
        mx0 = fmaxf(mx0, __shfl_xor_sync(0xffffffffu, mx0, 2));
        mx1 = fmaxf(mx1, __shfl_xor_sync(0xffffffffu, mx1, 1));
        mx1 = fmaxf(mx1, __shfl_xor_sync(0xffffffffu, mx1, 2));

        float mn0 = fmaxf(m0, mx0);
        float mn1 = fmaxf(m1, mx1);
        float corr0 = ex2f(m0 - mn0);
        float corr1 = ex2f(m1 - mn1);
        m0 = mn0; m1 = mn1;

        float sum0 = 0.f, sum1 = 0.f;
#pragma unroll
        for (int nt = 0; nt < 8; nt++) {
            sc[nt][0] = ex2f(sc[nt][0] - mn0);
            sc[nt][1] = ex2f(sc[nt][1] - mn0);
            sc[nt][2] = ex2f(sc[nt][2] - mn1);
            sc[nt][3] = ex2f(sc[nt][3] - mn1);
            sum0 += sc[nt][0] + sc[nt][1];
            sum1 += sc[nt][2] + sc[nt][3];
        }
        sum0 += __shfl_xor_sync(0xffffffffu, sum0, 1);
        sum0 += __shfl_xor_sync(0xffffffffu, sum0, 2);
        sum1 += __shfl_xor_sync(0xffffffffu, sum1, 1);
        sum1 += __shfl_xor_sync(0xffffffffu, sum1, 2);
        l0 = l0 * corr0 + sum0;
        l1 = l1 * corr1 + sum1;

#pragma unroll
        for (int nt = 0; nt < 8; nt++) {
            oacc[nt][0] *= corr0; oacc[nt][1] *= corr0;
            oacc[nt][2] *= corr1; oacc[nt][3] *= corr1;
        }

        uint32_t ph[4][4];
#pragma unroll
        for (int t = 0; t < 4; t++) {
            ph[t][0] = pack2h(sc[2 * t][0],     sc[2 * t][1]);
            ph[t][1] = pack2h(sc[2 * t][2],     sc[2 * t][3]);
            ph[t][2] = pack2h(sc[2 * t + 1][0], sc[2 * t + 1][1]);
            ph[t][3] = pack2h(sc[2 * t + 1][2], sc[2 * t + 1][3]);
        }

        // O += P @ Vh
#pragma unroll
        for (int t = 0; t < 4; t++) {
#pragma unroll
            for (int g = 0; g < 4; g++) {
                uint32_t addr = st + A_ARR +
                    (uint32_t)((t * 16 + (lane & 7) + ((lane >> 3) & 1) * 8) * AROW +
                               g * 16 + ((lane >> 4) << 3)) * 2;
                uint32_t vh4[4];
                ldsm_x4t(vh4, addr);
                mma_f16(oacc[2 * g],     ph[t], vh4[0], vh4[1]);
                mma_f16(oacc[2 * g + 1], ph[t], vh4[2], vh4[3]);
            }
        }
    }

    // ---- epilogue: normalize + fp16 to global (for out-proj) ----
    float inv0 = 1.0f / l0;
    float inv1 = 1.0f / l1;
    size_t base0 = (size_t)(b * S_LEN + row_lo) * D_MODEL + h * DK;
    size_t base1 = base0 + (size_t)8 * D_MODEL;
#pragma unroll
    for (int nt = 0; nt < 8; nt++) {
        int col = nt * 8 + (lane & 3) * 2;
        *(uint32_t*)(g_attnh + base0 + col) = pack2h(oacc[nt][0] * inv0, oacc[nt][1] * inv0);
        *(uint32_t*)(g_attnh + base1 + col) = pack2h(oacc[nt][2] * inv1, oacc[nt][3] * inv1);
    }
}

// ---------------- launch ------------------------------------------------------
extern "C" void kernel_launch(void* const* d_in, const int* in_sizes, int n_in,
                              void* d_out, int out_size)
{
    const float* x  = (const float*)d_in[0];
    const float* Wq = (const float*)d_in[1];
    const float* bq = (const float*)d_in[2];
    const float* Wk = (const float*)d_in[3];
    const float* bk = (const float*)d_in[4];
    const float* Wv = (const float*)d_in[5];
    const float* bv = (const float*)d_in[6];
    const float* Wo = (const float*)d_in[7];
    const float* bo = (const float*)d_in[8];
    float* out = (float*)d_out;

    static int configured = 0;
    if (!configured) {
        cudaFuncSetAttribute(tc_qkv_v6, cudaFuncAttributeMaxDynamicSharedMemorySize, GSMEM_TOTAL);
        cudaFuncSetAttribute(tc_out_v6, cudaFuncAttributeMaxDynamicSharedMemorySize, GSMEM_TOTAL);
        cudaFuncSetAttribute(attn_mma_kernel, cudaFuncAttributeMaxDynamicSharedMemorySize, A_SMEM);
        configured = 1;
    }

    // 0) fused rope table + fp16 casts of x and weights
    split_all<<<(2 * 1024 * 1024) / 256, 256>>>(x, Wq, Wk, Wv, Wo);

    // 1) QKV projections (single-product fp16, 3-stage ring) + RoPE epilogue
    dim3 g_qkv(D_MODEL / 128, M_TOT / 128, 3);
    tc_qkv_v6<<<g_qkv, 256, GSMEM_TOTAL>>>(bq, bk, bv);

    // 2) causal attention (exp2 domain, single fp16 Q, 3-stage ring, tile skip)
    dim3 g_att(S_LEN / 128, BATCH * NHEAD);
    attn_mma_kernel<<<g_att, 256, A_SMEM>>>();

    // 3) output projection (single-product fp16, 3-stage ring)
    dim3 g_out(D_MODEL / 128, M_TOT / 128);
    tc_out_v6<<<g_out, 256, GSMEM_TOTAL>>>(bo, out);
}

// round 13
// speedup vs baseline: 7.4186x; 1.0484x over previous
#include <cuda_runtime.h>
#include <cuda_bf16.h>
#include <cuda_fp16.h>
#include <math.h>
#include <stdint.h>

#define D_MODEL 1024
#define S_LEN   2048
#define BATCH   2
#define NHEAD   16
#define DK      64
#define M_TOT   (BATCH * S_LEN)   // 4096
#define QSCALE  0.1803368801111244f   // (1/8) * log2(e)

// ---------------- scratch (device globals; no allocations allowed) ----------
__device__ __half g_Xh[M_TOT * D_MODEL];
__device__ __half g_Wq[D_MODEL * D_MODEL];
__device__ __half g_Wk[D_MODEL * D_MODEL];
__device__ __half g_Wv[D_MODEL * D_MODEL];
__device__ __half g_Wo[D_MODEL * D_MODEL];
__device__ __half g_Qh [M_TOT * D_MODEL];
__device__ __half g_Kh [M_TOT * D_MODEL];
__device__ __half g_Vh [M_TOT * D_MODEL];
__device__ __half g_attnh[M_TOT * D_MODEL];
__device__ float g_cos[S_LEN * 32];
__device__ float g_sin[S_LEN * 32];

// ---------------- common helpers --------------------------------------------
__device__ __forceinline__ uint32_t smem_u32(const void* p) {
    uint32_t a;
    asm("{ .reg .u64 t; cvta.to.shared.u64 t, %1; cvt.u32.u64 %0, t; }" : "=r"(a) : "l"(p));
    return a;
}

__device__ __forceinline__ float ex2f(float x) {
    float y;
    asm("ex2.approx.f32 %0, %1;" : "=f"(y) : "f"(x));
    return y;
}

__device__ __forceinline__ void ldsm_x4(uint32_t* r, uint32_t addr) {
    asm volatile("ldmatrix.sync.aligned.m8n8.x4.shared.b16 {%0,%1,%2,%3}, [%4];"
                 : "=r"(r[0]), "=r"(r[1]), "=r"(r[2]), "=r"(r[3]) : "r"(addr));
}

__device__ __forceinline__ void ldsm_x4t(uint32_t* r, uint32_t addr) {
    asm volatile("ldmatrix.sync.aligned.m8n8.x4.trans.shared.b16 {%0,%1,%2,%3}, [%4];"
                 : "=r"(r[0]), "=r"(r[1]), "=r"(r[2]), "=r"(r[3]) : "r"(addr));
}

__device__ __forceinline__ void mma_f16(float* c, const uint32_t* a,
                                        uint32_t b0, uint32_t b1) {
    asm volatile("mma.sync.aligned.m16n8k16.row.col.f32.f16.f16.f32 "
                 "{%0,%1,%2,%3}, {%4,%5,%6,%7}, {%8,%9}, {%0,%1,%2,%3};"
                 : "+f"(c[0]), "+f"(c[1]), "+f"(c[2]), "+f"(c[3])
                 : "r"(a[0]), "r"(a[1]), "r"(a[2]), "r"(a[3]), "r"(b0), "r"(b1));
}

__device__ __forceinline__ uint32_t pack2h(float a, float b) {
    union { __half2 h; uint32_t u; } c;
    c.h = __halves2half2(__float2half_rn(a), __float2half_rn(b));
    return c.u;
}

#define CP16(saddr, gptr) \
    asm volatile("cp.async.cg.shared.global [%0], [%1], 16;" :: "r"(saddr), "l"(gptr))
#define CP_COMMIT() asm volatile("cp.async.commit_group;" ::: "memory")
#define CP_WAIT0()  asm volatile("cp.async.wait_group 0;" ::: "memory")
#define CP_WAIT1()  asm volatile("cp.async.wait_group 1;" ::: "memory")

// ---------------- fused rope table + fp16 casts ------------------------------
__global__ void split_all(const float* __restrict__ x,  const float* __restrict__ Wq,
                          const float* __restrict__ Wk, const float* __restrict__ Wv,
                          const float* __restrict__ Wo)
{
    int t = blockIdx.x * blockDim.x + threadIdx.x;   // 0..2M-1
    if (t < S_LEN * 32) {
        int s = t >> 5, i = t & 31;
        float inv_freq = __expf(-(float)(2 * i) * (9.210340371976184f / 64.0f));
        float ang = (float)s * inv_freq;
        g_cos[t] = cosf(ang);
        g_sin[t] = sinf(ang);
    }
    const float* src;
    __half* dst;
    size_t off;
    if (t < (1 << 20)) { src = x; dst = g_Xh; off = t; }
    else {
        int r = t - (1 << 20);
        int w = r >> 18;
        off = (size_t)(r & ((1 << 18) - 1));
        if      (w == 0) { src = Wq; dst = g_Wq; }
        else if (w == 1) { src = Wk; dst = g_Wk; }
        else if (w == 2) { src = Wv; dst = g_Wv; }
        else             { src = Wo; dst = g_Wo; }
    }
    float4 v = ((const float4*)src)[off];
    uint2 o;
    o.x = pack2h(v.x, v.y);
    o.y = pack2h(v.z, v.w);
    ((uint2*)dst)[off] = o;
}

// ========== fp16 single-product GEMM (BK=64, 3-stage cp.async ring) ==========
#define GBK 64
#define GCHUNKS (D_MODEL / GBK)           // 16
#define GROWH  72                         // 144B row stride, conflict-free
#define GARR_B (128 * GROWH * 2)          // 18432
#define GSTG_B (2 * GARR_B)               // 36864 (A, B)
#define GSMEM_TOTAL (3 * GSTG_B)          // 110592

__device__ __forceinline__ void gemm_v5_core(
    const __half* __restrict__ A, const __half* __restrict__ B,
    int bm, int bn, float (&acc)[4][4][4])
{
    extern __shared__ char smem[];
    const uint32_t sb = smem_u32(smem);
    const int tid  = threadIdx.x;
    const int wid  = tid >> 5;
    const int lane = tid & 31;
    const int warp_m = (wid >> 2) * 64;
    const int warp_n = (wid & 3) * 32;

#pragma unroll
    for (int i = 0; i < 4; i++)
#pragma unroll
        for (int j = 0; j < 4; j++)
#pragma unroll
            for (int k = 0; k < 4; k++) acc[i][j][k] = 0.f;

    auto issue = [&](int stg, int c) {
        const uint32_t st = sb + stg * GSTG_B;
        const int k0 = c * GBK;
#pragma unroll
        for (int it = 0; it < 4; it++) {
            int slot = tid + it * 256;            // 0..1023
            int r  = slot >> 3;                   // 0..127
            int c8 = (slot & 7) * 8;              // halves
            uint32_t soff = (uint32_t)(r * GROWH + c8) * 2;
            size_t ga = (size_t)(bm + r) * D_MODEL + k0 + c8;
            size_t gb = (size_t)(bn + r) * D_MODEL + k0 + c8;
            CP16(st + soff,          (const char*)(A + ga));
            CP16(st + GARR_B + soff, (const char*)(B + gb));
        }
    };

    issue(0, 0);
    CP_COMMIT();
    issue(1, 1);
    CP_COMMIT();

    const int qrow = lane & 15;
    const int qcol = (lane >> 4) << 3;

    for (int c = 0; c < GCHUNKS; c++) {
        if (c + 1 < GCHUNKS) CP_WAIT1(); else CP_WAIT0();
        __syncthreads();
        if (c + 2 < GCHUNKS) { issue((c + 2) % 3, c + 2); CP_COMMIT(); }

        const uint32_t st = sb + (c % 3) * GSTG_B;
        const uint32_t aBase = st + (uint32_t)((warp_m + qrow) * GROWH + qcol) * 2;
        const uint32_t bBase = st + GARR_B + (uint32_t)((warp_n + qrow) * GROWH + qcol) * 2;

#pragma unroll
        for (int ks = 0; ks < 4; ks++) {
            const uint32_t ko = (uint32_t)(ks * 16) * 2;
            uint32_t bf[2][4];
#pragma unroll
            for (int nt = 0; nt < 2; nt++)
                ldsm_x4(bf[nt], bBase + nt * (16 * GROWH * 2) + ko);
#pragma unroll
            for (int mi = 0; mi < 4; mi++) {
                uint32_t af[4];
                ldsm_x4(af, aBase + mi * (16 * GROWH * 2) + ko);
#pragma unroll
                for (int nt = 0; nt < 2; nt++)
#pragma unroll
                    for (int nj = 0; nj < 2; nj++)
                        mma_f16(acc[mi][nt * 2 + nj], af, bf[nt][nj], bf[nt][nj + 2]);
            }
        }
    }
}

// QKV GEMM: fused bias + RoPE; Q (log2e-scaled), K, V -> plain fp16
__global__ __launch_bounds__(256, 2)
void tc_qkv_v6(const float* __restrict__ bq, const float* __restrict__ bk,
               const float* __restrict__ bv)
{
    const int z = blockIdx.z;
    const __half* W;
    const float* bias;
    __half* D;
    if (z == 0)      { W = g_Wq; bias = bq; D = g_Qh; }
    else if (z == 1) { W = g_Wk; bias = bk; D = g_Kh; }
    else             { W = g_Wv; bias = bv; D = g_Vh; }

    const int bm = blockIdx.y * 128;
    const int bn = blockIdx.x * 128;
    float acc[4][4][4];
    gemm_v5_core(g_Xh, W, bm, bn, acc);

    const int wid  = threadIdx.x >> 5;
    const int lane = threadIdx.x & 31;
    const int warp_m = (wid >> 2) * 64;
    const int warp_n = (wid & 3) * 32;
    const int erow = lane >> 2;
    const int ecol = (lane & 3) * 2;

#pragma unroll
    for (int mi = 0; mi < 4; mi++)
#pragma unroll
        for (int nt = 0; nt < 2; nt++)
#pragma unroll
            for (int nj = 0; nj < 2; nj++) {
                float* cc = acc[mi][nt * 2 + nj];
                int m = bm + warp_m + mi * 16 + erow;
                int n = bn + warp_n + nt * 16 + nj * 8 + ecol;
                float v0 = cc[0] + bias[n], v1 = cc[1] + bias[n + 1];
                float w0 = cc[2] + bias[n], w1 = cc[3] + bias[n + 1];
                if (z < 2) {
                    int i  = (n & 63) >> 1;
                    int s0 = (m & 2047) * 32 + i;
                    int s1 = ((m + 8) & 2047) * 32 + i;
                    float cs0 = g_cos[s0], sn0 = g_sin[s0];
                    float cs1 = g_cos[s1], sn1 = g_sin[s1];
                    float t0 = v0 * cs0 - v1 * sn0, t1 = v0 * sn0 + v1 * cs0;
                    float u0 = w0 * cs1 - w1 * sn1, u1 = w0 * sn1 + w1 * cs1;
                    if (z == 0) { t0 *= QSCALE; t1 *= QSCALE; u0 *= QSCALE; u1 *= QSCALE; }
                    v0 = t0; v1 = t1; w0 = u0; w1 = u1;
                }
                size_t o0 = (size_t)m * D_MODEL + n;
                size_t o1 = (size_t)(m + 8) * D_MODEL + n;
                *(uint32_t*)(D + o0) = pack2h(v0, v1);
                *(uint32_t*)(D + o1) = pack2h(w0, w1);
            }
}

__global__ __launch_bounds__(256, 2)
void tc_out_v6(const float* __restrict__ bo, float* __restrict__ out)
{
    const int bm = blockIdx.y * 128;
    const int bn = blockIdx.x * 128;
    float acc[4][4][4];
    gemm_v5_core(g_attnh, g_Wo, bm, bn, acc);

    const int wid  = threadIdx.x >> 5;
    const int lane = threadIdx.x & 31;
    const int warp_m = (wid >> 2) * 64;
    const int warp_n = (wid & 3) * 32;
    const int erow = lane >> 2;
    const int ecol = (lane & 3) * 2;

#pragma unroll
    for (int mi = 0; mi < 4; mi++)
#pragma unroll
        for (int nt = 0; nt < 2; nt++)
#pragma unroll
            for (int nj = 0; nj < 2; nj++) {
                float* cc = acc[mi][nt * 2 + nj];
                int m = bm + warp_m + mi * 16 + erow;
                int n = bn + warp_n + nt * 16 + nj * 8 + ecol;
                float2 v0 = make_float2(cc[0] + bo[n], cc[1] + bo[n + 1]);
                float2 v1 = make_float2(cc[2] + bo[n], cc[3] + bo[n + 1]);
                *(float2*)(out + (size_t)m * D_MODEL + n)       = v0;
                *(float2*)(out + (size_t)(m + 8) * D_MODEL + n) = v1;
            }
}

// ---- attention: 4 warps x 32 rows, single fp16 Q, 3-stage ring --------------
#define AROW   72
#define A_ARR  (64 * AROW * 2)            // 9216
#define AQ_ARR (128 * AROW * 2)           // 18432
#define SQ_OFF 0
#define STG0   AQ_ARR                     // 18432
#define ASTG_B (2 * A_ARR)                // 18432 (Kh, Vh)
#define A_SMEM (AQ_ARR + 3 * ASTG_B)      // 73728

__global__ __launch_bounds__(128, 3)
void attn_mma_kernel()
{
    extern __shared__ char smem[];
    const uint32_t sb = smem_u32(smem);
    const int tid  = threadIdx.x;
    const int wid  = tid >> 5;                 // 0..3
    const int lane = tid & 31;
    const int qb = (int)gridDim.x - 1 - (int)blockIdx.x;
    const int bh = blockIdx.y;
    const int b  = bh >> 4;
    const int h  = bh & 15;
    const int q0 = qb * 128;

    const size_t qgbase = (size_t)(b * S_LEN + q0) * D_MODEL + h * DK;
    const size_t kgbase = (size_t)(b * S_LEN) * D_MODEL + h * DK;

    auto issue_tile = [&](int stg, int kt) {
        const uint32_t sbase = sb + STG0 + stg * ASTG_B;
        const size_t g0 = kgbase + (size_t)(kt * 64) * D_MODEL;
#pragma unroll
        for (int it = 0; it < 4; it++) {
            int slot = tid + it * 128;         // 0..511
            int r  = slot >> 3;                // 0..63
            int c8 = (slot & 7) * 8;
            uint32_t soff = (uint32_t)(r * AROW + c8) * 2;
            const size_t go = g0 + (size_t)r * D_MODEL + c8;
            CP16(sbase + soff,         (const char*)(g_Kh + go));
            CP16(sbase + A_ARR + soff, (const char*)(g_Vh + go));
        }
    };

    const int ntiles = 2 * qb + 2;

    issue_tile(0, 0);
    CP_COMMIT();
    issue_tile(1, 1);
    CP_COMMIT();

    // load Q tile (128 rows)
#pragma unroll
    for (int it = 0; it < 8; it++) {
        int slot = tid + it * 128;             // 0..1023
        int r  = slot >> 3;                    // 0..127
        int c8 = (slot & 7) * 8;
        uint32_t soff = (uint32_t)(r * AROW + c8) * 2;
        const size_t go = qgbase + (size_t)r * D_MODEL + c8;
        *(uint4*)(smem + SQ_OFF + soff) = *(const uint4*)(g_Qh + go);
    }

    // two 16-row groups per warp: rows wid*32 and wid*32+16
    float oa0[8][4], oa1[8][4];
#pragma unroll
    for (int nt = 0; nt < 8; nt++)
#pragma unroll
        for (int j = 0; j < 4; j++) { oa0[nt][j] = 0.f; oa1[nt][j] = 0.f; }
    float m0 = -1e30f, m1 = -1e30f, m2 = -1e30f, m3 = -1e30f;
    float l0 = 0.f, l1 = 0.f, l2 = 0.f, l3 = 0.f;

    const int wrow_min = q0 + wid * 32;
    const int row_a = wrow_min + (lane >> 2);        // group0 rows (and +8)
    const int row_b = row_a + 16;                    // group1 rows (and +8)

    const uint32_t qBase0 = sb + SQ_OFF +
        (uint32_t)((wid * 32 + (lane & 15)) * AROW + ((lane >> 4) << 3)) * 2;
    const uint32_t qBase1 = qBase0 + (uint32_t)(16 * AROW) * 2;

    for (int kt = 0; kt < ntiles; kt++) {
        if (kt + 1 < ntiles) CP_WAIT1(); else CP_WAIT0();
        __syncthreads();
        if (kt + 2 < ntiles) { issue_tile((kt + 2) % 3, kt + 2); CP_COMMIT(); }

        if (kt * 64 > wrow_min + 31) continue;

        const uint32_t st = sb + STG0 + (kt % 3) * ASTG_B;

        float s0[8][4], s1[8][4];
#pragma unroll
        for (int nt = 0; nt < 8; nt++)
#pragma unroll
            for (int j = 0; j < 4; j++) { s0[nt][j] = 0.f; s1[nt][j] = 0.f; }

        // S = Q @ K^T for both row groups; each K fragment feeds 4 mma
#pragma unroll
        for (int t = 0; t < 4; t++) {
            uint32_t q0f[4], q1f[4];
            ldsm_x4(q0f, qBase0 + (uint32_t)(t * 16) * 2);
            ldsm_x4(q1f, qBase1 + (uint32_t)(t * 16) * 2);
#pragma unroll
            for (int g = 0; g < 4; g++) {
                uint32_t addr = st +
                    (uint32_t)((g * 16 + (lane & 15)) * AROW + t * 16 + ((lane >> 4) << 3)) * 2;
                uint32_t kh4[4];
                ldsm_x4(kh4, addr);
                mma_f16(s0[2 * g],     q0f, kh4[0], kh4[2]);
                mma_f16(s0[2 * g + 1], q0f, kh4[1], kh4[3]);
                mma_f16(s1[2 * g],     q1f, kh4[0], kh4[2]);
                mma_f16(s1[2 * g + 1], q1f, kh4[1], kh4[3]);
            }
        }

        if (kt * 64 + 63 > wrow_min) {
#pragma unroll
            for (int nt = 0; nt < 8; nt++) {
                int col = kt * 64 + nt * 8 + (lane & 3) * 2;
                if (col     > row_a)     s0[nt][0] = -1e30f;
                if (col + 1 > row_a)     s0[nt][1] = -1e30f;
                if (col     > row_a + 8) s0[nt][2] = -1e30f;
                if (col + 1 > row_a + 8) s0[nt][3] = -1e30f;
                if (col     > row_b)     s1[nt][0] = -1e30f;
                if (col + 1 > row_b)     s1[nt][1] = -1e30f;
                if (col     > row_b + 8) s1[nt][2] = -1e30f;
                if (col + 1 > row_b + 8) s1[nt][3] = -1e30f;
            }
        }

        // ---- online softmax, both groups ----
        float x0 = -1e30f, x1 = -1e30f, x2 = -1e30f, x3 = -1e30f;
#pragma unroll
        for (int nt = 0; nt < 8; nt++) {
            x0 = fmaxf(x0, fmaxf(s0[nt][0], s0[nt][1]));
            x1 = fmaxf(x1, fmaxf(s0[nt][2], s0[nt][3]));
            x2 = fmaxf(x2, fmaxf(s1[nt][0], s1[nt][1]));
            x3 = fmaxf(x3, fmaxf(s1[nt][2], s1[nt][3]));
        }
        x0 = fmaxf(x0, __shfl_xor_sync(0xffffffffu, x0, 1));
        x0 = fmaxf(x0, __shfl_xor_sync(0xffffffffu, x0, 2));
        x1 = fmaxf(x1, __shfl_xor_sync(0xffffffffu, x1, 1));
        x1 = fmaxf(x1, __shfl_xor_sync(0xffffffffu, x1, 2));
        x2 = fmaxf(x2, __shfl_xor_sync(0xffffffffu, x2, 1));
        x2 = fmaxf(x2, __shfl_xor_sync(0xffffffffu, x2, 2));
        x3 = fmaxf(x3, __shfl_xor_sync(0xffffffffu, x3, 1));
        x3 = fmaxf(x3, __shfl_xor_sync(0xffffffffu, x3, 2));

        float n0 = fmaxf(m0, x0), n1 = fmaxf(m1, x1);
        float n2 = fmaxf(m2, x2), n3 = fmaxf(m3, x3);
        float c0 = ex2f(m0 - n0), c1 = ex2f(m1 - n1);
        float c2 = ex2f(m2 - n2), c3 = ex2f(m3 - n3);
        m0 = n0; m1 = n1; m2 = n2; m3 = n3;

        float u0 = 0.f, u1 = 0.f, u2 = 0.f, u3 = 0.f;
#pragma unroll
        for (int nt = 0; nt < 8; nt++) {
            s0[nt][0] = ex2f(s0[nt][0] - n0);
            s0[nt][1] = ex2f(s0[nt][1] - n0);
            s0[nt][2] = ex2f(s0[nt][2] - n1);
            s0[nt][3] = ex2f(s0[nt][3] - n1);
            s1[nt][0] = ex2f(s1[nt][0] - n2);
            s1[nt][1] = ex2f(s1[nt][1] - n2);
            s1[nt][2] = ex2f(s1[nt][2] - n3);
            s1[nt][3] = ex2f(s1[nt][3] - n3);
            u0 += s0[nt][0] + s0[nt][1];
            u1 += s0[nt][2] + s0[nt][3];
            u2 += s1[nt][0] + s1[nt][1];
            u3 += s1[nt][2] + s1[nt][3];
        }
        u0 += __shfl_xor_sync(0xffffffffu, u0, 1);
        u0 += __shfl_xor_sync(0xffffffffu, u0, 2);
        u1 += __shfl_xor_sync(0xffffffffu, u1, 1);
        u1 += __shfl_xor_sync(0xffffffffu, u1, 2);
        u2 += __shfl_xor_sync(0xffffffffu, u2, 1);
        u2 += __shfl_xor_sync(0xffffffffu, u2, 2);
        u3 += __shfl_xor_sync(0xffffffffu, u3, 1);
        u3 += __shfl_xor_sync(0xffffffffu, u3, 2);
        l0 = l0 * c0 + u0;
        l1 = l1 * c1 + u1;
        l2 = l2 * c2 + u2;
        l3 = l3 * c3 + u3;

#pragma unroll
        for (int nt = 0; nt < 8; nt++) {
            oa0[nt][0] *= c0; oa0[nt][1] *= c0;
            oa0[nt][2] *= c1; oa0[nt][3] *= c1;
            oa1[nt][0] *= c2; oa1[nt][1] *= c2;
            oa1[nt][2] *= c3; oa1[nt][3] *= c3;
        }

        uint32_t p0[4][4], p1[4][4];
#pragma unroll
        for (int t = 0; t < 4; t++) {
            p0[t][0] = pack2h(s0[2 * t][0],     s0[2 * t][1]);
            p0[t][1] = pack2h(s0[2 * t][2],     s0[2 * t][3]);
            p0[t][2] = pack2h(s0[2 * t + 1][0], s0[2 * t + 1][1]);
            p0[t][3] = pack2h(s0[2 * t + 1][2], s0[2 * t + 1][3]);
            p1[t][0] = pack2h(s1[2 * t][0],     s1[2 * t][1]);
            p1[t][1] = pack2h(s1[2 * t][2],     s1[2 * t][3]);
            p1[t][2] = pack2h(s1[2 * t + 1][0], s1[2 * t + 1][1]);
            p1[t][3] = pack2h(s1[2 * t + 1][2], s1[2 * t + 1][3]);
        }

        // O += P @ V for both groups; each V fragment feeds 4 mma
#pragma unroll
        for (int t = 0; t < 4; t++) {
#pragma unroll
            for (int g = 0; g < 4; g++) {
                uint32_t addr = st + A_ARR +
                    (uint32_t)((t * 16 + (lane & 7) + ((lane >> 3) & 1) * 8) * AROW +
                               g * 16 + ((lane >> 4) << 3)) * 2;
                uint32_t vh4[4];
                ldsm_x4t(vh4, addr);
                mma_f16(oa0[2 * g],     p0[t], vh4[0], vh4[1]);
                mma_f16(oa0[2 * g + 1], p0[t], vh4[2], vh4[3]);
                mma_f16(oa1[2 * g],     p1[t], vh4[0], vh4[1]);
                mma_f16(oa1[2 * g + 1], p1[t], vh4[2], vh4[3]);
            }
        }
    }

    // ---- epilogue: normalize + fp16 to global (for out-proj) ----
    float i0 = 1.0f / l0, i1 = 1.0f / l1, i2 = 1.0f / l2, i3 = 1.0f / l3;
    size_t ba0 = (size_t)(b * S_LEN + row_a) * D_MODEL + h * DK;
    size_t ba1 = ba0 + (size_t)8 * D_MODEL;
    size_t bb0 = (size_t)(b * S_LEN + row_b) * D_MODEL + h * DK;
    size_t bb1 = bb0 + (size_t)8 * D_MODEL;
#pragma unroll
    for (int nt = 0; nt < 8; nt++) {
        int col = nt * 8 + (lane & 3) * 2;
        *(uint32_t*)(g_attnh + ba0 + col) = pack2h(oa0[nt][0] * i0, oa0[nt][1] * i0);
        *(uint32_t*)(g_attnh + ba1 + col) = pack2h(oa0[nt][2] * i1, oa0[nt][3] * i1);
        *(uint32_t*)(g_attnh + bb0 + col) = pack2h(oa1[nt][0] * i2, oa1[nt][1] * i2);
        *(uint32_t*)(g_attnh + bb1 + col) = pack2h(oa1[nt][2] * i3, oa1[nt][3] * i3);
    }
}

// ---------------- launch ------------------------------------------------------
extern "C" void kernel_launch(void* const* d_in, const int* in_sizes, int n_in,
                              void* d_out, int out_size)
{
    const float* x  = (const float*)d_in[0];
    const float* Wq = (const float*)d_in[1];
    const float* bq = (const float*)d_in[2];
    const float* Wk = (const float*)d_in[3];
    const float* bk = (const float*)d_in[4];
    const float* Wv = (const float*)d_in[5];
    const float* bv = (const float*)d_in[6];
    const float* Wo = (const float*)d_in[7];
    const float* bo = (const float*)d_in[8];
    float* out = (float*)d_out;

    static int configured = 0;
    if (!configured) {
        cudaFuncSetAttribute(tc_qkv_v6, cudaFuncAttributeMaxDynamicSharedMemorySize, GSMEM_TOTAL);
        cudaFuncSetAttribute(tc_out_v6, cudaFuncAttributeMaxDynamicSharedMemorySize, GSMEM_TOTAL);
        cudaFuncSetAttribute(attn_mma_kernel, cudaFuncAttributeMaxDynamicSharedMemorySize, A_SMEM);
        configured = 1;
    }

    // 0) fused rope table + fp16 casts of x and weights
    split_all<<<(2 * 1024 * 1024) / 256, 256>>>(x, Wq, Wk, Wv, Wo);

    // 1) QKV projections (single-product fp16, 3-stage ring) + RoPE epilogue
    dim3 g_qkv(D_MODEL / 128, M_TOT / 128, 3);
    tc_qkv_v6<<<g_qkv, 256, GSMEM_TOTAL>>>(bq, bk, bv);

    // 2) causal attention (4 warps x 32 rows, exp2 domain, 3-stage ring)
    dim3 g_att(S_LEN / 128, BATCH * NHEAD);
    attn_mma_kernel<<<g_att, 128, A_SMEM>>>();

    // 3) output projection (single-product fp16, 3-stage ring)
    dim3 g_out(D_MODEL / 128, M_TOT / 128);
    tc_out_v6<<<g_out, 256, GSMEM_TOTAL>>>(bo, out);
}